// round 2
// baseline (speedup 1.0000x reference)
#include <cuda_runtime.h>
#include <math.h>

#define S_LEN   2048
#define DM      1024
#define NHEADS  16
#define HDIM    64
#define BATCH   2
#define MROWS   (BATCH * S_LEN)   // 4096

// Scratch (device-global; no runtime allocation allowed)
__device__ float g_qkv[MROWS * 3 * DM];   // [4096, 3072]
__device__ float g_ctx[MROWS * DM];       // [4096, 1024]

// ---------------------------------------------------------------------------
// SGEMM + bias: C[M,N] = A[M,K] @ B[K,N] + bias[N]
// 128x128 tile, BK=16, 256 threads, 8x8 per thread. All dims multiples of tile.
// ---------------------------------------------------------------------------
__global__ __launch_bounds__(256) void sgemm_bias(
    const float* __restrict__ A, const float* __restrict__ B,
    const float* __restrict__ bias, float* __restrict__ C,
    int M, int N, int K)
{
    __shared__ float As[16][128];   // transposed A tile: As[k][m]
    __shared__ float Bs[16][128];   // Bs[k][n]

    const int tid = threadIdx.x;
    const int tx = tid & 15;        // 0..15 (N direction)
    const int ty = tid >> 4;        // 0..15 (M direction)
    const int m0 = blockIdx.y * 128;
    const int n0 = blockIdx.x * 128;

    float acc[8][8];
    #pragma unroll
    for (int i = 0; i < 8; i++)
        #pragma unroll
        for (int j = 0; j < 8; j++) acc[i][j] = 0.0f;

    for (int k0 = 0; k0 < K; k0 += 16) {
        // Load A tile (128 rows x 16 cols), store transposed
        #pragma unroll
        for (int it = 0; it < 2; it++) {
            int idx = tid + it * 256;          // 0..511 float4 index
            int row = idx >> 2;                // 0..127
            int c4  = idx & 3;                 // 0..3
            float4 v = *reinterpret_cast<const float4*>(
                &A[(size_t)(m0 + row) * K + k0 + c4 * 4]);
            As[c4 * 4 + 0][row] = v.x;
            As[c4 * 4 + 1][row] = v.y;
            As[c4 * 4 + 2][row] = v.z;
            As[c4 * 4 + 3][row] = v.w;
        }
        // Load B tile (16 rows x 128 cols)
        #pragma unroll
        for (int it = 0; it < 2; it++) {
            int idx = tid + it * 256;
            int row = idx >> 5;                // 0..15
            int c4  = idx & 31;                // 0..31
            float4 v = *reinterpret_cast<const float4*>(
                &B[(size_t)(k0 + row) * N + n0 + c4 * 4]);
            *reinterpret_cast<float4*>(&Bs[row][c4 * 4]) = v;
        }
        __syncthreads();

        #pragma unroll
        for (int kk = 0; kk < 16; kk++) {
            float4 a0 = *reinterpret_cast<const float4*>(&As[kk][ty * 8]);
            float4 a1 = *reinterpret_cast<const float4*>(&As[kk][ty * 8 + 4]);
            float4 b0 = *reinterpret_cast<const float4*>(&Bs[kk][tx * 8]);
            float4 b1 = *reinterpret_cast<const float4*>(&Bs[kk][tx * 8 + 4]);
            float a[8] = {a0.x, a0.y, a0.z, a0.w, a1.x, a1.y, a1.z, a1.w};
            float b[8] = {b0.x, b0.y, b0.z, b0.w, b1.x, b1.y, b1.z, b1.w};
            #pragma unroll
            for (int i = 0; i < 8; i++)
                #pragma unroll
                for (int j = 0; j < 8; j++)
                    acc[i][j] = fmaf(a[i], b[j], acc[i][j]);
        }
        __syncthreads();
    }

    // Epilogue: + bias, store
    #pragma unroll
    for (int i = 0; i < 8; i++) {
        int row = m0 + ty * 8 + i;
        float* crow = &C[(size_t)row * N + n0 + tx * 8];
        const float* brow = &bias[n0 + tx * 8];
        float4 o0, o1;
        o0.x = acc[i][0] + brow[0]; o0.y = acc[i][1] + brow[1];
        o0.z = acc[i][2] + brow[2]; o0.w = acc[i][3] + brow[3];
        o1.x = acc[i][4] + brow[4]; o1.y = acc[i][5] + brow[5];
        o1.z = acc[i][6] + brow[6]; o1.w = acc[i][7] + brow[7];
        *reinterpret_cast<float4*>(crow)     = o0;
        *reinterpret_cast<float4*>(crow + 4) = o1;
    }
}

// ---------------------------------------------------------------------------
// Flash attention, fp32. One block per (q-tile of 64, b*h).
// qkv layout: [4096, 3072] with q at col h*64, k at 1024+h*64, v at 2048+h*64.
// Scale 1/sqrt(64)=0.125 folded into Q at load.
// 256 threads as 16x16; each thread: 4 q-rows x 4 cols (S frag / O frag).
// ---------------------------------------------------------------------------
#define FP  68                                    // smem row pitch (floats)
#define FLASH_SMEM (3 * 64 * FP * sizeof(float))  // 52224 bytes

__device__ __forceinline__ float fast_exp2(float x) {
    float y;
    asm("ex2.approx.ftz.f32 %0, %1;" : "=f"(y) : "f"(x));
    return y;
}

__global__ __launch_bounds__(256) void flash_kernel(
    const float* __restrict__ qkv, float* __restrict__ ctx)
{
    extern __shared__ float sm[];
    float* Qt = sm;                 // [d][r], pitch FP (Q transposed, pre-scaled)
    float* Kt = sm + 64 * FP;       // [d][c], pitch FP; aliased as Pt[k][r] later
    float* Vs = sm + 2 * 64 * FP;   // [k][d], pitch FP

    const int tid = threadIdx.x;
    const int tx = tid & 15;
    const int ty = tid >> 4;
    const int qtile = blockIdx.x;           // 0..31
    const int bh = blockIdx.y;              // 0..31
    const int b = bh >> 4, h = bh & 15;
    const size_t base = (size_t)b * S_LEN * (3 * DM);
    const int q0 = qtile * 64;
    const float LOG2E = 1.4426950408889634f;

    // Load Q tile transposed, fold scale
    #pragma unroll
    for (int it = 0; it < 4; it++) {
        int idx = tid + it * 256;           // 0..1023 float4 idx
        int row = idx >> 4;                 // 0..63
        int d   = (idx & 15) * 4;           // 0..60
        float4 v = *reinterpret_cast<const float4*>(
            &qkv[base + (size_t)(q0 + row) * (3 * DM) + h * HDIM + d]);
        Qt[(d + 0) * FP + row] = v.x * 0.125f;
        Qt[(d + 1) * FP + row] = v.y * 0.125f;
        Qt[(d + 2) * FP + row] = v.z * 0.125f;
        Qt[(d + 3) * FP + row] = v.w * 0.125f;
    }

    float m[4], l[4], o[4][4];
    #pragma unroll
    for (int i = 0; i < 4; i++) {
        m[i] = -INFINITY; l[i] = 0.0f;
        #pragma unroll
        for (int j = 0; j < 4; j++) o[i][j] = 0.0f;
    }

    for (int kt = 0; kt <= qtile; kt++) {
        const int k0 = kt * 64;
        __syncthreads();   // prev iter's Pt/Vs reads complete before overwrite

        // Load K (transposed) and V tiles
        #pragma unroll
        for (int it = 0; it < 4; it++) {
            int idx = tid + it * 256;
            int row = idx >> 4;
            int d   = (idx & 15) * 4;
            size_t roff = base + (size_t)(k0 + row) * (3 * DM) + h * HDIM + d;
            float4 kv = *reinterpret_cast<const float4*>(&qkv[roff + DM]);
            Kt[(d + 0) * FP + row] = kv.x;
            Kt[(d + 1) * FP + row] = kv.y;
            Kt[(d + 2) * FP + row] = kv.z;
            Kt[(d + 3) * FP + row] = kv.w;
            float4 vv = *reinterpret_cast<const float4*>(&qkv[roff + 2 * DM]);
            *reinterpret_cast<float4*>(&Vs[row * FP + d]) = vv;
        }
        __syncthreads();

        // S = Q @ K^T  (scale already folded)
        float s[4][4];
        #pragma unroll
        for (int i = 0; i < 4; i++)
            #pragma unroll
            for (int j = 0; j < 4; j++) s[i][j] = 0.0f;

        #pragma unroll 16
        for (int d = 0; d < 64; d++) {
            float4 a = *reinterpret_cast<const float4*>(&Qt[d * FP + ty * 4]);
            float4 bb = *reinterpret_cast<const float4*>(&Kt[d * FP + tx * 4]);
            float av[4] = {a.x, a.y, a.z, a.w};
            float bv[4] = {bb.x, bb.y, bb.z, bb.w};
            #pragma unroll
            for (int i = 0; i < 4; i++)
                #pragma unroll
                for (int j = 0; j < 4; j++)
                    s[i][j] = fmaf(av[i], bv[j], s[i][j]);
        }

        // Causal mask (diagonal tile only; k0 == q0 there)
        if (kt == qtile) {
            #pragma unroll
            for (int i = 0; i < 4; i++)
                #pragma unroll
                for (int j = 0; j < 4; j++)
                    if (tx * 4 + j > ty * 4 + i) s[i][j] = -1e30f;
        }

        // Online softmax (row reductions across the 16 tx lanes via shfl.xor)
        float alpha[4];
        #pragma unroll
        for (int i = 0; i < 4; i++) {
            float mloc = fmaxf(fmaxf(s[i][0], s[i][1]), fmaxf(s[i][2], s[i][3]));
            #pragma unroll
            for (int off = 1; off < 16; off <<= 1)
                mloc = fmaxf(mloc, __shfl_xor_sync(0xffffffffu, mloc, off));
            float mn = fmaxf(m[i], mloc);
            alpha[i] = fast_exp2((m[i] - mn) * LOG2E);   // exp(-inf)=0 on first tile
            m[i] = mn;
            float lloc = 0.0f;
            #pragma unroll
            for (int j = 0; j < 4; j++) {
                float p = fast_exp2((s[i][j] - mn) * LOG2E);
                s[i][j] = p;
                lloc += p;
            }
            #pragma unroll
            for (int off = 1; off < 16; off <<= 1)
                lloc += __shfl_xor_sync(0xffffffffu, lloc, off);
            l[i] = l[i] * alpha[i] + lloc;
            #pragma unroll
            for (int j = 0; j < 4; j++) o[i][j] *= alpha[i];
        }

        __syncthreads();   // all S-phase reads of Kt done before Pt overwrite

        // Write P transposed into Pt (= Kt buffer): Pt[k][r]
        #pragma unroll
        for (int j = 0; j < 4; j++)
            #pragma unroll
            for (int i = 0; i < 4; i++)
                Kt[(tx * 4 + j) * FP + ty * 4 + i] = s[i][j];
        __syncthreads();

        // O += P @ V
        #pragma unroll 16
        for (int k = 0; k < 64; k++) {
            float4 p = *reinterpret_cast<const float4*>(&Kt[k * FP + ty * 4]);
            float4 v = *reinterpret_cast<const float4*>(&Vs[k * FP + tx * 4]);
            float pv[4] = {p.x, p.y, p.z, p.w};
            float vv[4] = {v.x, v.y, v.z, v.w};
            #pragma unroll
            for (int i = 0; i < 4; i++)
                #pragma unroll
                for (int j = 0; j < 4; j++)
                    o[i][j] = fmaf(pv[i], vv[j], o[i][j]);
        }
    }

    // Epilogue: normalize and write ctx[(b*S + q)*DM + h*64 + d]
    #pragma unroll
    for (int i = 0; i < 4; i++) {
        float inv = 1.0f / l[i];
        float4 v;
        v.x = o[i][0] * inv; v.y = o[i][1] * inv;
        v.z = o[i][2] * inv; v.w = o[i][3] * inv;
        *reinterpret_cast<float4*>(
            &ctx[(size_t)(b * S_LEN + q0 + ty * 4 + i) * DM + h * HDIM + tx * 4]) = v;
    }
}

// ---------------------------------------------------------------------------
extern "C" void kernel_launch(void* const* d_in, const int* in_sizes, int n_in,
                              void* d_out, int out_size)
{
    const float* x    = (const float*)d_in[0];
    const float* Wqkv = (const float*)d_in[1];
    const float* bqkv = (const float*)d_in[2];
    const float* Wout = (const float*)d_in[3];
    const float* bout = (const float*)d_in[4];
    float* out = (float*)d_out;

    float *qkv, *ctx;
    cudaGetSymbolAddress((void**)&qkv, g_qkv);
    cudaGetSymbolAddress((void**)&ctx, g_ctx);

    cudaFuncSetAttribute(flash_kernel,
                         cudaFuncAttributeMaxDynamicSharedMemorySize, FLASH_SMEM);

    // 1) QKV projection: [4096,1024] @ [1024,3072] + b
    dim3 g1(3 * DM / 128, MROWS / 128);   // (24, 32)
    sgemm_bias<<<g1, 256>>>(x, Wqkv, bqkv, qkv, MROWS, 3 * DM, DM);

    // 2) Causal flash attention
    dim3 gf(S_LEN / 64, BATCH * NHEADS);  // (32, 32)
    flash_kernel<<<gf, 256, FLASH_SMEM>>>(qkv, ctx);

    // 3) Output projection: [4096,1024] @ [1024,1024] + b
    dim3 g2(DM / 128, MROWS / 128);       // (8, 32)
    sgemm_bias<<<g2, 256>>>(ctx, Wout, bout, out, MROWS, DM, DM);
}

// round 4
// speedup vs baseline: 1.5291x; 1.5291x over previous
#include <cuda_runtime.h>
#include <cuda_bf16.h>
#include <cstdint>
#include <math.h>

#define S_LEN   2048
#define DM      1024
#define NHEADS  16
#define HDIM    64
#define BATCH   2
#define MROWS   (BATCH * S_LEN)   // 4096

// ---------------------------------------------------------------------------
// Scratch (device globals; no runtime allocation allowed)
// ---------------------------------------------------------------------------
__device__ __align__(256) float g_qkv[MROWS * 3 * DM];           // [4096, 3072] f32
__device__ __align__(256) float g_ctx[MROWS * DM];               // [4096, 1024] f32
__device__ __align__(256) __nv_bfloat16 g_xhi[MROWS * DM];       // x split
__device__ __align__(256) __nv_bfloat16 g_xlo[MROWS * DM];
__device__ __align__(256) __nv_bfloat16 g_ctxhi[MROWS * DM];     // ctx split
__device__ __align__(256) __nv_bfloat16 g_ctxlo[MROWS * DM];
__device__ __align__(256) __nv_bfloat16 g_wqkvThi[3 * DM * DM];  // Wqkv^T [3072,1024]
__device__ __align__(256) __nv_bfloat16 g_wqkvTlo[3 * DM * DM];
__device__ __align__(256) __nv_bfloat16 g_woutThi[DM * DM];      // Wout^T [1024,1024]
__device__ __align__(256) __nv_bfloat16 g_woutTlo[DM * DM];

// ---------------------------------------------------------------------------
// Helpers
// ---------------------------------------------------------------------------
__device__ __forceinline__ uint32_t smem_to_u32(const void* p) {
    uint32_t a;
    asm("{ .reg .u64 t; cvta.to.shared.u64 t, %1; cvt.u32.u64 %0, t; }" : "=r"(a) : "l"(p));
    return a;
}
#define SMEM_SWIZZLE_128B(off) ((off) ^ (((off) >> 3) & 0x70))

__device__ __forceinline__ void ldsm_x4(uint32_t (&r)[4], uint32_t addr) {
    asm volatile("ldmatrix.sync.aligned.m8n8.x4.shared.b16 {%0,%1,%2,%3}, [%4];"
        : "=r"(r[0]), "=r"(r[1]), "=r"(r[2]), "=r"(r[3]) : "r"(addr));
}
__device__ __forceinline__ void mma_bf16(float (&c)[4], const uint32_t (&a)[4],
                                         uint32_t b0, uint32_t b1) {
    asm volatile("mma.sync.aligned.m16n8k16.row.col.f32.bf16.bf16.f32 "
        "{%0,%1,%2,%3}, {%4,%5,%6,%7}, {%8,%9}, {%0,%1,%2,%3};"
        : "+f"(c[0]), "+f"(c[1]), "+f"(c[2]), "+f"(c[3])
        : "r"(a[0]), "r"(a[1]), "r"(a[2]), "r"(a[3]), "r"(b0), "r"(b1));
}

// ---------------------------------------------------------------------------
// Split kernels: f32 -> (hi, lo) bf16
// ---------------------------------------------------------------------------
__global__ __launch_bounds__(256) void split_f32(
    const float* __restrict__ src, __nv_bfloat16* __restrict__ hi,
    __nv_bfloat16* __restrict__ lo, int n4)
{
    int i = blockIdx.x * 256 + threadIdx.x;
    if (i >= n4) return;
    float4 v = reinterpret_cast<const float4*>(src)[i];
    __nv_bfloat16 h[4], l[4];
    float vv[4] = {v.x, v.y, v.z, v.w};
    #pragma unroll
    for (int j = 0; j < 4; j++) {
        h[j] = __float2bfloat16(vv[j]);
        l[j] = __float2bfloat16(vv[j] - __bfloat162float(h[j]));
    }
    reinterpret_cast<uint2*>(hi)[i] = *reinterpret_cast<uint2*>(h);
    reinterpret_cast<uint2*>(lo)[i] = *reinterpret_cast<uint2*>(l);
}

// Transpose + split: W[K,N] f32 -> WT[N,K] bf16 hi/lo. 32x32 tiles, 256 threads.
__global__ __launch_bounds__(256) void splitT_f32(
    const float* __restrict__ W, __nv_bfloat16* __restrict__ hiT,
    __nv_bfloat16* __restrict__ loT, int K, int N)
{
    __shared__ float t[32][33];
    const int kb = blockIdx.y * 32, nb = blockIdx.x * 32;
    const int tx = threadIdx.x & 31, ty0 = threadIdx.x >> 5;
    #pragma unroll
    for (int r = ty0; r < 32; r += 8)
        t[r][tx] = W[(size_t)(kb + r) * N + nb + tx];
    __syncthreads();
    #pragma unroll
    for (int r = ty0; r < 32; r += 8) {
        float v = t[tx][r];                      // W[kb+tx][nb+r]
        __nv_bfloat16 h = __float2bfloat16(v);
        __nv_bfloat16 l = __float2bfloat16(v - __bfloat162float(h));
        size_t o = (size_t)(nb + r) * K + kb + tx;
        hiT[o] = h;
        loT[o] = l;
    }
}

// ---------------------------------------------------------------------------
// mma.sync bf16 split-GEMM + bias:
//   C[M,N] = (Ahi+Alo)[M,K] @ (Bhi+Blo)^T + bias   (B stored [N,K] row-major)
// CTA 128x128, BK=64 smem stage, 8 warps of 64x32, HMMA m16n8k16.
// ---------------------------------------------------------------------------
#define GT_BYTES   16384                       // one 128x64 bf16 tile
#define SOFF_AHI   0
#define SOFF_ALO   (GT_BYTES)
#define SOFF_BHI   (2 * GT_BYTES)
#define SOFF_BLO   (3 * GT_BYTES)
#define GEMM_SMEM  (4 * GT_BYTES)              // 65536

__global__ __launch_bounds__(256, 2) void gemm_mma(
    const __nv_bfloat16* __restrict__ Ahi, const __nv_bfloat16* __restrict__ Alo,
    const __nv_bfloat16* __restrict__ Bhi, const __nv_bfloat16* __restrict__ Blo,
    const float* __restrict__ bias, float* __restrict__ C,
    int M, int N, int K)
{
    extern __shared__ char smem[];
    const uint32_t sb = smem_to_u32(smem);
    const int tid = threadIdx.x;
    const int wid = tid >> 5, lid = tid & 31;
    const int wm = wid & 1;          // 0..1 -> 64-row slab
    const int wn = wid >> 1;         // 0..3 -> 32-col slab
    const int m0 = blockIdx.y * 128, n0 = blockIdx.x * 128;

    float acc[4][4][4];
    #pragma unroll
    for (int i = 0; i < 4; i++)
        #pragma unroll
        for (int j = 0; j < 4; j++)
            #pragma unroll
            for (int r = 0; r < 4; r++) acc[i][j][r] = 0.0f;

    // ldmatrix lane geometry (non-trans, x4)
    const int a_row  = (lid & 7) + ((lid >> 3) & 1) * 8;   // row within m16 tile
    const int a_koff = (lid >> 4) << 3;                    // 0 or 8
    const int b_row  = ((lid >> 4) << 3) + (lid & 7);      // row within n16 group
    const int b_koff = ((lid >> 3) & 1) << 3;

    for (int k0 = 0; k0 < K; k0 += 64) {
        __syncthreads();  // prior stage's ldmatrix reads done before overwrite

        // Load 4 tiles (Ahi, Alo, Bhi, Blo): 128 rows x 64 bf16, SW128 swizzled
        #pragma unroll
        for (int t = 0; t < 4; ++t) {
            const __nv_bfloat16* src = (t == 0) ? Ahi : (t == 1) ? Alo
                                     : (t == 2) ? Bhi : Blo;
            const int r0 = (t < 2) ? m0 : n0;
            char* base = smem + t * GT_BYTES;
            #pragma unroll
            for (int p = 0; p < 4; ++p) {
                int idx = tid + p * 256;          // 0..1023
                int r = idx >> 3;                 // 0..127
                int c = (idx & 7) << 3;           // 0..56 (bf16 cols)
                uint4 v = *reinterpret_cast<const uint4*>(
                    src + (size_t)(r0 + r) * K + k0 + c);
                uint32_t off = (uint32_t)(r * 128 + c * 2);
                *reinterpret_cast<uint4*>(base + SMEM_SWIZZLE_128B(off)) = v;
            }
        }
        __syncthreads();

        #pragma unroll
        for (int ks = 0; ks < 4; ++ks) {
            const int kk = ks << 4;
            uint32_t ah[4][4], al[4][4];
            #pragma unroll
            for (int mi = 0; mi < 4; ++mi) {
                int rg = wm * 64 + mi * 16 + a_row;
                uint32_t sw = (uint32_t)(rg * 128 + (kk + a_koff) * 2)
                              ^ ((uint32_t)(rg & 7) << 4);
                ldsm_x4(ah[mi], sb + SOFF_AHI + sw);
                ldsm_x4(al[mi], sb + SOFF_ALO + sw);
            }
            #pragma unroll
            for (int g = 0; g < 2; ++g) {
                int rg = wn * 32 + g * 16 + b_row;
                uint32_t sw = (uint32_t)(rg * 128 + (kk + b_koff) * 2)
                              ^ ((uint32_t)(rg & 7) << 4);
                uint32_t bh[4];
                ldsm_x4(bh, sb + SOFF_BHI + sw);
                #pragma unroll
                for (int mi = 0; mi < 4; ++mi) {
                    mma_bf16(acc[mi][2 * g],     ah[mi], bh[0], bh[1]);
                    mma_bf16(acc[mi][2 * g + 1], ah[mi], bh[2], bh[3]);
                    mma_bf16(acc[mi][2 * g],     al[mi], bh[0], bh[1]);
                    mma_bf16(acc[mi][2 * g + 1], al[mi], bh[2], bh[3]);
                }
                uint32_t bl[4];
                ldsm_x4(bl, sb + SOFF_BLO + sw);
                #pragma unroll
                for (int mi = 0; mi < 4; ++mi) {
                    mma_bf16(acc[mi][2 * g],     ah[mi], bl[0], bl[1]);
                    mma_bf16(acc[mi][2 * g + 1], ah[mi], bl[2], bl[3]);
                }
            }
        }
    }

    // Epilogue: c-frag layout m16n8: lane = 4*g+t
    const int cg = lid >> 2, ct = lid & 3;
    #pragma unroll
    for (int mi = 0; mi < 4; ++mi) {
        #pragma unroll
        for (int ni = 0; ni < 4; ++ni) {
            int row = m0 + wm * 64 + mi * 16 + cg;
            int col = n0 + wn * 32 + ni * 8 + 2 * ct;
            float2 bv = *reinterpret_cast<const float2*>(&bias[col]);
            float2 o0, o1;
            o0.x = acc[mi][ni][0] + bv.x; o0.y = acc[mi][ni][1] + bv.y;
            o1.x = acc[mi][ni][2] + bv.x; o1.y = acc[mi][ni][3] + bv.y;
            *reinterpret_cast<float2*>(&C[(size_t)row * N + col]) = o0;
            *reinterpret_cast<float2*>(&C[(size_t)(row + 8) * N + col]) = o1;
        }
    }
}

// ---------------------------------------------------------------------------
// Flash attention, fp32 (unchanged, known-good). One block per (q-tile 64, b*h).
// ---------------------------------------------------------------------------
#define FP  68
#define FLASH_SMEM (3 * 64 * FP * sizeof(float))

__device__ __forceinline__ float fast_exp2(float x) {
    float y;
    asm("ex2.approx.ftz.f32 %0, %1;" : "=f"(y) : "f"(x));
    return y;
}

__global__ __launch_bounds__(256) void flash_kernel(
    const float* __restrict__ qkv, float* __restrict__ ctx)
{
    extern __shared__ float sm[];
    float* Qt = sm;
    float* Kt = sm + 64 * FP;
    float* Vs = sm + 2 * 64 * FP;

    const int tid = threadIdx.x;
    const int tx = tid & 15;
    const int ty = tid >> 4;
    const int qtile = blockIdx.x;
    const int bh = blockIdx.y;
    const int b = bh >> 4, h = bh & 15;
    const size_t base = (size_t)b * S_LEN * (3 * DM);
    const int q0 = qtile * 64;
    const float LOG2E = 1.4426950408889634f;

    #pragma unroll
    for (int it = 0; it < 4; it++) {
        int idx = tid + it * 256;
        int row = idx >> 4;
        int d   = (idx & 15) * 4;
        float4 v = *reinterpret_cast<const float4*>(
            &qkv[base + (size_t)(q0 + row) * (3 * DM) + h * HDIM + d]);
        Qt[(d + 0) * FP + row] = v.x * 0.125f;
        Qt[(d + 1) * FP + row] = v.y * 0.125f;
        Qt[(d + 2) * FP + row] = v.z * 0.125f;
        Qt[(d + 3) * FP + row] = v.w * 0.125f;
    }

    float m[4], l[4], o[4][4];
    #pragma unroll
    for (int i = 0; i < 4; i++) {
        m[i] = -INFINITY; l[i] = 0.0f;
        #pragma unroll
        for (int j = 0; j < 4; j++) o[i][j] = 0.0f;
    }

    for (int kt = 0; kt <= qtile; kt++) {
        const int k0 = kt * 64;
        __syncthreads();

        #pragma unroll
        for (int it = 0; it < 4; it++) {
            int idx = tid + it * 256;
            int row = idx >> 4;
            int d   = (idx & 15) * 4;
            size_t roff = base + (size_t)(k0 + row) * (3 * DM) + h * HDIM + d;
            float4 kv = *reinterpret_cast<const float4*>(&qkv[roff + DM]);
            Kt[(d + 0) * FP + row] = kv.x;
            Kt[(d + 1) * FP + row] = kv.y;
            Kt[(d + 2) * FP + row] = kv.z;
            Kt[(d + 3) * FP + row] = kv.w;
            float4 vv = *reinterpret_cast<const float4*>(&qkv[roff + 2 * DM]);
            *reinterpret_cast<float4*>(&Vs[row * FP + d]) = vv;
        }
        __syncthreads();

        float s[4][4];
        #pragma unroll
        for (int i = 0; i < 4; i++)
            #pragma unroll
            for (int j = 0; j < 4; j++) s[i][j] = 0.0f;

        #pragma unroll 16
        for (int d = 0; d < 64; d++) {
            float4 a = *reinterpret_cast<const float4*>(&Qt[d * FP + ty * 4]);
            float4 bb = *reinterpret_cast<const float4*>(&Kt[d * FP + tx * 4]);
            float av[4] = {a.x, a.y, a.z, a.w};
            float bv[4] = {bb.x, bb.y, bb.z, bb.w};
            #pragma unroll
            for (int i = 0; i < 4; i++)
                #pragma unroll
                for (int j = 0; j < 4; j++)
                    s[i][j] = fmaf(av[i], bv[j], s[i][j]);
        }

        if (kt == qtile) {
            #pragma unroll
            for (int i = 0; i < 4; i++)
                #pragma unroll
                for (int j = 0; j < 4; j++)
                    if (tx * 4 + j > ty * 4 + i) s[i][j] = -1e30f;
        }

        float alpha[4];
        #pragma unroll
        for (int i = 0; i < 4; i++) {
            float mloc = fmaxf(fmaxf(s[i][0], s[i][1]), fmaxf(s[i][2], s[i][3]));
            #pragma unroll
            for (int off = 1; off < 16; off <<= 1)
                mloc = fmaxf(mloc, __shfl_xor_sync(0xffffffffu, mloc, off));
            float mn = fmaxf(m[i], mloc);
            alpha[i] = fast_exp2((m[i] - mn) * LOG2E);
            m[i] = mn;
            float lloc = 0.0f;
            #pragma unroll
            for (int j = 0; j < 4; j++) {
                float p = fast_exp2((s[i][j] - mn) * LOG2E);
                s[i][j] = p;
                lloc += p;
            }
            #pragma unroll
            for (int off = 1; off < 16; off <<= 1)
                lloc += __shfl_xor_sync(0xffffffffu, lloc, off);
            l[i] = l[i] * alpha[i] + lloc;
            #pragma unroll
            for (int j = 0; j < 4; j++) o[i][j] *= alpha[i];
        }

        __syncthreads();

        #pragma unroll
        for (int j = 0; j < 4; j++)
            #pragma unroll
            for (int i = 0; i < 4; i++)
                Kt[(tx * 4 + j) * FP + ty * 4 + i] = s[i][j];
        __syncthreads();

        #pragma unroll 16
        for (int k = 0; k < 64; k++) {
            float4 p = *reinterpret_cast<const float4*>(&Kt[k * FP + ty * 4]);
            float4 v = *reinterpret_cast<const float4*>(&Vs[k * FP + tx * 4]);
            float pv[4] = {p.x, p.y, p.z, p.w};
            float vv[4] = {v.x, v.y, v.z, v.w};
            #pragma unroll
            for (int i = 0; i < 4; i++)
                #pragma unroll
                for (int j = 0; j < 4; j++)
                    o[i][j] = fmaf(pv[i], vv[j], o[i][j]);
        }
    }

    #pragma unroll
    for (int i = 0; i < 4; i++) {
        float inv = 1.0f / l[i];
        float4 v;
        v.x = o[i][0] * inv; v.y = o[i][1] * inv;
        v.z = o[i][2] * inv; v.w = o[i][3] * inv;
        *reinterpret_cast<float4*>(
            &ctx[(size_t)(b * S_LEN + q0 + ty * 4 + i) * DM + h * HDIM + tx * 4]) = v;
    }
}

// ---------------------------------------------------------------------------
extern "C" void kernel_launch(void* const* d_in, const int* in_sizes, int n_in,
                              void* d_out, int out_size)
{
    const float* x    = (const float*)d_in[0];
    const float* Wqkv = (const float*)d_in[1];
    const float* bqkv = (const float*)d_in[2];
    const float* Wout = (const float*)d_in[3];
    const float* bout = (const float*)d_in[4];
    float* out = (float*)d_out;

    float *qkv, *ctx;
    __nv_bfloat16 *xhi, *xlo, *ctxhi, *ctxlo, *wqhi, *wqlo, *wohi, *wolo;
    cudaGetSymbolAddress((void**)&qkv, g_qkv);
    cudaGetSymbolAddress((void**)&ctx, g_ctx);
    cudaGetSymbolAddress((void**)&xhi, g_xhi);
    cudaGetSymbolAddress((void**)&xlo, g_xlo);
    cudaGetSymbolAddress((void**)&ctxhi, g_ctxhi);
    cudaGetSymbolAddress((void**)&ctxlo, g_ctxlo);
    cudaGetSymbolAddress((void**)&wqhi, g_wqkvThi);
    cudaGetSymbolAddress((void**)&wqlo, g_wqkvTlo);
    cudaGetSymbolAddress((void**)&wohi, g_woutThi);
    cudaGetSymbolAddress((void**)&wolo, g_woutTlo);

    cudaFuncSetAttribute(gemm_mma, cudaFuncAttributeMaxDynamicSharedMemorySize, GEMM_SMEM);
    cudaFuncSetAttribute(flash_kernel, cudaFuncAttributeMaxDynamicSharedMemorySize, FLASH_SMEM);

    // 0) Split inputs / weights to bf16 hi/lo (weights transposed to [N,K])
    int nx4 = MROWS * DM / 4;
    split_f32<<<(nx4 + 255) / 256, 256>>>(x, xhi, xlo, nx4);
    splitT_f32<<<dim3(3 * DM / 32, DM / 32), 256>>>(Wqkv, wqhi, wqlo, DM, 3 * DM);
    splitT_f32<<<dim3(DM / 32, DM / 32), 256>>>(Wout, wohi, wolo, DM, DM);

    // 1) QKV projection on HMMA: [4096,1024] @ [1024,3072]^T' + b
    gemm_mma<<<dim3(3 * DM / 128, MROWS / 128), 256, GEMM_SMEM>>>(
        xhi, xlo, wqhi, wqlo, bqkv, qkv, MROWS, 3 * DM, DM);

    // 2) Causal flash attention (fp32)
    flash_kernel<<<dim3(S_LEN / 64, BATCH * NHEADS), 256, FLASH_SMEM>>>(qkv, ctx);

    // 3) Split ctx, then output projection on HMMA
    split_f32<<<(nx4 + 255) / 256, 256>>>(ctx, ctxhi, ctxlo, nx4);
    gemm_mma<<<dim3(DM / 128, MROWS / 128), 256, GEMM_SMEM>>>(
        ctxhi, ctxlo, wohi, wolo, bout, out, MROWS, DM, DM);
}

// round 5
// speedup vs baseline: 2.6512x; 1.7338x over previous
#include <cuda_runtime.h>
#include <cuda_bf16.h>
#include <cstdint>
#include <math.h>

#define S_LEN   2048
#define DM      1024
#define NHEADS  16
#define HDIM    64
#define BATCH   2
#define MROWS   (BATCH * S_LEN)   // 4096

// ---------------------------------------------------------------------------
// Scratch (device globals; no runtime allocation allowed)
// ---------------------------------------------------------------------------
__device__ __align__(256) __nv_bfloat16 g_qkvhi[MROWS * 3 * DM]; // qkv split
__device__ __align__(256) __nv_bfloat16 g_qkvlo[MROWS * 3 * DM];
__device__ __align__(256) __nv_bfloat16 g_xhi[MROWS * DM];       // x split
__device__ __align__(256) __nv_bfloat16 g_xlo[MROWS * DM];
__device__ __align__(256) __nv_bfloat16 g_ctxhi[MROWS * DM];     // ctx split
__device__ __align__(256) __nv_bfloat16 g_ctxlo[MROWS * DM];
__device__ __align__(256) __nv_bfloat16 g_wqkvThi[3 * DM * DM];  // Wqkv^T [3072,1024]
__device__ __align__(256) __nv_bfloat16 g_wqkvTlo[3 * DM * DM];
__device__ __align__(256) __nv_bfloat16 g_woutThi[DM * DM];      // Wout^T [1024,1024]
__device__ __align__(256) __nv_bfloat16 g_woutTlo[DM * DM];

// ---------------------------------------------------------------------------
// Helpers
// ---------------------------------------------------------------------------
__device__ __forceinline__ uint32_t smem_to_u32(const void* p) {
    uint32_t a;
    asm("{ .reg .u64 t; cvta.to.shared.u64 t, %1; cvt.u32.u64 %0, t; }" : "=r"(a) : "l"(p));
    return a;
}
#define SMEM_SWIZZLE_128B(off) ((off) ^ (((off) >> 3) & 0x70))

__device__ __forceinline__ void ldsm_x4(uint32_t (&r)[4], uint32_t addr) {
    asm volatile("ldmatrix.sync.aligned.m8n8.x4.shared.b16 {%0,%1,%2,%3}, [%4];"
        : "=r"(r[0]), "=r"(r[1]), "=r"(r[2]), "=r"(r[3]) : "r"(addr));
}
__device__ __forceinline__ void ldsm_x4_t(uint32_t (&r)[4], uint32_t addr) {
    asm volatile("ldmatrix.sync.aligned.m8n8.x4.trans.shared.b16 {%0,%1,%2,%3}, [%4];"
        : "=r"(r[0]), "=r"(r[1]), "=r"(r[2]), "=r"(r[3]) : "r"(addr));
}
__device__ __forceinline__ void mma_bf16(float (&c)[4], const uint32_t (&a)[4],
                                         uint32_t b0, uint32_t b1) {
    asm volatile("mma.sync.aligned.m16n8k16.row.col.f32.bf16.bf16.f32 "
        "{%0,%1,%2,%3}, {%4,%5,%6,%7}, {%8,%9}, {%0,%1,%2,%3};"
        : "+f"(c[0]), "+f"(c[1]), "+f"(c[2]), "+f"(c[3])
        : "r"(a[0]), "r"(a[1]), "r"(a[2]), "r"(a[3]), "r"(b0), "r"(b1));
}
__device__ __forceinline__ float fast_exp2(float x) {
    float y;
    asm("ex2.approx.ftz.f32 %0, %1;" : "=f"(y) : "f"(x));
    return y;
}
// split two f32 into packed bf16x2 hi and lo (lo = residual)
__device__ __forceinline__ void split2(float v0, float v1, uint32_t& hi, uint32_t& lo) {
    __nv_bfloat16 h0 = __float2bfloat16(v0), h1 = __float2bfloat16(v1);
    __nv_bfloat16 l0 = __float2bfloat16(v0 - __bfloat162float(h0));
    __nv_bfloat16 l1 = __float2bfloat16(v1 - __bfloat162float(h1));
    __nv_bfloat162 hp = __halves2bfloat162(h0, h1);
    __nv_bfloat162 lp = __halves2bfloat162(l0, l1);
    hi = *reinterpret_cast<uint32_t*>(&hp);
    lo = *reinterpret_cast<uint32_t*>(&lp);
}

// ---------------------------------------------------------------------------
// Split kernels: f32 -> (hi, lo) bf16
// ---------------------------------------------------------------------------
__global__ __launch_bounds__(256) void split_f32(
    const float* __restrict__ src, __nv_bfloat16* __restrict__ hi,
    __nv_bfloat16* __restrict__ lo, int n4)
{
    int i = blockIdx.x * 256 + threadIdx.x;
    if (i >= n4) return;
    float4 v = reinterpret_cast<const float4*>(src)[i];
    __nv_bfloat16 h[4], l[4];
    float vv[4] = {v.x, v.y, v.z, v.w};
    #pragma unroll
    for (int j = 0; j < 4; j++) {
        h[j] = __float2bfloat16(vv[j]);
        l[j] = __float2bfloat16(vv[j] - __bfloat162float(h[j]));
    }
    reinterpret_cast<uint2*>(hi)[i] = *reinterpret_cast<uint2*>(h);
    reinterpret_cast<uint2*>(lo)[i] = *reinterpret_cast<uint2*>(l);
}

// Transpose + split: W[K,N] f32 -> WT[N,K] bf16 hi/lo. 32x32 tiles, 256 threads.
__global__ __launch_bounds__(256) void splitT_f32(
    const float* __restrict__ W, __nv_bfloat16* __restrict__ hiT,
    __nv_bfloat16* __restrict__ loT, int K, int N)
{
    __shared__ float t[32][33];
    const int kb = blockIdx.y * 32, nb = blockIdx.x * 32;
    const int tx = threadIdx.x & 31, ty0 = threadIdx.x >> 5;
    #pragma unroll
    for (int r = ty0; r < 32; r += 8)
        t[r][tx] = W[(size_t)(kb + r) * N + nb + tx];
    __syncthreads();
    #pragma unroll
    for (int r = ty0; r < 32; r += 8) {
        float v = t[tx][r];
        __nv_bfloat16 h = __float2bfloat16(v);
        __nv_bfloat16 l = __float2bfloat16(v - __bfloat162float(h));
        size_t o = (size_t)(nb + r) * K + kb + tx;
        hiT[o] = h;
        loT[o] = l;
    }
}

// ---------------------------------------------------------------------------
// mma.sync bf16 split-GEMM + bias.
// MODE 0: write f32 C. MODE 1: write split bf16 (Chi, Clo).
// CTA 128x128, BK=64 smem stage, 8 warps of 64x32, HMMA m16n8k16.
// ---------------------------------------------------------------------------
#define GT_BYTES   16384
#define SOFF_AHI   0
#define SOFF_ALO   (GT_BYTES)
#define SOFF_BHI   (2 * GT_BYTES)
#define SOFF_BLO   (3 * GT_BYTES)
#define GEMM_SMEM  (4 * GT_BYTES)              // 65536

template<int MODE>
__global__ __launch_bounds__(256, 2) void gemm_mma(
    const __nv_bfloat16* __restrict__ Ahi, const __nv_bfloat16* __restrict__ Alo,
    const __nv_bfloat16* __restrict__ Bhi, const __nv_bfloat16* __restrict__ Blo,
    const float* __restrict__ bias, float* __restrict__ C,
    __nv_bfloat16* __restrict__ Chi, __nv_bfloat16* __restrict__ Clo,
    int M, int N, int K)
{
    extern __shared__ char smem[];
    const uint32_t sb = smem_to_u32(smem);
    const int tid = threadIdx.x;
    const int wid = tid >> 5, lid = tid & 31;
    const int wm = wid & 1;
    const int wn = wid >> 1;
    const int m0 = blockIdx.y * 128, n0 = blockIdx.x * 128;

    float acc[4][4][4];
    #pragma unroll
    for (int i = 0; i < 4; i++)
        #pragma unroll
        for (int j = 0; j < 4; j++)
            #pragma unroll
            for (int r = 0; r < 4; r++) acc[i][j][r] = 0.0f;

    const int a_row  = (lid & 7) + ((lid >> 3) & 1) * 8;
    const int a_koff = (lid >> 4) << 3;
    const int b_row  = ((lid >> 4) << 3) + (lid & 7);
    const int b_koff = ((lid >> 3) & 1) << 3;

    for (int k0 = 0; k0 < K; k0 += 64) {
        __syncthreads();
        #pragma unroll
        for (int t = 0; t < 4; ++t) {
            const __nv_bfloat16* src = (t == 0) ? Ahi : (t == 1) ? Alo
                                     : (t == 2) ? Bhi : Blo;
            const int r0 = (t < 2) ? m0 : n0;
            char* base = smem + t * GT_BYTES;
            #pragma unroll
            for (int p = 0; p < 4; ++p) {
                int idx = tid + p * 256;
                int r = idx >> 3;
                int c = (idx & 7) << 3;
                uint4 v = *reinterpret_cast<const uint4*>(
                    src + (size_t)(r0 + r) * K + k0 + c);
                uint32_t off = (uint32_t)(r * 128 + c * 2);
                *reinterpret_cast<uint4*>(base + SMEM_SWIZZLE_128B(off)) = v;
            }
        }
        __syncthreads();

        #pragma unroll
        for (int ks = 0; ks < 4; ++ks) {
            const int kk = ks << 4;
            uint32_t ah[4][4], al[4][4];
            #pragma unroll
            for (int mi = 0; mi < 4; ++mi) {
                int rg = wm * 64 + mi * 16 + a_row;
                uint32_t sw = (uint32_t)(rg * 128 + (kk + a_koff) * 2)
                              ^ ((uint32_t)(rg & 7) << 4);
                ldsm_x4(ah[mi], sb + SOFF_AHI + sw);
                ldsm_x4(al[mi], sb + SOFF_ALO + sw);
            }
            #pragma unroll
            for (int g = 0; g < 2; ++g) {
                int rg = wn * 32 + g * 16 + b_row;
                uint32_t sw = (uint32_t)(rg * 128 + (kk + b_koff) * 2)
                              ^ ((uint32_t)(rg & 7) << 4);
                uint32_t bh[4];
                ldsm_x4(bh, sb + SOFF_BHI + sw);
                #pragma unroll
                for (int mi = 0; mi < 4; ++mi) {
                    mma_bf16(acc[mi][2 * g],     ah[mi], bh[0], bh[1]);
                    mma_bf16(acc[mi][2 * g + 1], ah[mi], bh[2], bh[3]);
                    mma_bf16(acc[mi][2 * g],     al[mi], bh[0], bh[1]);
                    mma_bf16(acc[mi][2 * g + 1], al[mi], bh[2], bh[3]);
                }
                uint32_t bl[4];
                ldsm_x4(bl, sb + SOFF_BLO + sw);
                #pragma unroll
                for (int mi = 0; mi < 4; ++mi) {
                    mma_bf16(acc[mi][2 * g],     ah[mi], bl[0], bl[1]);
                    mma_bf16(acc[mi][2 * g + 1], ah[mi], bl[2], bl[3]);
                }
            }
        }
    }

    const int cg = lid >> 2, ct = lid & 3;
    #pragma unroll
    for (int mi = 0; mi < 4; ++mi) {
        #pragma unroll
        for (int ni = 0; ni < 4; ++ni) {
            int row = m0 + wm * 64 + mi * 16 + cg;
            int col = n0 + wn * 32 + ni * 8 + 2 * ct;
            float2 bv = *reinterpret_cast<const float2*>(&bias[col]);
            float v00 = acc[mi][ni][0] + bv.x, v01 = acc[mi][ni][1] + bv.y;
            float v10 = acc[mi][ni][2] + bv.x, v11 = acc[mi][ni][3] + bv.y;
            if (MODE == 0) {
                float2 o0 = {v00, v01}, o1 = {v10, v11};
                *reinterpret_cast<float2*>(&C[(size_t)row * N + col]) = o0;
                *reinterpret_cast<float2*>(&C[(size_t)(row + 8) * N + col]) = o1;
            } else {
                uint32_t h, l;
                split2(v00, v01, h, l);
                *reinterpret_cast<uint32_t*>(&Chi[(size_t)row * N + col]) = h;
                *reinterpret_cast<uint32_t*>(&Clo[(size_t)row * N + col]) = l;
                split2(v10, v11, h, l);
                *reinterpret_cast<uint32_t*>(&Chi[(size_t)(row + 8) * N + col]) = h;
                *reinterpret_cast<uint32_t*>(&Clo[(size_t)(row + 8) * N + col]) = l;
            }
        }
    }
}

// ---------------------------------------------------------------------------
// Tensor-core flash attention (split-bf16, HMMA).
// Block: (q-tile of 128, b*h). 8 warps, each owns 16 q-rows.
// qkv stored split bf16 [4096, 3072]: q at h*64, k at 1024+h*64, v at 2048+h*64.
// Output written directly as split bf16 ctx (for out-proj A operand).
// ---------------------------------------------------------------------------
#define FTS_QHI  0
#define FTS_QLO  (16 * 1024)
#define FTS_KHI  (32 * 1024)
#define FTS_KLO  (40 * 1024)
#define FTS_VHI  (48 * 1024)
#define FTS_VLO  (56 * 1024)
#define FLASH_SMEM_TC (64 * 1024)

__global__ __launch_bounds__(256, 2) void flash_tc(
    const __nv_bfloat16* __restrict__ qkvhi, const __nv_bfloat16* __restrict__ qkvlo,
    __nv_bfloat16* __restrict__ ctxhi, __nv_bfloat16* __restrict__ ctxlo)
{
    extern __shared__ char smem[];
    const uint32_t sb = smem_to_u32(smem);
    const int tid = threadIdx.x;
    const int wid = tid >> 5, lid = tid & 31;
    const int qt = blockIdx.x;                 // 0..15
    const int bh = blockIdx.y;                 // 0..31
    const int b = bh >> 4, h = bh & 15;
    const int q0 = qt * 128;
    const float LOG2E = 1.4426950408889634f;

    // ---- Load Q tiles (hi/lo) into smem, swizzled
    #pragma unroll
    for (int t = 0; t < 2; ++t) {
        const __nv_bfloat16* src = t ? qkvlo : qkvhi;
        char* base = smem + (t ? FTS_QLO : FTS_QHI);
        #pragma unroll
        for (int p = 0; p < 4; ++p) {
            int idx = tid + p * 256;
            int r = idx >> 3;
            int c = (idx & 7) << 3;
            uint4 v = *reinterpret_cast<const uint4*>(
                src + (size_t)(b * S_LEN + q0 + r) * (3 * DM) + h * HDIM + c);
            uint32_t off = (uint32_t)(r * 128 + c * 2);
            *reinterpret_cast<uint4*>(base + SMEM_SWIZZLE_128B(off)) = v;
        }
    }
    __syncthreads();

    // ---- Q fragments (kept in registers for the whole kernel)
    const int a_row  = (lid & 7) + ((lid >> 3) & 1) * 8;
    const int a_koff = (lid >> 4) << 3;
    const int b_row  = ((lid >> 4) << 3) + (lid & 7);
    const int b_koff = ((lid >> 3) & 1) << 3;
    uint32_t qh[4][4], ql[4][4];
    #pragma unroll
    for (int kk = 0; kk < 4; ++kk) {
        int rg = wid * 16 + a_row;
        uint32_t sw = (uint32_t)(rg * 128 + (kk * 16 + a_koff) * 2)
                      ^ ((uint32_t)(rg & 7) << 4);
        ldsm_x4(qh[kk], sb + FTS_QHI + sw);
        ldsm_x4(ql[kk], sb + FTS_QLO + sw);
    }

    float o[8][4];
    #pragma unroll
    for (int j = 0; j < 8; ++j)
        #pragma unroll
        for (int r = 0; r < 4; ++r) o[j][r] = 0.0f;
    float mrow[2] = {-INFINITY, -INFINITY};
    float lrow[2] = {0.0f, 0.0f};

    const int g8 = lid >> 2, t2 = (lid & 3) * 2;
    const int nkt = 2 * qt + 2;

    for (int kt = 0; kt < nkt; ++kt) {
        const int k0 = kt * 64;
        __syncthreads();
        // ---- Load K/V hi/lo tiles (64x64 each), swizzled
        #pragma unroll
        for (int t = 0; t < 4; ++t) {
            const __nv_bfloat16* src = (t & 1) ? qkvlo : qkvhi;
            const int coloff = (t < 2) ? DM : 2 * DM;
            char* base = smem + FTS_KHI + t * 8192;
            #pragma unroll
            for (int p = 0; p < 2; ++p) {
                int idx = tid + p * 256;
                int r = idx >> 3;
                int c = (idx & 7) << 3;
                uint4 v = *reinterpret_cast<const uint4*>(
                    src + (size_t)(b * S_LEN + k0 + r) * (3 * DM) + coloff + h * HDIM + c);
                uint32_t off = (uint32_t)(r * 128 + c * 2);
                *reinterpret_cast<uint4*>(base + SMEM_SWIZZLE_128B(off)) = v;
            }
        }
        __syncthreads();

        // fully-masked warp: skip compute (still participated in loads)
        if (q0 + wid * 16 + 15 < k0) continue;

        // ---- S = Q @ K^T (split: qh@kh + ql@kh + qh@kl)
        float s[8][4];
        #pragma unroll
        for (int j = 0; j < 8; ++j)
            #pragma unroll
            for (int r = 0; r < 4; ++r) s[j][r] = 0.0f;

        #pragma unroll
        for (int g = 0; g < 4; ++g) {
            #pragma unroll
            for (int kk = 0; kk < 4; ++kk) {
                int rg = g * 16 + b_row;
                uint32_t sw = (uint32_t)(rg * 128 + (kk * 16 + b_koff) * 2)
                              ^ ((uint32_t)(rg & 7) << 4);
                uint32_t kh[4];
                ldsm_x4(kh, sb + FTS_KHI + sw);
                mma_bf16(s[2 * g],     qh[kk], kh[0], kh[1]);
                mma_bf16(s[2 * g + 1], qh[kk], kh[2], kh[3]);
                mma_bf16(s[2 * g],     ql[kk], kh[0], kh[1]);
                mma_bf16(s[2 * g + 1], ql[kk], kh[2], kh[3]);
                uint32_t kl[4];
                ldsm_x4(kl, sb + FTS_KLO + sw);
                mma_bf16(s[2 * g],     qh[kk], kl[0], kl[1]);
                mma_bf16(s[2 * g + 1], qh[kk], kl[2], kl[3]);
            }
        }

        // ---- scale + causal mask
        const bool diag = (k0 + 63 > q0 + wid * 16);
        #pragma unroll
        for (int j = 0; j < 8; ++j) {
            #pragma unroll
            for (int r2 = 0; r2 < 2; ++r2) {
                int qrow = q0 + wid * 16 + g8 + 8 * r2;
                #pragma unroll
                for (int e = 0; e < 2; ++e) {
                    float v = s[j][2 * r2 + e] * 0.125f;
                    if (diag && (k0 + j * 8 + t2 + e > qrow)) v = -1e30f;
                    s[j][2 * r2 + e] = v;
                }
            }
        }

        // ---- online softmax per row-half
        #pragma unroll
        for (int r2 = 0; r2 < 2; ++r2) {
            float mx = -INFINITY;
            #pragma unroll
            for (int j = 0; j < 8; ++j)
                mx = fmaxf(mx, fmaxf(s[j][2 * r2], s[j][2 * r2 + 1]));
            mx = fmaxf(mx, __shfl_xor_sync(0xffffffffu, mx, 1));
            mx = fmaxf(mx, __shfl_xor_sync(0xffffffffu, mx, 2));
            float mnew = fmaxf(mrow[r2], mx);
            float alpha = fast_exp2((mrow[r2] - mnew) * LOG2E);
            mrow[r2] = mnew;
            float ls = 0.0f;
            #pragma unroll
            for (int j = 0; j < 8; ++j) {
                float p0 = fast_exp2((s[j][2 * r2] - mnew) * LOG2E);
                float p1 = fast_exp2((s[j][2 * r2 + 1] - mnew) * LOG2E);
                s[j][2 * r2] = p0;
                s[j][2 * r2 + 1] = p1;
                ls += p0 + p1;
            }
            ls += __shfl_xor_sync(0xffffffffu, ls, 1);
            ls += __shfl_xor_sync(0xffffffffu, ls, 2);
            lrow[r2] = lrow[r2] * alpha + ls;
            #pragma unroll
            for (int j = 0; j < 8; ++j) {
                o[j][2 * r2] *= alpha;
                o[j][2 * r2 + 1] *= alpha;
            }
        }

        // ---- O += P @ V (split: ph@vh + ph@vl + pl@vh)
        #pragma unroll
        for (int kk = 0; kk < 4; ++kk) {
            // P A-frags for k-chunk kk from S n-tiles 2kk, 2kk+1
            uint32_t ph[4], pl[4];
            split2(s[2 * kk][0],     s[2 * kk][1],     ph[0], pl[0]);
            split2(s[2 * kk][2],     s[2 * kk][3],     ph[1], pl[1]);
            split2(s[2 * kk + 1][0], s[2 * kk + 1][1], ph[2], pl[2]);
            split2(s[2 * kk + 1][2], s[2 * kk + 1][3], ph[3], pl[3]);
            // V B-frags via ldmatrix.trans
            int vrow = kk * 16 + (lid & 7) + ((lid >> 3) & 1) * 8;
            #pragma unroll
            for (int j2 = 0; j2 < 4; ++j2) {
                uint32_t sw = (uint32_t)(vrow * 128 + j2 * 32 + ((lid >> 4) & 1) * 16)
                              ^ ((uint32_t)(vrow & 7) << 4);
                uint32_t vh[4];
                ldsm_x4_t(vh, sb + FTS_VHI + sw);
                mma_bf16(o[2 * j2],     ph, vh[0], vh[1]);
                mma_bf16(o[2 * j2 + 1], ph, vh[2], vh[3]);
                mma_bf16(o[2 * j2],     pl, vh[0], vh[1]);
                mma_bf16(o[2 * j2 + 1], pl, vh[2], vh[3]);
                uint32_t vl[4];
                ldsm_x4_t(vl, sb + FTS_VLO + sw);
                mma_bf16(o[2 * j2],     ph, vl[0], vl[1]);
                mma_bf16(o[2 * j2 + 1], ph, vl[2], vl[3]);
            }
        }
    }

    // ---- Epilogue: normalize, split to bf16 hi/lo, store ctx
    float inv0 = 1.0f / lrow[0], inv1 = 1.0f / lrow[1];
    size_t row0 = (size_t)(b * S_LEN + q0 + wid * 16 + g8);
    #pragma unroll
    for (int j = 0; j < 8; ++j) {
        int c = h * HDIM + j * 8 + t2;
        uint32_t hi0, lo0, hi1, lo1;
        split2(o[j][0] * inv0, o[j][1] * inv0, hi0, lo0);
        split2(o[j][2] * inv1, o[j][3] * inv1, hi1, lo1);
        *reinterpret_cast<uint32_t*>(&ctxhi[row0 * DM + c]) = hi0;
        *reinterpret_cast<uint32_t*>(&ctxlo[row0 * DM + c]) = lo0;
        *reinterpret_cast<uint32_t*>(&ctxhi[(row0 + 8) * DM + c]) = hi1;
        *reinterpret_cast<uint32_t*>(&ctxlo[(row0 + 8) * DM + c]) = lo1;
    }
}

// ---------------------------------------------------------------------------
extern "C" void kernel_launch(void* const* d_in, const int* in_sizes, int n_in,
                              void* d_out, int out_size)
{
    const float* x    = (const float*)d_in[0];
    const float* Wqkv = (const float*)d_in[1];
    const float* bqkv = (const float*)d_in[2];
    const float* Wout = (const float*)d_in[3];
    const float* bout = (const float*)d_in[4];
    float* out = (float*)d_out;

    __nv_bfloat16 *qkvhi, *qkvlo, *xhi, *xlo, *ctxhi, *ctxlo;
    __nv_bfloat16 *wqhi, *wqlo, *wohi, *wolo;
    cudaGetSymbolAddress((void**)&qkvhi, g_qkvhi);
    cudaGetSymbolAddress((void**)&qkvlo, g_qkvlo);
    cudaGetSymbolAddress((void**)&xhi, g_xhi);
    cudaGetSymbolAddress((void**)&xlo, g_xlo);
    cudaGetSymbolAddress((void**)&ctxhi, g_ctxhi);
    cudaGetSymbolAddress((void**)&ctxlo, g_ctxlo);
    cudaGetSymbolAddress((void**)&wqhi, g_wqkvThi);
    cudaGetSymbolAddress((void**)&wqlo, g_wqkvTlo);
    cudaGetSymbolAddress((void**)&wohi, g_woutThi);
    cudaGetSymbolAddress((void**)&wolo, g_woutTlo);

    cudaFuncSetAttribute(gemm_mma<0>, cudaFuncAttributeMaxDynamicSharedMemorySize, GEMM_SMEM);
    cudaFuncSetAttribute(gemm_mma<1>, cudaFuncAttributeMaxDynamicSharedMemorySize, GEMM_SMEM);
    cudaFuncSetAttribute(flash_tc, cudaFuncAttributeMaxDynamicSharedMemorySize, FLASH_SMEM_TC);

    // 0) Split inputs / weights to bf16 hi/lo
    int nx4 = MROWS * DM / 4;
    split_f32<<<(nx4 + 255) / 256, 256>>>(x, xhi, xlo, nx4);
    splitT_f32<<<dim3(3 * DM / 32, DM / 32), 256>>>(Wqkv, wqhi, wqlo, DM, 3 * DM);
    splitT_f32<<<dim3(DM / 32, DM / 32), 256>>>(Wout, wohi, wolo, DM, DM);

    // 1) QKV projection -> split bf16 qkv directly
    gemm_mma<1><<<dim3(3 * DM / 128, MROWS / 128), 256, GEMM_SMEM>>>(
        xhi, xlo, wqhi, wqlo, bqkv, nullptr, qkvhi, qkvlo, MROWS, 3 * DM, DM);

    // 2) Tensor-core causal flash attention -> split bf16 ctx directly
    flash_tc<<<dim3(S_LEN / 128, BATCH * NHEADS), 256, FLASH_SMEM_TC>>>(
        qkvhi, qkvlo, ctxhi, ctxlo);

    // 3) Output projection -> f32 out
    gemm_mma<0><<<dim3(DM / 128, MROWS / 128), 256, GEMM_SMEM>>>(
        ctxhi, ctxlo, wohi, wolo, bout, out, nullptr, nullptr, MROWS, DM, DM);
}

// round 6
// speedup vs baseline: 2.9271x; 1.1041x over previous
#include <cuda_runtime.h>
#include <cuda_bf16.h>
#include <cstdint>
#include <math.h>

#define S_LEN   2048
#define DM      1024
#define NHEADS  16
#define HDIM    64
#define BATCH   2
#define MROWS   (BATCH * S_LEN)   // 4096

// ---------------------------------------------------------------------------
// Scratch (device globals; no runtime allocation allowed)
// ---------------------------------------------------------------------------
__device__ __align__(256) __nv_bfloat16 g_qkvhi[MROWS * 3 * DM];
__device__ __align__(256) __nv_bfloat16 g_qkvlo[MROWS * 3 * DM];
__device__ __align__(256) __nv_bfloat16 g_xhi[MROWS * DM];
__device__ __align__(256) __nv_bfloat16 g_xlo[MROWS * DM];
__device__ __align__(256) __nv_bfloat16 g_ctxhi[MROWS * DM];
__device__ __align__(256) __nv_bfloat16 g_ctxlo[MROWS * DM];
__device__ __align__(256) __nv_bfloat16 g_wqkvThi[3 * DM * DM];
__device__ __align__(256) __nv_bfloat16 g_wqkvTlo[3 * DM * DM];
__device__ __align__(256) __nv_bfloat16 g_woutThi[DM * DM];
__device__ __align__(256) __nv_bfloat16 g_woutTlo[DM * DM];

// ---------------------------------------------------------------------------
// Helpers
// ---------------------------------------------------------------------------
__device__ __forceinline__ uint32_t smem_to_u32(const void* p) {
    uint32_t a;
    asm("{ .reg .u64 t; cvta.to.shared.u64 t, %1; cvt.u32.u64 %0, t; }" : "=r"(a) : "l"(p));
    return a;
}
#define SMEM_SWIZZLE_128B(off) ((off) ^ (((off) >> 3) & 0x70))
#define SMEM_SWIZZLE_64B(off)  ((off) ^ (((off) >> 3) & 0x30))

__device__ __forceinline__ void cp16(uint32_t dst, const void* src) {
    asm volatile("cp.async.cg.shared.global [%0], [%1], 16;" :: "r"(dst), "l"(src));
}
#define CP_COMMIT()    asm volatile("cp.async.commit_group;" ::: "memory")
#define CP_WAIT(n)     asm volatile("cp.async.wait_group %0;" :: "n"(n) : "memory")

__device__ __forceinline__ void ldsm_x4(uint32_t (&r)[4], uint32_t addr) {
    asm volatile("ldmatrix.sync.aligned.m8n8.x4.shared.b16 {%0,%1,%2,%3}, [%4];"
        : "=r"(r[0]), "=r"(r[1]), "=r"(r[2]), "=r"(r[3]) : "r"(addr));
}
__device__ __forceinline__ void ldsm_x4_t(uint32_t (&r)[4], uint32_t addr) {
    asm volatile("ldmatrix.sync.aligned.m8n8.x4.trans.shared.b16 {%0,%1,%2,%3}, [%4];"
        : "=r"(r[0]), "=r"(r[1]), "=r"(r[2]), "=r"(r[3]) : "r"(addr));
}
__device__ __forceinline__ void mma_bf16(float (&c)[4], const uint32_t (&a)[4],
                                         uint32_t b0, uint32_t b1) {
    asm volatile("mma.sync.aligned.m16n8k16.row.col.f32.bf16.bf16.f32 "
        "{%0,%1,%2,%3}, {%4,%5,%6,%7}, {%8,%9}, {%0,%1,%2,%3};"
        : "+f"(c[0]), "+f"(c[1]), "+f"(c[2]), "+f"(c[3])
        : "r"(a[0]), "r"(a[1]), "r"(a[2]), "r"(a[3]), "r"(b0), "r"(b1));
}
__device__ __forceinline__ float fast_exp2(float x) {
    float y;
    asm("ex2.approx.ftz.f32 %0, %1;" : "=f"(y) : "f"(x));
    return y;
}
__device__ __forceinline__ void split2(float v0, float v1, uint32_t& hi, uint32_t& lo) {
    __nv_bfloat16 h0 = __float2bfloat16(v0), h1 = __float2bfloat16(v1);
    __nv_bfloat16 l0 = __float2bfloat16(v0 - __bfloat162float(h0));
    __nv_bfloat16 l1 = __float2bfloat16(v1 - __bfloat162float(h1));
    __nv_bfloat162 hp = __halves2bfloat162(h0, h1);
    __nv_bfloat162 lp = __halves2bfloat162(l0, l1);
    hi = *reinterpret_cast<uint32_t*>(&hp);
    lo = *reinterpret_cast<uint32_t*>(&lp);
}

// ---------------------------------------------------------------------------
// Split kernels: f32 -> (hi, lo) bf16
// ---------------------------------------------------------------------------
__global__ __launch_bounds__(256) void split_f32(
    const float* __restrict__ src, __nv_bfloat16* __restrict__ hi,
    __nv_bfloat16* __restrict__ lo, int n4)
{
    int i = blockIdx.x * 256 + threadIdx.x;
    if (i >= n4) return;
    float4 v = reinterpret_cast<const float4*>(src)[i];
    __nv_bfloat16 h[4], l[4];
    float vv[4] = {v.x, v.y, v.z, v.w};
    #pragma unroll
    for (int j = 0; j < 4; j++) {
        h[j] = __float2bfloat16(vv[j]);
        l[j] = __float2bfloat16(vv[j] - __bfloat162float(h[j]));
    }
    reinterpret_cast<uint2*>(hi)[i] = *reinterpret_cast<uint2*>(h);
    reinterpret_cast<uint2*>(lo)[i] = *reinterpret_cast<uint2*>(l);
}

__global__ __launch_bounds__(256) void splitT_f32(
    const float* __restrict__ W, __nv_bfloat16* __restrict__ hiT,
    __nv_bfloat16* __restrict__ loT, int K, int N)
{
    __shared__ float t[32][33];
    const int kb = blockIdx.y * 32, nb = blockIdx.x * 32;
    const int tx = threadIdx.x & 31, ty0 = threadIdx.x >> 5;
    #pragma unroll
    for (int r = ty0; r < 32; r += 8)
        t[r][tx] = W[(size_t)(kb + r) * N + nb + tx];
    __syncthreads();
    #pragma unroll
    for (int r = ty0; r < 32; r += 8) {
        float v = t[tx][r];
        __nv_bfloat16 h = __float2bfloat16(v);
        __nv_bfloat16 l = __float2bfloat16(v - __bfloat162float(h));
        size_t o = (size_t)(nb + r) * K + kb + tx;
        hiT[o] = h;
        loT[o] = l;
    }
}

// ---------------------------------------------------------------------------
// mma.sync bf16 split-GEMM + bias, cp.async double-buffered.
// CTA 128x128, BK=32 stages x2, 8 warps of 64x32, HMMA m16n8k16.
// MODE 0: write f32 C. MODE 1: write split bf16 (Chi, Clo).
// ---------------------------------------------------------------------------
#define GS_TILE   8192                       // 128 rows x 32 bf16 (64B rows)
#define GS_STAGE  (4 * GS_TILE)              // 32768
#define GEMM_SMEM (2 * GS_STAGE)             // 65536

template<int MODE>
__global__ __launch_bounds__(256, 2) void gemm_mma(
    const __nv_bfloat16* __restrict__ Ahi, const __nv_bfloat16* __restrict__ Alo,
    const __nv_bfloat16* __restrict__ Bhi, const __nv_bfloat16* __restrict__ Blo,
    const float* __restrict__ bias, float* __restrict__ C,
    __nv_bfloat16* __restrict__ Chi, __nv_bfloat16* __restrict__ Clo,
    int M, int N, int K)
{
    extern __shared__ char smem[];
    const uint32_t sb = smem_to_u32(smem);
    const int tid = threadIdx.x;
    const int wid = tid >> 5, lid = tid & 31;
    const int wm = wid & 1;
    const int wn = wid >> 1;
    const int m0 = blockIdx.y * 128, n0 = blockIdx.x * 128;

    float acc[4][4][4];
    #pragma unroll
    for (int i = 0; i < 4; i++)
        #pragma unroll
        for (int j = 0; j < 4; j++)
            #pragma unroll
            for (int r = 0; r < 4; r++) acc[i][j][r] = 0.0f;

    const int a_row  = (lid & 7) + ((lid >> 3) & 1) * 8;
    const int a_koff = (lid >> 4) << 3;
    const int b_row  = ((lid >> 4) << 3) + (lid & 7);
    const int b_koff = ((lid >> 3) & 1) << 3;

    const int nStages = K >> 5;

    // stage loader: 4 tiles x 128 rows x 64B, SW64 swizzle
    auto load_stage = [&](int buf, int k0) {
        uint32_t sbase = sb + buf * GS_STAGE;
        #pragma unroll
        for (int t = 0; t < 4; ++t) {
            const __nv_bfloat16* src = (t == 0) ? Ahi : (t == 1) ? Alo
                                     : (t == 2) ? Bhi : Blo;
            const int r0 = (t < 2) ? m0 : n0;
            #pragma unroll
            for (int p = 0; p < 2; ++p) {
                int idx = tid + p * 256;          // 0..511
                int r = idx >> 2;                 // 0..127
                int c = (idx & 3) << 3;           // 0..24 (bf16 cols)
                uint32_t off = (uint32_t)(r * 64 + c * 2);
                cp16(sbase + t * GS_TILE + SMEM_SWIZZLE_64B(off),
                     src + (size_t)(r0 + r) * K + k0 + c);
            }
        }
    };

    load_stage(0, 0);
    CP_COMMIT();

    for (int it = 0; it < nStages; ++it) {
        if (it + 1 < nStages) {
            load_stage((it + 1) & 1, (it + 1) << 5);
            CP_COMMIT();
            CP_WAIT(1);
        } else {
            CP_WAIT(0);
        }
        __syncthreads();

        const uint32_t stage = sb + (it & 1) * GS_STAGE;
        #pragma unroll
        for (int ks = 0; ks < 2; ++ks) {
            const int kk = ks << 4;
            uint32_t ah[4][4], al[4][4];
            #pragma unroll
            for (int mi = 0; mi < 4; ++mi) {
                int rg = wm * 64 + mi * 16 + a_row;
                uint32_t off = (uint32_t)(rg * 64 + (kk + a_koff) * 2);
                off = SMEM_SWIZZLE_64B(off);
                ldsm_x4(ah[mi], stage + off);
                ldsm_x4(al[mi], stage + GS_TILE + off);
            }
            #pragma unroll
            for (int g = 0; g < 2; ++g) {
                int rg = wn * 32 + g * 16 + b_row;
                uint32_t off = (uint32_t)(rg * 64 + (kk + b_koff) * 2);
                off = SMEM_SWIZZLE_64B(off);
                uint32_t bh[4];
                ldsm_x4(bh, stage + 2 * GS_TILE + off);
                #pragma unroll
                for (int mi = 0; mi < 4; ++mi) {
                    mma_bf16(acc[mi][2 * g],     ah[mi], bh[0], bh[1]);
                    mma_bf16(acc[mi][2 * g + 1], ah[mi], bh[2], bh[3]);
                    mma_bf16(acc[mi][2 * g],     al[mi], bh[0], bh[1]);
                    mma_bf16(acc[mi][2 * g + 1], al[mi], bh[2], bh[3]);
                }
                uint32_t bl[4];
                ldsm_x4(bl, stage + 3 * GS_TILE + off);
                #pragma unroll
                for (int mi = 0; mi < 4; ++mi) {
                    mma_bf16(acc[mi][2 * g],     ah[mi], bl[0], bl[1]);
                    mma_bf16(acc[mi][2 * g + 1], ah[mi], bl[2], bl[3]);
                }
            }
        }
        __syncthreads();   // all reads done before next prefetch overwrites
    }

    const int cg = lid >> 2, ct = lid & 3;
    #pragma unroll
    for (int mi = 0; mi < 4; ++mi) {
        #pragma unroll
        for (int ni = 0; ni < 4; ++ni) {
            int row = m0 + wm * 64 + mi * 16 + cg;
            int col = n0 + wn * 32 + ni * 8 + 2 * ct;
            float2 bv = *reinterpret_cast<const float2*>(&bias[col]);
            float v00 = acc[mi][ni][0] + bv.x, v01 = acc[mi][ni][1] + bv.y;
            float v10 = acc[mi][ni][2] + bv.x, v11 = acc[mi][ni][3] + bv.y;
            if (MODE == 0) {
                float2 o0 = {v00, v01}, o1 = {v10, v11};
                *reinterpret_cast<float2*>(&C[(size_t)row * N + col]) = o0;
                *reinterpret_cast<float2*>(&C[(size_t)(row + 8) * N + col]) = o1;
            } else {
                uint32_t h, l;
                split2(v00, v01, h, l);
                *reinterpret_cast<uint32_t*>(&Chi[(size_t)row * N + col]) = h;
                *reinterpret_cast<uint32_t*>(&Clo[(size_t)row * N + col]) = l;
                split2(v10, v11, h, l);
                *reinterpret_cast<uint32_t*>(&Chi[(size_t)(row + 8) * N + col]) = h;
                *reinterpret_cast<uint32_t*>(&Clo[(size_t)(row + 8) * N + col]) = l;
            }
        }
    }
}

// ---------------------------------------------------------------------------
// Tensor-core flash attention (split-bf16, HMMA), cp.async double-buffered KV.
// Block: (q-tile of 128, b*h). 8 warps, each owns 16 q-rows.
// ---------------------------------------------------------------------------
#define FTS_QHI   0
#define FTS_QLO   16384
#define FKV_BASE  32768
#define FKV_STAGE 32768      // khi 8K, klo 8K, vhi 8K, vlo 8K
#define FLASH_SMEM_TC (FKV_BASE + 2 * FKV_STAGE)   // 98304

__global__ __launch_bounds__(256, 2) void flash_tc(
    const __nv_bfloat16* __restrict__ qkvhi, const __nv_bfloat16* __restrict__ qkvlo,
    __nv_bfloat16* __restrict__ ctxhi, __nv_bfloat16* __restrict__ ctxlo)
{
    extern __shared__ char smem[];
    const uint32_t sb = smem_to_u32(smem);
    const int tid = threadIdx.x;
    const int wid = tid >> 5, lid = tid & 31;
    const int qt = blockIdx.x;
    const int bh = blockIdx.y;
    const int b = bh >> 4, h = bh & 15;
    const int q0 = qt * 128;
    const float LOG2E = 1.4426950408889634f;

    // ---- KV stage loader (cp.async)
    auto load_kv = [&](int buf, int k0) {
        uint32_t sbase = sb + FKV_BASE + buf * FKV_STAGE;
        #pragma unroll
        for (int t = 0; t < 4; ++t) {
            const __nv_bfloat16* src = (t & 1) ? qkvlo : qkvhi;
            const int coloff = (t < 2) ? DM : 2 * DM;
            #pragma unroll
            for (int p = 0; p < 2; ++p) {
                int idx = tid + p * 256;
                int r = idx >> 3;                  // 0..63
                int c = (idx & 7) << 3;            // 0..56
                uint32_t off = (uint32_t)(r * 128 + c * 2);
                cp16(sbase + t * 8192 + SMEM_SWIZZLE_128B(off),
                     src + (size_t)(b * S_LEN + k0 + r) * (3 * DM) + coloff + h * HDIM + c);
            }
        }
    };

    // ---- Load Q tiles (hi/lo) into smem, swizzled (plain loads)
    #pragma unroll
    for (int t = 0; t < 2; ++t) {
        const __nv_bfloat16* src = t ? qkvlo : qkvhi;
        char* base = smem + (t ? FTS_QLO : FTS_QHI);
        #pragma unroll
        for (int p = 0; p < 4; ++p) {
            int idx = tid + p * 256;
            int r = idx >> 3;
            int c = (idx & 7) << 3;
            uint4 v = *reinterpret_cast<const uint4*>(
                src + (size_t)(b * S_LEN + q0 + r) * (3 * DM) + h * HDIM + c);
            uint32_t off = (uint32_t)(r * 128 + c * 2);
            *reinterpret_cast<uint4*>(base + SMEM_SWIZZLE_128B(off)) = v;
        }
    }
    // prefetch first KV stage
    load_kv(0, 0);
    CP_COMMIT();
    __syncthreads();

    // ---- Q fragments (registers for the whole kernel)
    const int a_row  = (lid & 7) + ((lid >> 3) & 1) * 8;
    const int a_koff = (lid >> 4) << 3;
    const int b_row  = ((lid >> 4) << 3) + (lid & 7);
    const int b_koff = ((lid >> 3) & 1) << 3;
    uint32_t qh[4][4], ql[4][4];
    #pragma unroll
    for (int kk = 0; kk < 4; ++kk) {
        int rg = wid * 16 + a_row;
        uint32_t sw = (uint32_t)(rg * 128 + (kk * 16 + a_koff) * 2)
                      ^ ((uint32_t)(rg & 7) << 4);
        ldsm_x4(qh[kk], sb + FTS_QHI + sw);
        ldsm_x4(ql[kk], sb + FTS_QLO + sw);
    }

    float o[8][4];
    #pragma unroll
    for (int j = 0; j < 8; ++j)
        #pragma unroll
        for (int r = 0; r < 4; ++r) o[j][r] = 0.0f;
    float mrow[2] = {-INFINITY, -INFINITY};
    float lrow[2] = {0.0f, 0.0f};

    const int g8 = lid >> 2, t2 = (lid & 3) * 2;
    const int nkt = 2 * qt + 2;

    for (int kt = 0; kt < nkt; ++kt) {
        const int k0 = kt * 64;
        if (kt + 1 < nkt) {
            load_kv((kt + 1) & 1, (kt + 1) * 64);
            CP_COMMIT();
            CP_WAIT(1);
        } else {
            CP_WAIT(0);
        }
        __syncthreads();

        const uint32_t kvs = sb + FKV_BASE + (kt & 1) * FKV_STAGE;

        if (q0 + wid * 16 + 15 >= k0) {
            // ---- S = Q @ K^T
            float s[8][4];
            #pragma unroll
            for (int j = 0; j < 8; ++j)
                #pragma unroll
                for (int r = 0; r < 4; ++r) s[j][r] = 0.0f;

            #pragma unroll
            for (int g = 0; g < 4; ++g) {
                #pragma unroll
                for (int kk = 0; kk < 4; ++kk) {
                    int rg = g * 16 + b_row;
                    uint32_t sw = (uint32_t)(rg * 128 + (kk * 16 + b_koff) * 2)
                                  ^ ((uint32_t)(rg & 7) << 4);
                    uint32_t kh[4];
                    ldsm_x4(kh, kvs + sw);
                    mma_bf16(s[2 * g],     qh[kk], kh[0], kh[1]);
                    mma_bf16(s[2 * g + 1], qh[kk], kh[2], kh[3]);
                    mma_bf16(s[2 * g],     ql[kk], kh[0], kh[1]);
                    mma_bf16(s[2 * g + 1], ql[kk], kh[2], kh[3]);
                    uint32_t kl[4];
                    ldsm_x4(kl, kvs + 8192 + sw);
                    mma_bf16(s[2 * g],     qh[kk], kl[0], kl[1]);
                    mma_bf16(s[2 * g + 1], qh[kk], kl[2], kl[3]);
                }
            }

            // ---- scale + causal mask
            const bool diag = (k0 + 63 > q0 + wid * 16);
            #pragma unroll
            for (int j = 0; j < 8; ++j) {
                #pragma unroll
                for (int r2 = 0; r2 < 2; ++r2) {
                    int qrow = q0 + wid * 16 + g8 + 8 * r2;
                    #pragma unroll
                    for (int e = 0; e < 2; ++e) {
                        float v = s[j][2 * r2 + e] * 0.125f;
                        if (diag && (k0 + j * 8 + t2 + e > qrow)) v = -1e30f;
                        s[j][2 * r2 + e] = v;
                    }
                }
            }

            // ---- online softmax per row-half
            #pragma unroll
            for (int r2 = 0; r2 < 2; ++r2) {
                float mx = -INFINITY;
                #pragma unroll
                for (int j = 0; j < 8; ++j)
                    mx = fmaxf(mx, fmaxf(s[j][2 * r2], s[j][2 * r2 + 1]));
                mx = fmaxf(mx, __shfl_xor_sync(0xffffffffu, mx, 1));
                mx = fmaxf(mx, __shfl_xor_sync(0xffffffffu, mx, 2));
                float mnew = fmaxf(mrow[r2], mx);
                float alpha = fast_exp2((mrow[r2] - mnew) * LOG2E);
                mrow[r2] = mnew;
                float ls = 0.0f;
                #pragma unroll
                for (int j = 0; j < 8; ++j) {
                    float p0 = fast_exp2((s[j][2 * r2] - mnew) * LOG2E);
                    float p1 = fast_exp2((s[j][2 * r2 + 1] - mnew) * LOG2E);
                    s[j][2 * r2] = p0;
                    s[j][2 * r2 + 1] = p1;
                    ls += p0 + p1;
                }
                ls += __shfl_xor_sync(0xffffffffu, ls, 1);
                ls += __shfl_xor_sync(0xffffffffu, ls, 2);
                lrow[r2] = lrow[r2] * alpha + ls;
                #pragma unroll
                for (int j = 0; j < 8; ++j) {
                    o[j][2 * r2] *= alpha;
                    o[j][2 * r2 + 1] *= alpha;
                }
            }

            // ---- O += P @ V
            #pragma unroll
            for (int kk = 0; kk < 4; ++kk) {
                uint32_t ph[4], pl[4];
                split2(s[2 * kk][0],     s[2 * kk][1],     ph[0], pl[0]);
                split2(s[2 * kk][2],     s[2 * kk][3],     ph[1], pl[1]);
                split2(s[2 * kk + 1][0], s[2 * kk + 1][1], ph[2], pl[2]);
                split2(s[2 * kk + 1][2], s[2 * kk + 1][3], ph[3], pl[3]);
                int vrow = kk * 16 + (lid & 7) + ((lid >> 3) & 1) * 8;
                #pragma unroll
                for (int j2 = 0; j2 < 4; ++j2) {
                    uint32_t sw = (uint32_t)(vrow * 128 + j2 * 32 + ((lid >> 4) & 1) * 16)
                                  ^ ((uint32_t)(vrow & 7) << 4);
                    uint32_t vh[4];
                    ldsm_x4_t(vh, kvs + 16384 + sw);
                    mma_bf16(o[2 * j2],     ph, vh[0], vh[1]);
                    mma_bf16(o[2 * j2 + 1], ph, vh[2], vh[3]);
                    mma_bf16(o[2 * j2],     pl, vh[0], vh[1]);
                    mma_bf16(o[2 * j2 + 1], pl, vh[2], vh[3]);
                    uint32_t vl[4];
                    ldsm_x4_t(vl, kvs + 24576 + sw);
                    mma_bf16(o[2 * j2],     ph, vl[0], vl[1]);
                    mma_bf16(o[2 * j2 + 1], ph, vl[2], vl[3]);
                }
            }
        }
        __syncthreads();   // all reads done before next prefetch overwrites
    }

    // ---- Epilogue
    float inv0 = 1.0f / lrow[0], inv1 = 1.0f / lrow[1];
    size_t row0 = (size_t)(b * S_LEN + q0 + wid * 16 + g8);
    #pragma unroll
    for (int j = 0; j < 8; ++j) {
        int c = h * HDIM + j * 8 + t2;
        uint32_t hi0, lo0, hi1, lo1;
        split2(o[j][0] * inv0, o[j][1] * inv0, hi0, lo0);
        split2(o[j][2] * inv1, o[j][3] * inv1, hi1, lo1);
        *reinterpret_cast<uint32_t*>(&ctxhi[row0 * DM + c]) = hi0;
        *reinterpret_cast<uint32_t*>(&ctxlo[row0 * DM + c]) = lo0;
        *reinterpret_cast<uint32_t*>(&ctxhi[(row0 + 8) * DM + c]) = hi1;
        *reinterpret_cast<uint32_t*>(&ctxlo[(row0 + 8) * DM + c]) = lo1;
    }
}

// ---------------------------------------------------------------------------
extern "C" void kernel_launch(void* const* d_in, const int* in_sizes, int n_in,
                              void* d_out, int out_size)
{
    const float* x    = (const float*)d_in[0];
    const float* Wqkv = (const float*)d_in[1];
    const float* bqkv = (const float*)d_in[2];
    const float* Wout = (const float*)d_in[3];
    const float* bout = (const float*)d_in[4];
    float* out = (float*)d_out;

    __nv_bfloat16 *qkvhi, *qkvlo, *xhi, *xlo, *ctxhi, *ctxlo;
    __nv_bfloat16 *wqhi, *wqlo, *wohi, *wolo;
    cudaGetSymbolAddress((void**)&qkvhi, g_qkvhi);
    cudaGetSymbolAddress((void**)&qkvlo, g_qkvlo);
    cudaGetSymbolAddress((void**)&xhi, g_xhi);
    cudaGetSymbolAddress((void**)&xlo, g_xlo);
    cudaGetSymbolAddress((void**)&ctxhi, g_ctxhi);
    cudaGetSymbolAddress((void**)&ctxlo, g_ctxlo);
    cudaGetSymbolAddress((void**)&wqhi, g_wqkvThi);
    cudaGetSymbolAddress((void**)&wqlo, g_wqkvTlo);
    cudaGetSymbolAddress((void**)&wohi, g_woutThi);
    cudaGetSymbolAddress((void**)&wolo, g_woutTlo);

    cudaFuncSetAttribute(gemm_mma<0>, cudaFuncAttributeMaxDynamicSharedMemorySize, GEMM_SMEM);
    cudaFuncSetAttribute(gemm_mma<1>, cudaFuncAttributeMaxDynamicSharedMemorySize, GEMM_SMEM);
    cudaFuncSetAttribute(flash_tc, cudaFuncAttributeMaxDynamicSharedMemorySize, FLASH_SMEM_TC);

    // 0) Split inputs / weights to bf16 hi/lo
    int nx4 = MROWS * DM / 4;
    split_f32<<<(nx4 + 255) / 256, 256>>>(x, xhi, xlo, nx4);
    splitT_f32<<<dim3(3 * DM / 32, DM / 32), 256>>>(Wqkv, wqhi, wqlo, DM, 3 * DM);
    splitT_f32<<<dim3(DM / 32, DM / 32), 256>>>(Wout, wohi, wolo, DM, DM);

    // 1) QKV projection -> split bf16 qkv directly
    gemm_mma<1><<<dim3(3 * DM / 128, MROWS / 128), 256, GEMM_SMEM>>>(
        xhi, xlo, wqhi, wqlo, bqkv, nullptr, qkvhi, qkvlo, MROWS, 3 * DM, DM);

    // 2) Tensor-core causal flash attention -> split bf16 ctx directly
    flash_tc<<<dim3(S_LEN / 128, BATCH * NHEADS), 256, FLASH_SMEM_TC>>>(
        qkvhi, qkvlo, ctxhi, ctxlo);

    // 3) Output projection -> f32 out
    gemm_mma<0><<<dim3(DM / 128, MROWS / 128), 256, GEMM_SMEM>>>(
        ctxhi, ctxlo, wohi, wolo, bout, out, nullptr, nullptr, MROWS, DM, DM);
}

// round 7
// speedup vs baseline: 3.3004x; 1.1275x over previous
#include <cuda_runtime.h>
#include <cuda_bf16.h>
#include <cstdint>
#include <math.h>

#define S_LEN   2048
#define DM      1024
#define NHEADS  16
#define HDIM    64
#define BATCH   2
#define MROWS   (BATCH * S_LEN)   // 4096

// ---------------------------------------------------------------------------
// Scratch (device globals; no runtime allocation allowed)
// ---------------------------------------------------------------------------
__device__ __align__(256) __nv_bfloat16 g_qkvhi[MROWS * 3 * DM];
__device__ __align__(256) __nv_bfloat16 g_qkvlo[MROWS * 3 * DM];
__device__ __align__(256) __nv_bfloat16 g_xhi[MROWS * DM];
__device__ __align__(256) __nv_bfloat16 g_xlo[MROWS * DM];
__device__ __align__(256) __nv_bfloat16 g_ctxhi[MROWS * DM];
__device__ __align__(256) __nv_bfloat16 g_ctxlo[MROWS * DM];
__device__ __align__(256) __nv_bfloat16 g_wqkvThi[3 * DM * DM];
__device__ __align__(256) __nv_bfloat16 g_wqkvTlo[3 * DM * DM];
__device__ __align__(256) __nv_bfloat16 g_woutThi[DM * DM];
__device__ __align__(256) __nv_bfloat16 g_woutTlo[DM * DM];

// ---------------------------------------------------------------------------
// Helpers
// ---------------------------------------------------------------------------
__device__ __forceinline__ uint32_t smem_to_u32(const void* p) {
    uint32_t a;
    asm("{ .reg .u64 t; cvta.to.shared.u64 t, %1; cvt.u32.u64 %0, t; }" : "=r"(a) : "l"(p));
    return a;
}
#define SMEM_SWIZZLE_128B(off) ((off) ^ (((off) >> 3) & 0x70))
#define SMEM_SWIZZLE_64B(off)  ((off) ^ (((off) >> 3) & 0x30))

__device__ __forceinline__ void cp16(uint32_t dst, const void* src) {
    asm volatile("cp.async.cg.shared.global [%0], [%1], 16;" :: "r"(dst), "l"(src));
}
#define CP_COMMIT()    asm volatile("cp.async.commit_group;" ::: "memory")
#define CP_WAIT(n)     asm volatile("cp.async.wait_group %0;" :: "n"(n) : "memory")

__device__ __forceinline__ void ldsm_x4(uint32_t (&r)[4], uint32_t addr) {
    asm volatile("ldmatrix.sync.aligned.m8n8.x4.shared.b16 {%0,%1,%2,%3}, [%4];"
        : "=r"(r[0]), "=r"(r[1]), "=r"(r[2]), "=r"(r[3]) : "r"(addr));
}
__device__ __forceinline__ void ldsm_x4_t(uint32_t (&r)[4], uint32_t addr) {
    asm volatile("ldmatrix.sync.aligned.m8n8.x4.trans.shared.b16 {%0,%1,%2,%3}, [%4];"
        : "=r"(r[0]), "=r"(r[1]), "=r"(r[2]), "=r"(r[3]) : "r"(addr));
}
__device__ __forceinline__ void mma_bf16(float (&c)[4], const uint32_t (&a)[4],
                                         uint32_t b0, uint32_t b1) {
    asm volatile("mma.sync.aligned.m16n8k16.row.col.f32.bf16.bf16.f32 "
        "{%0,%1,%2,%3}, {%4,%5,%6,%7}, {%8,%9}, {%0,%1,%2,%3};"
        : "+f"(c[0]), "+f"(c[1]), "+f"(c[2]), "+f"(c[3])
        : "r"(a[0]), "r"(a[1]), "r"(a[2]), "r"(a[3]), "r"(b0), "r"(b1));
}
__device__ __forceinline__ float fast_exp2(float x) {
    float y;
    asm("ex2.approx.ftz.f32 %0, %1;" : "=f"(y) : "f"(x));
    return y;
}
__device__ __forceinline__ void split2(float v0, float v1, uint32_t& hi, uint32_t& lo) {
    __nv_bfloat16 h0 = __float2bfloat16(v0), h1 = __float2bfloat16(v1);
    __nv_bfloat16 l0 = __float2bfloat16(v0 - __bfloat162float(h0));
    __nv_bfloat16 l1 = __float2bfloat16(v1 - __bfloat162float(h1));
    __nv_bfloat162 hp = __halves2bfloat162(h0, h1);
    __nv_bfloat162 lp = __halves2bfloat162(l0, l1);
    hi = *reinterpret_cast<uint32_t*>(&hp);
    lo = *reinterpret_cast<uint32_t*>(&lp);
}

// ---------------------------------------------------------------------------
// Split kernels: f32 -> (hi, lo) bf16
// ---------------------------------------------------------------------------
__global__ __launch_bounds__(256) void split_f32(
    const float* __restrict__ src, __nv_bfloat16* __restrict__ hi,
    __nv_bfloat16* __restrict__ lo, int n4)
{
    int i = blockIdx.x * 256 + threadIdx.x;
    if (i >= n4) return;
    float4 v = reinterpret_cast<const float4*>(src)[i];
    __nv_bfloat16 h[4], l[4];
    float vv[4] = {v.x, v.y, v.z, v.w};
    #pragma unroll
    for (int j = 0; j < 4; j++) {
        h[j] = __float2bfloat16(vv[j]);
        l[j] = __float2bfloat16(vv[j] - __bfloat162float(h[j]));
    }
    reinterpret_cast<uint2*>(hi)[i] = *reinterpret_cast<uint2*>(h);
    reinterpret_cast<uint2*>(lo)[i] = *reinterpret_cast<uint2*>(l);
}

__global__ __launch_bounds__(256) void splitT_f32(
    const float* __restrict__ W, __nv_bfloat16* __restrict__ hiT,
    __nv_bfloat16* __restrict__ loT, int K, int N)
{
    __shared__ float t[32][33];
    const int kb = blockIdx.y * 32, nb = blockIdx.x * 32;
    const int tx = threadIdx.x & 31, ty0 = threadIdx.x >> 5;
    #pragma unroll
    for (int r = ty0; r < 32; r += 8)
        t[r][tx] = W[(size_t)(kb + r) * N + nb + tx];
    __syncthreads();
    #pragma unroll
    for (int r = ty0; r < 32; r += 8) {
        float v = t[tx][r];
        __nv_bfloat16 h = __float2bfloat16(v);
        __nv_bfloat16 l = __float2bfloat16(v - __bfloat162float(h));
        size_t o = (size_t)(nb + r) * K + kb + tx;
        hiT[o] = h;
        loT[o] = l;
    }
}

// ---------------------------------------------------------------------------
// mma.sync bf16 split-GEMM + bias, cp.async double-buffered, 1 bar/iter.
// CTA 128x128, BK=32 stages x2, 8 warps of 64x32, HMMA m16n8k16.
// ---------------------------------------------------------------------------
#define GS_TILE   8192
#define GS_STAGE  (4 * GS_TILE)              // 32768
#define GEMM_SMEM (2 * GS_STAGE)             // 65536

template<int MODE>
__global__ __launch_bounds__(256, 2) void gemm_mma(
    const __nv_bfloat16* __restrict__ Ahi, const __nv_bfloat16* __restrict__ Alo,
    const __nv_bfloat16* __restrict__ Bhi, const __nv_bfloat16* __restrict__ Blo,
    const float* __restrict__ bias, float* __restrict__ C,
    __nv_bfloat16* __restrict__ Chi, __nv_bfloat16* __restrict__ Clo,
    int M, int N, int K)
{
    extern __shared__ char smem[];
    const uint32_t sb = smem_to_u32(smem);
    const int tid = threadIdx.x;
    const int wid = tid >> 5, lid = tid & 31;
    const int wm = wid & 1;
    const int wn = wid >> 1;
    const int m0 = blockIdx.y * 128, n0 = blockIdx.x * 128;

    float acc[4][4][4];
    #pragma unroll
    for (int i = 0; i < 4; i++)
        #pragma unroll
        for (int j = 0; j < 4; j++)
            #pragma unroll
            for (int r = 0; r < 4; r++) acc[i][j][r] = 0.0f;

    const int a_row  = (lid & 7) + ((lid >> 3) & 1) * 8;
    const int a_koff = (lid >> 4) << 3;
    const int b_row  = ((lid >> 4) << 3) + (lid & 7);
    const int b_koff = ((lid >> 3) & 1) << 3;

    const int nStages = K >> 5;

    auto load_stage = [&](int buf, int k0) {
        uint32_t sbase = sb + buf * GS_STAGE;
        #pragma unroll
        for (int t = 0; t < 4; ++t) {
            const __nv_bfloat16* src = (t == 0) ? Ahi : (t == 1) ? Alo
                                     : (t == 2) ? Bhi : Blo;
            const int r0 = (t < 2) ? m0 : n0;
            #pragma unroll
            for (int p = 0; p < 2; ++p) {
                int idx = tid + p * 256;
                int r = idx >> 2;
                int c = (idx & 3) << 3;
                uint32_t off = (uint32_t)(r * 64 + c * 2);
                cp16(sbase + t * GS_TILE + SMEM_SWIZZLE_64B(off),
                     src + (size_t)(r0 + r) * K + k0 + c);
            }
        }
    };

    load_stage(0, 0);
    CP_COMMIT();

    for (int it = 0; it < nStages; ++it) {
        CP_WAIT(0);
        __syncthreads();           // stage it ready; all warps done reading stage it-1
        if (it + 1 < nStages) {
            load_stage((it + 1) & 1, (it + 1) << 5);
            CP_COMMIT();
        }

        const uint32_t stage = sb + (it & 1) * GS_STAGE;
        #pragma unroll
        for (int ks = 0; ks < 2; ++ks) {
            const int kk = ks << 4;
            uint32_t ah[4][4], al[4][4];
            #pragma unroll
            for (int mi = 0; mi < 4; ++mi) {
                int rg = wm * 64 + mi * 16 + a_row;
                uint32_t off = (uint32_t)(rg * 64 + (kk + a_koff) * 2);
                off = SMEM_SWIZZLE_64B(off);
                ldsm_x4(ah[mi], stage + off);
                ldsm_x4(al[mi], stage + GS_TILE + off);
            }
            #pragma unroll
            for (int g = 0; g < 2; ++g) {
                int rg = wn * 32 + g * 16 + b_row;
                uint32_t off = (uint32_t)(rg * 64 + (kk + b_koff) * 2);
                off = SMEM_SWIZZLE_64B(off);
                uint32_t bh[4];
                ldsm_x4(bh, stage + 2 * GS_TILE + off);
                #pragma unroll
                for (int mi = 0; mi < 4; ++mi) {
                    mma_bf16(acc[mi][2 * g],     ah[mi], bh[0], bh[1]);
                    mma_bf16(acc[mi][2 * g + 1], ah[mi], bh[2], bh[3]);
                    mma_bf16(acc[mi][2 * g],     al[mi], bh[0], bh[1]);
                    mma_bf16(acc[mi][2 * g + 1], al[mi], bh[2], bh[3]);
                }
                uint32_t bl[4];
                ldsm_x4(bl, stage + 3 * GS_TILE + off);
                #pragma unroll
                for (int mi = 0; mi < 4; ++mi) {
                    mma_bf16(acc[mi][2 * g],     ah[mi], bl[0], bl[1]);
                    mma_bf16(acc[mi][2 * g + 1], ah[mi], bl[2], bl[3]);
                }
            }
        }
    }

    const int cg = lid >> 2, ct = lid & 3;
    #pragma unroll
    for (int mi = 0; mi < 4; ++mi) {
        #pragma unroll
        for (int ni = 0; ni < 4; ++ni) {
            int row = m0 + wm * 64 + mi * 16 + cg;
            int col = n0 + wn * 32 + ni * 8 + 2 * ct;
            float2 bv = *reinterpret_cast<const float2*>(&bias[col]);
            float v00 = acc[mi][ni][0] + bv.x, v01 = acc[mi][ni][1] + bv.y;
            float v10 = acc[mi][ni][2] + bv.x, v11 = acc[mi][ni][3] + bv.y;
            if (MODE == 0) {
                float2 o0 = {v00, v01}, o1 = {v10, v11};
                *reinterpret_cast<float2*>(&C[(size_t)row * N + col]) = o0;
                *reinterpret_cast<float2*>(&C[(size_t)(row + 8) * N + col]) = o1;
            } else {
                uint32_t h, l;
                split2(v00, v01, h, l);
                *reinterpret_cast<uint32_t*>(&Chi[(size_t)row * N + col]) = h;
                *reinterpret_cast<uint32_t*>(&Clo[(size_t)row * N + col]) = l;
                split2(v10, v11, h, l);
                *reinterpret_cast<uint32_t*>(&Chi[(size_t)(row + 8) * N + col]) = h;
                *reinterpret_cast<uint32_t*>(&Clo[(size_t)(row + 8) * N + col]) = l;
            }
        }
    }
}

// ---------------------------------------------------------------------------
// Tensor-core flash attention (split-bf16, HMMA), cp.async 2-stage KV,
// 1 barrier/iter, heavy q-tiles scheduled first.
// ---------------------------------------------------------------------------
#define FTS_QHI   0
#define FTS_QLO   16384
#define FKV_BASE  32768
#define FKV_STAGE 32768
#define FLASH_SMEM_TC (FKV_BASE + 2 * FKV_STAGE)   // 98304

__global__ __launch_bounds__(256, 2) void flash_tc(
    const __nv_bfloat16* __restrict__ qkvhi, const __nv_bfloat16* __restrict__ qkvlo,
    __nv_bfloat16* __restrict__ ctxhi, __nv_bfloat16* __restrict__ ctxlo)
{
    extern __shared__ char smem[];
    const uint32_t sb = smem_to_u32(smem);
    const int tid = threadIdx.x;
    const int wid = tid >> 5, lid = tid & 31;
    const int bh = blockIdx.x;                      // 0..31
    const int qt = (gridDim.y - 1) - blockIdx.y;    // heavy tiles first
    const int b = bh >> 4, h = bh & 15;
    const int q0 = qt * 128;
    const float LOG2E = 1.4426950408889634f;

    auto load_kv = [&](int buf, int k0) {
        uint32_t sbase = sb + FKV_BASE + buf * FKV_STAGE;
        #pragma unroll
        for (int t = 0; t < 4; ++t) {
            const __nv_bfloat16* src = (t & 1) ? qkvlo : qkvhi;
            const int coloff = (t < 2) ? DM : 2 * DM;
            #pragma unroll
            for (int p = 0; p < 2; ++p) {
                int idx = tid + p * 256;
                int r = idx >> 3;
                int c = (idx & 7) << 3;
                uint32_t off = (uint32_t)(r * 128 + c * 2);
                cp16(sbase + t * 8192 + SMEM_SWIZZLE_128B(off),
                     src + (size_t)(b * S_LEN + k0 + r) * (3 * DM) + coloff + h * HDIM + c);
            }
        }
    };

    // Q tiles (hi/lo) into smem, swizzled
    #pragma unroll
    for (int t = 0; t < 2; ++t) {
        const __nv_bfloat16* src = t ? qkvlo : qkvhi;
        char* base = smem + (t ? FTS_QLO : FTS_QHI);
        #pragma unroll
        for (int p = 0; p < 4; ++p) {
            int idx = tid + p * 256;
            int r = idx >> 3;
            int c = (idx & 7) << 3;
            uint4 v = *reinterpret_cast<const uint4*>(
                src + (size_t)(b * S_LEN + q0 + r) * (3 * DM) + h * HDIM + c);
            uint32_t off = (uint32_t)(r * 128 + c * 2);
            *reinterpret_cast<uint4*>(base + SMEM_SWIZZLE_128B(off)) = v;
        }
    }
    load_kv(0, 0);
    CP_COMMIT();
    __syncthreads();

    // Q fragments (registers for the whole kernel)
    const int a_row  = (lid & 7) + ((lid >> 3) & 1) * 8;
    const int a_koff = (lid >> 4) << 3;
    const int b_row  = ((lid >> 4) << 3) + (lid & 7);
    const int b_koff = ((lid >> 3) & 1) << 3;
    uint32_t qh[4][4], ql[4][4];
    #pragma unroll
    for (int kk = 0; kk < 4; ++kk) {
        int rg = wid * 16 + a_row;
        uint32_t sw = (uint32_t)(rg * 128 + (kk * 16 + a_koff) * 2)
                      ^ ((uint32_t)(rg & 7) << 4);
        ldsm_x4(qh[kk], sb + FTS_QHI + sw);
        ldsm_x4(ql[kk], sb + FTS_QLO + sw);
    }

    float o[8][4];
    #pragma unroll
    for (int j = 0; j < 8; ++j)
        #pragma unroll
        for (int r = 0; r < 4; ++r) o[j][r] = 0.0f;
    float mrow[2] = {-INFINITY, -INFINITY};
    float lrow[2] = {0.0f, 0.0f};

    const int g8 = lid >> 2, t2 = (lid & 3) * 2;
    const int nkt = 2 * qt + 2;

    for (int kt = 0; kt < nkt; ++kt) {
        const int k0 = kt * 64;
        CP_WAIT(0);
        __syncthreads();           // stage kt ready; all warps done with kt-1
        if (kt + 1 < nkt) {
            load_kv((kt + 1) & 1, (kt + 1) * 64);
            CP_COMMIT();
        }

        const uint32_t kvs = sb + FKV_BASE + (kt & 1) * FKV_STAGE;

        if (q0 + wid * 16 + 15 >= k0) {
            float s[8][4];
            #pragma unroll
            for (int j = 0; j < 8; ++j)
                #pragma unroll
                for (int r = 0; r < 4; ++r) s[j][r] = 0.0f;

            #pragma unroll
            for (int g = 0; g < 4; ++g) {
                #pragma unroll
                for (int kk = 0; kk < 4; ++kk) {
                    int rg = g * 16 + b_row;
                    uint32_t sw = (uint32_t)(rg * 128 + (kk * 16 + b_koff) * 2)
                                  ^ ((uint32_t)(rg & 7) << 4);
                    uint32_t kh[4];
                    ldsm_x4(kh, kvs + sw);
                    mma_bf16(s[2 * g],     qh[kk], kh[0], kh[1]);
                    mma_bf16(s[2 * g + 1], qh[kk], kh[2], kh[3]);
                    mma_bf16(s[2 * g],     ql[kk], kh[0], kh[1]);
                    mma_bf16(s[2 * g + 1], ql[kk], kh[2], kh[3]);
                    uint32_t kl[4];
                    ldsm_x4(kl, kvs + 8192 + sw);
                    mma_bf16(s[2 * g],     qh[kk], kl[0], kl[1]);
                    mma_bf16(s[2 * g + 1], qh[kk], kl[2], kl[3]);
                }
            }

            const bool diag = (k0 + 63 > q0 + wid * 16);
            #pragma unroll
            for (int j = 0; j < 8; ++j) {
                #pragma unroll
                for (int r2 = 0; r2 < 2; ++r2) {
                    int qrow = q0 + wid * 16 + g8 + 8 * r2;
                    #pragma unroll
                    for (int e = 0; e < 2; ++e) {
                        float v = s[j][2 * r2 + e] * 0.125f;
                        if (diag && (k0 + j * 8 + t2 + e > qrow)) v = -1e30f;
                        s[j][2 * r2 + e] = v;
                    }
                }
            }

            #pragma unroll
            for (int r2 = 0; r2 < 2; ++r2) {
                float mx = -INFINITY;
                #pragma unroll
                for (int j = 0; j < 8; ++j)
                    mx = fmaxf(mx, fmaxf(s[j][2 * r2], s[j][2 * r2 + 1]));
                mx = fmaxf(mx, __shfl_xor_sync(0xffffffffu, mx, 1));
                mx = fmaxf(mx, __shfl_xor_sync(0xffffffffu, mx, 2));
                float mnew = fmaxf(mrow[r2], mx);
                float alpha = fast_exp2((mrow[r2] - mnew) * LOG2E);
                mrow[r2] = mnew;
                float ls = 0.0f;
                #pragma unroll
                for (int j = 0; j < 8; ++j) {
                    float p0 = fast_exp2((s[j][2 * r2] - mnew) * LOG2E);
                    float p1 = fast_exp2((s[j][2 * r2 + 1] - mnew) * LOG2E);
                    s[j][2 * r2] = p0;
                    s[j][2 * r2 + 1] = p1;
                    ls += p0 + p1;
                }
                ls += __shfl_xor_sync(0xffffffffu, ls, 1);
                ls += __shfl_xor_sync(0xffffffffu, ls, 2);
                lrow[r2] = lrow[r2] * alpha + ls;
                #pragma unroll
                for (int j = 0; j < 8; ++j) {
                    o[j][2 * r2] *= alpha;
                    o[j][2 * r2 + 1] *= alpha;
                }
            }

            #pragma unroll
            for (int kk = 0; kk < 4; ++kk) {
                uint32_t ph[4], pl[4];
                split2(s[2 * kk][0],     s[2 * kk][1],     ph[0], pl[0]);
                split2(s[2 * kk][2],     s[2 * kk][3],     ph[1], pl[1]);
                split2(s[2 * kk + 1][0], s[2 * kk + 1][1], ph[2], pl[2]);
                split2(s[2 * kk + 1][2], s[2 * kk + 1][3], ph[3], pl[3]);
                int vrow = kk * 16 + (lid & 7) + ((lid >> 3) & 1) * 8;
                #pragma unroll
                for (int j2 = 0; j2 < 4; ++j2) {
                    uint32_t sw = (uint32_t)(vrow * 128 + j2 * 32 + ((lid >> 4) & 1) * 16)
                                  ^ ((uint32_t)(vrow & 7) << 4);
                    uint32_t vh[4];
                    ldsm_x4_t(vh, kvs + 16384 + sw);
                    mma_bf16(o[2 * j2],     ph, vh[0], vh[1]);
                    mma_bf16(o[2 * j2 + 1], ph, vh[2], vh[3]);
                    mma_bf16(o[2 * j2],     pl, vh[0], vh[1]);
                    mma_bf16(o[2 * j2 + 1], pl, vh[2], vh[3]);
                    uint32_t vl[4];
                    ldsm_x4_t(vl, kvs + 24576 + sw);
                    mma_bf16(o[2 * j2],     ph, vl[0], vl[1]);
                    mma_bf16(o[2 * j2 + 1], ph, vl[2], vl[3]);
                }
            }
        }
    }

    float inv0 = 1.0f / lrow[0], inv1 = 1.0f / lrow[1];
    size_t row0 = (size_t)(b * S_LEN + q0 + wid * 16 + g8);
    #pragma unroll
    for (int j = 0; j < 8; ++j) {
        int c = h * HDIM + j * 8 + t2;
        uint32_t hi0, lo0, hi1, lo1;
        split2(o[j][0] * inv0, o[j][1] * inv0, hi0, lo0);
        split2(o[j][2] * inv1, o[j][3] * inv1, hi1, lo1);
        *reinterpret_cast<uint32_t*>(&ctxhi[row0 * DM + c]) = hi0;
        *reinterpret_cast<uint32_t*>(&ctxlo[row0 * DM + c]) = lo0;
        *reinterpret_cast<uint32_t*>(&ctxhi[(row0 + 8) * DM + c]) = hi1;
        *reinterpret_cast<uint32_t*>(&ctxlo[(row0 + 8) * DM + c]) = lo1;
    }
}

// ---------------------------------------------------------------------------
extern "C" void kernel_launch(void* const* d_in, const int* in_sizes, int n_in,
                              void* d_out, int out_size)
{
    const float* x    = (const float*)d_in[0];
    const float* Wqkv = (const float*)d_in[1];
    const float* bqkv = (const float*)d_in[2];
    const float* Wout = (const float*)d_in[3];
    const float* bout = (const float*)d_in[4];
    float* out = (float*)d_out;

    __nv_bfloat16 *qkvhi, *qkvlo, *xhi, *xlo, *ctxhi, *ctxlo;
    __nv_bfloat16 *wqhi, *wqlo, *wohi, *wolo;
    cudaGetSymbolAddress((void**)&qkvhi, g_qkvhi);
    cudaGetSymbolAddress((void**)&qkvlo, g_qkvlo);
    cudaGetSymbolAddress((void**)&xhi, g_xhi);
    cudaGetSymbolAddress((void**)&xlo, g_xlo);
    cudaGetSymbolAddress((void**)&ctxhi, g_ctxhi);
    cudaGetSymbolAddress((void**)&ctxlo, g_ctxlo);
    cudaGetSymbolAddress((void**)&wqhi, g_wqkvThi);
    cudaGetSymbolAddress((void**)&wqlo, g_wqkvTlo);
    cudaGetSymbolAddress((void**)&wohi, g_woutThi);
    cudaGetSymbolAddress((void**)&wolo, g_woutTlo);

    cudaFuncSetAttribute(gemm_mma<0>, cudaFuncAttributeMaxDynamicSharedMemorySize, GEMM_SMEM);
    cudaFuncSetAttribute(gemm_mma<1>, cudaFuncAttributeMaxDynamicSharedMemorySize, GEMM_SMEM);
    cudaFuncSetAttribute(flash_tc, cudaFuncAttributeMaxDynamicSharedMemorySize, FLASH_SMEM_TC);

    // 0) Split inputs / weights to bf16 hi/lo
    int nx4 = MROWS * DM / 4;
    split_f32<<<(nx4 + 255) / 256, 256>>>(x, xhi, xlo, nx4);
    splitT_f32<<<dim3(3 * DM / 32, DM / 32), 256>>>(Wqkv, wqhi, wqlo, DM, 3 * DM);
    splitT_f32<<<dim3(DM / 32, DM / 32), 256>>>(Wout, wohi, wolo, DM, DM);

    // 1) QKV projection -> split bf16 qkv directly
    gemm_mma<1><<<dim3(3 * DM / 128, MROWS / 128), 256, GEMM_SMEM>>>(
        xhi, xlo, wqhi, wqlo, bqkv, nullptr, qkvhi, qkvlo, MROWS, 3 * DM, DM);

    // 2) Tensor-core causal flash attention -> split bf16 ctx directly
    //    grid: x = batch*heads, y = q-tiles (reversed inside kernel)
    flash_tc<<<dim3(BATCH * NHEADS, S_LEN / 128), 256, FLASH_SMEM_TC>>>(
        qkvhi, qkvlo, ctxhi, ctxlo);

    // 3) Output projection -> f32 out
    gemm_mma<0><<<dim3(DM / 128, MROWS / 128), 256, GEMM_SMEM>>>(
        ctxhi, ctxlo, wohi, wolo, bout, out, nullptr, nullptr, MROWS, DM, DM);
}

// round 8
// speedup vs baseline: 3.3867x; 1.0261x over previous
#include <cuda_runtime.h>
#include <cuda_bf16.h>
#include <cstdint>
#include <math.h>

#define S_LEN   2048
#define DM      1024
#define NHEADS  16
#define HDIM    64
#define BATCH   2
#define MROWS   (BATCH * S_LEN)   // 4096

// ---------------------------------------------------------------------------
// Scratch (device globals; no runtime allocation allowed)
// ---------------------------------------------------------------------------
__device__ __align__(256) __nv_bfloat16 g_qkvhi[MROWS * 3 * DM];
__device__ __align__(256) __nv_bfloat16 g_qkvlo[MROWS * 3 * DM];
__device__ __align__(256) __nv_bfloat16 g_xhi[MROWS * DM];
__device__ __align__(256) __nv_bfloat16 g_xlo[MROWS * DM];
__device__ __align__(256) __nv_bfloat16 g_ctxhi[MROWS * DM];
__device__ __align__(256) __nv_bfloat16 g_ctxlo[MROWS * DM];
__device__ __align__(256) __nv_bfloat16 g_wqkvThi[3 * DM * DM];
__device__ __align__(256) __nv_bfloat16 g_wqkvTlo[3 * DM * DM];
__device__ __align__(256) __nv_bfloat16 g_woutThi[DM * DM];
__device__ __align__(256) __nv_bfloat16 g_woutTlo[DM * DM];

// ---------------------------------------------------------------------------
// Helpers
// ---------------------------------------------------------------------------
__device__ __forceinline__ uint32_t smem_to_u32(const void* p) {
    uint32_t a;
    asm("{ .reg .u64 t; cvta.to.shared.u64 t, %1; cvt.u32.u64 %0, t; }" : "=r"(a) : "l"(p));
    return a;
}
#define SMEM_SWIZZLE_128B(off) ((off) ^ (((off) >> 3) & 0x70))
#define SMEM_SWIZZLE_64B(off)  ((off) ^ (((off) >> 3) & 0x30))

__device__ __forceinline__ void cp16(uint32_t dst, const void* src) {
    asm volatile("cp.async.cg.shared.global [%0], [%1], 16;" :: "r"(dst), "l"(src));
}
#define CP_COMMIT()    asm volatile("cp.async.commit_group;" ::: "memory")
#define CP_WAIT(n)     asm volatile("cp.async.wait_group %0;" :: "n"(n) : "memory")

__device__ __forceinline__ void ldsm_x4(uint32_t (&r)[4], uint32_t addr) {
    asm volatile("ldmatrix.sync.aligned.m8n8.x4.shared.b16 {%0,%1,%2,%3}, [%4];"
        : "=r"(r[0]), "=r"(r[1]), "=r"(r[2]), "=r"(r[3]) : "r"(addr));
}
__device__ __forceinline__ void ldsm_x4_t(uint32_t (&r)[4], uint32_t addr) {
    asm volatile("ldmatrix.sync.aligned.m8n8.x4.trans.shared.b16 {%0,%1,%2,%3}, [%4];"
        : "=r"(r[0]), "=r"(r[1]), "=r"(r[2]), "=r"(r[3]) : "r"(addr));
}
__device__ __forceinline__ void mma_bf16(float (&c)[4], const uint32_t (&a)[4],
                                         uint32_t b0, uint32_t b1) {
    asm volatile("mma.sync.aligned.m16n8k16.row.col.f32.bf16.bf16.f32 "
        "{%0,%1,%2,%3}, {%4,%5,%6,%7}, {%8,%9}, {%0,%1,%2,%3};"
        : "+f"(c[0]), "+f"(c[1]), "+f"(c[2]), "+f"(c[3])
        : "r"(a[0]), "r"(a[1]), "r"(a[2]), "r"(a[3]), "r"(b0), "r"(b1));
}
__device__ __forceinline__ float fast_exp2(float x) {
    float y;
    asm("ex2.approx.ftz.f32 %0, %1;" : "=f"(y) : "f"(x));
    return y;
}
__device__ __forceinline__ void split2(float v0, float v1, uint32_t& hi, uint32_t& lo) {
    __nv_bfloat16 h0 = __float2bfloat16(v0), h1 = __float2bfloat16(v1);
    __nv_bfloat16 l0 = __float2bfloat16(v0 - __bfloat162float(h0));
    __nv_bfloat16 l1 = __float2bfloat16(v1 - __bfloat162float(h1));
    __nv_bfloat162 hp = __halves2bfloat162(h0, h1);
    __nv_bfloat162 lp = __halves2bfloat162(l0, l1);
    hi = *reinterpret_cast<uint32_t*>(&hp);
    lo = *reinterpret_cast<uint32_t*>(&lp);
}

// ---------------------------------------------------------------------------
// Split kernels
// ---------------------------------------------------------------------------
__global__ __launch_bounds__(256) void split_f32(
    const float* __restrict__ src, __nv_bfloat16* __restrict__ hi,
    __nv_bfloat16* __restrict__ lo, int n4)
{
    int i = blockIdx.x * 256 + threadIdx.x;
    if (i >= n4) return;
    float4 v = reinterpret_cast<const float4*>(src)[i];
    __nv_bfloat16 h[4], l[4];
    float vv[4] = {v.x, v.y, v.z, v.w};
    #pragma unroll
    for (int j = 0; j < 4; j++) {
        h[j] = __float2bfloat16(vv[j]);
        l[j] = __float2bfloat16(vv[j] - __bfloat162float(h[j]));
    }
    reinterpret_cast<uint2*>(hi)[i] = *reinterpret_cast<uint2*>(h);
    reinterpret_cast<uint2*>(lo)[i] = *reinterpret_cast<uint2*>(l);
}

__global__ __launch_bounds__(256) void splitT_f32(
    const float* __restrict__ W, __nv_bfloat16* __restrict__ hiT,
    __nv_bfloat16* __restrict__ loT, int K, int N)
{
    __shared__ float t[32][33];
    const int kb = blockIdx.y * 32, nb = blockIdx.x * 32;
    const int tx = threadIdx.x & 31, ty0 = threadIdx.x >> 5;
    #pragma unroll
    for (int r = ty0; r < 32; r += 8)
        t[r][tx] = W[(size_t)(kb + r) * N + nb + tx];
    __syncthreads();
    #pragma unroll
    for (int r = ty0; r < 32; r += 8) {
        float v = t[tx][r];
        __nv_bfloat16 h = __float2bfloat16(v);
        __nv_bfloat16 l = __float2bfloat16(v - __bfloat162float(h));
        size_t o = (size_t)(nb + r) * K + kb + tx;
        hiT[o] = h;
        loT[o] = l;
    }
}

// ---------------------------------------------------------------------------
// mma.sync bf16 split-GEMM + bias. Pass-ordered MMA issue (RAW distance 16).
// CTA 128x128, BK=32 stages x2, 8 warps of 64x32, HMMA m16n8k16.
// ---------------------------------------------------------------------------
#define GS_TILE   8192
#define GS_STAGE  (4 * GS_TILE)              // 32768
#define GEMM_SMEM (2 * GS_STAGE)             // 65536

template<int MODE>
__global__ __launch_bounds__(256, 2) void gemm_mma(
    const __nv_bfloat16* __restrict__ Ahi, const __nv_bfloat16* __restrict__ Alo,
    const __nv_bfloat16* __restrict__ Bhi, const __nv_bfloat16* __restrict__ Blo,
    const float* __restrict__ bias, float* __restrict__ C,
    __nv_bfloat16* __restrict__ Chi, __nv_bfloat16* __restrict__ Clo,
    int M, int N, int K)
{
    extern __shared__ char smem[];
    const uint32_t sb = smem_to_u32(smem);
    const int tid = threadIdx.x;
    const int wid = tid >> 5, lid = tid & 31;
    const int wm = wid & 1;
    const int wn = wid >> 1;
    const int m0 = blockIdx.y * 128, n0 = blockIdx.x * 128;

    float acc[4][4][4];
    #pragma unroll
    for (int i = 0; i < 4; i++)
        #pragma unroll
        for (int j = 0; j < 4; j++)
            #pragma unroll
            for (int r = 0; r < 4; r++) acc[i][j][r] = 0.0f;

    const int a_row  = (lid & 7) + ((lid >> 3) & 1) * 8;
    const int a_koff = (lid >> 4) << 3;
    const int b_row  = ((lid >> 4) << 3) + (lid & 7);
    const int b_koff = ((lid >> 3) & 1) << 3;

    const int nStages = K >> 5;

    auto load_stage = [&](int buf, int k0) {
        uint32_t sbase = sb + buf * GS_STAGE;
        #pragma unroll
        for (int t = 0; t < 4; ++t) {
            const __nv_bfloat16* src = (t == 0) ? Ahi : (t == 1) ? Alo
                                     : (t == 2) ? Bhi : Blo;
            const int r0 = (t < 2) ? m0 : n0;
            #pragma unroll
            for (int p = 0; p < 2; ++p) {
                int idx = tid + p * 256;
                int r = idx >> 2;
                int c = (idx & 3) << 3;
                uint32_t off = (uint32_t)(r * 64 + c * 2);
                cp16(sbase + t * GS_TILE + SMEM_SWIZZLE_64B(off),
                     src + (size_t)(r0 + r) * K + k0 + c);
            }
        }
    };

    load_stage(0, 0);
    CP_COMMIT();

    for (int it = 0; it < nStages; ++it) {
        CP_WAIT(0);
        __syncthreads();
        if (it + 1 < nStages) {
            load_stage((it + 1) & 1, (it + 1) << 5);
            CP_COMMIT();
        }

        const uint32_t stage = sb + (it & 1) * GS_STAGE;
        #pragma unroll
        for (int ks = 0; ks < 2; ++ks) {
            const int kk = ks << 4;
            uint32_t ah[4][4], al[4][4], bb[2][4];
            #pragma unroll
            for (int mi = 0; mi < 4; ++mi) {
                int rg = wm * 64 + mi * 16 + a_row;
                uint32_t off = (uint32_t)(rg * 64 + (kk + a_koff) * 2);
                off = SMEM_SWIZZLE_64B(off);
                ldsm_x4(ah[mi], stage + off);
                ldsm_x4(al[mi], stage + GS_TILE + off);
            }
            uint32_t boff[2];
            #pragma unroll
            for (int g = 0; g < 2; ++g) {
                int rg = wn * 32 + g * 16 + b_row;
                uint32_t off = (uint32_t)(rg * 64 + (kk + b_koff) * 2);
                boff[g] = SMEM_SWIZZLE_64B(off);
                ldsm_x4(bb[g], stage + 2 * GS_TILE + boff[g]);
            }
            // pass 1: ah @ bh  (each acc written once; distance 16)
            #pragma unroll
            for (int mi = 0; mi < 4; ++mi)
                #pragma unroll
                for (int g = 0; g < 2; ++g) {
                    mma_bf16(acc[mi][2 * g],     ah[mi], bb[g][0], bb[g][1]);
                    mma_bf16(acc[mi][2 * g + 1], ah[mi], bb[g][2], bb[g][3]);
                }
            // pass 2: al @ bh
            #pragma unroll
            for (int mi = 0; mi < 4; ++mi)
                #pragma unroll
                for (int g = 0; g < 2; ++g) {
                    mma_bf16(acc[mi][2 * g],     al[mi], bb[g][0], bb[g][1]);
                    mma_bf16(acc[mi][2 * g + 1], al[mi], bb[g][2], bb[g][3]);
                }
            // load bl (reuse bb), pass 3: ah @ bl
            #pragma unroll
            for (int g = 0; g < 2; ++g)
                ldsm_x4(bb[g], stage + 3 * GS_TILE + boff[g]);
            #pragma unroll
            for (int mi = 0; mi < 4; ++mi)
                #pragma unroll
                for (int g = 0; g < 2; ++g) {
                    mma_bf16(acc[mi][2 * g],     ah[mi], bb[g][0], bb[g][1]);
                    mma_bf16(acc[mi][2 * g + 1], ah[mi], bb[g][2], bb[g][3]);
                }
        }
    }

    const int cg = lid >> 2, ct = lid & 3;
    #pragma unroll
    for (int mi = 0; mi < 4; ++mi) {
        #pragma unroll
        for (int ni = 0; ni < 4; ++ni) {
            int row = m0 + wm * 64 + mi * 16 + cg;
            int col = n0 + wn * 32 + ni * 8 + 2 * ct;
            float2 bv = *reinterpret_cast<const float2*>(&bias[col]);
            float v00 = acc[mi][ni][0] + bv.x, v01 = acc[mi][ni][1] + bv.y;
            float v10 = acc[mi][ni][2] + bv.x, v11 = acc[mi][ni][3] + bv.y;
            if (MODE == 0) {
                float2 o0 = {v00, v01}, o1 = {v10, v11};
                *reinterpret_cast<float2*>(&C[(size_t)row * N + col]) = o0;
                *reinterpret_cast<float2*>(&C[(size_t)(row + 8) * N + col]) = o1;
            } else {
                uint32_t h, l;
                split2(v00, v01, h, l);
                *reinterpret_cast<uint32_t*>(&Chi[(size_t)row * N + col]) = h;
                *reinterpret_cast<uint32_t*>(&Clo[(size_t)row * N + col]) = l;
                split2(v10, v11, h, l);
                *reinterpret_cast<uint32_t*>(&Chi[(size_t)(row + 8) * N + col]) = h;
                *reinterpret_cast<uint32_t*>(&Clo[(size_t)(row + 8) * N + col]) = l;
            }
        }
    }
}

// ---------------------------------------------------------------------------
// Tensor-core flash attention (split-bf16, HMMA), pass-ordered MMA issue.
// ---------------------------------------------------------------------------
#define FTS_QHI   0
#define FTS_QLO   16384
#define FKV_BASE  32768
#define FKV_STAGE 32768
#define FLASH_SMEM_TC (FKV_BASE + 2 * FKV_STAGE)   // 98304

__global__ __launch_bounds__(256, 2) void flash_tc(
    const __nv_bfloat16* __restrict__ qkvhi, const __nv_bfloat16* __restrict__ qkvlo,
    __nv_bfloat16* __restrict__ ctxhi, __nv_bfloat16* __restrict__ ctxlo)
{
    extern __shared__ char smem[];
    const uint32_t sb = smem_to_u32(smem);
    const int tid = threadIdx.x;
    const int wid = tid >> 5, lid = tid & 31;
    const int bh = blockIdx.x;
    const int qt = (gridDim.y - 1) - blockIdx.y;    // heavy tiles first
    const int b = bh >> 4, h = bh & 15;
    const int q0 = qt * 128;
    const float LOG2E = 1.4426950408889634f;

    auto load_kv = [&](int buf, int k0) {
        uint32_t sbase = sb + FKV_BASE + buf * FKV_STAGE;
        #pragma unroll
        for (int t = 0; t < 4; ++t) {
            const __nv_bfloat16* src = (t & 1) ? qkvlo : qkvhi;
            const int coloff = (t < 2) ? DM : 2 * DM;
            #pragma unroll
            for (int p = 0; p < 2; ++p) {
                int idx = tid + p * 256;
                int r = idx >> 3;
                int c = (idx & 7) << 3;
                uint32_t off = (uint32_t)(r * 128 + c * 2);
                cp16(sbase + t * 8192 + SMEM_SWIZZLE_128B(off),
                     src + (size_t)(b * S_LEN + k0 + r) * (3 * DM) + coloff + h * HDIM + c);
            }
        }
    };

    #pragma unroll
    for (int t = 0; t < 2; ++t) {
        const __nv_bfloat16* src = t ? qkvlo : qkvhi;
        char* base = smem + (t ? FTS_QLO : FTS_QHI);
        #pragma unroll
        for (int p = 0; p < 4; ++p) {
            int idx = tid + p * 256;
            int r = idx >> 3;
            int c = (idx & 7) << 3;
            uint4 v = *reinterpret_cast<const uint4*>(
                src + (size_t)(b * S_LEN + q0 + r) * (3 * DM) + h * HDIM + c);
            uint32_t off = (uint32_t)(r * 128 + c * 2);
            *reinterpret_cast<uint4*>(base + SMEM_SWIZZLE_128B(off)) = v;
        }
    }
    load_kv(0, 0);
    CP_COMMIT();
    __syncthreads();

    const int a_row  = (lid & 7) + ((lid >> 3) & 1) * 8;
    const int a_koff = (lid >> 4) << 3;
    const int b_row  = ((lid >> 4) << 3) + (lid & 7);
    const int b_koff = ((lid >> 3) & 1) << 3;
    uint32_t qh[4][4], ql[4][4];
    #pragma unroll
    for (int kk = 0; kk < 4; ++kk) {
        int rg = wid * 16 + a_row;
        uint32_t sw = (uint32_t)(rg * 128 + (kk * 16 + a_koff) * 2)
                      ^ ((uint32_t)(rg & 7) << 4);
        ldsm_x4(qh[kk], sb + FTS_QHI + sw);
        ldsm_x4(ql[kk], sb + FTS_QLO + sw);
    }

    float o[8][4];
    #pragma unroll
    for (int j = 0; j < 8; ++j)
        #pragma unroll
        for (int r = 0; r < 4; ++r) o[j][r] = 0.0f;
    float mrow[2] = {-INFINITY, -INFINITY};
    float lrow[2] = {0.0f, 0.0f};

    const int g8 = lid >> 2, t2 = (lid & 3) * 2;
    const int nkt = 2 * qt + 2;

    for (int kt = 0; kt < nkt; ++kt) {
        const int k0 = kt * 64;
        CP_WAIT(0);
        __syncthreads();
        if (kt + 1 < nkt) {
            load_kv((kt + 1) & 1, (kt + 1) * 64);
            CP_COMMIT();
        }

        const uint32_t kvs = sb + FKV_BASE + (kt & 1) * FKV_STAGE;

        if (q0 + wid * 16 + 15 >= k0) {
            float s[8][4];
            #pragma unroll
            for (int j = 0; j < 8; ++j)
                #pragma unroll
                for (int r = 0; r < 4; ++r) s[j][r] = 0.0f;

            // S = Q@K^T : per kk, pass-ordered (distance 8)
            #pragma unroll
            for (int kk = 0; kk < 4; ++kk) {
                uint32_t kb[4][4];
                uint32_t koff[4];
                #pragma unroll
                for (int g = 0; g < 4; ++g) {
                    int rg = g * 16 + b_row;
                    koff[g] = (uint32_t)(rg * 128 + (kk * 16 + b_koff) * 2)
                              ^ ((uint32_t)(rg & 7) << 4);
                    ldsm_x4(kb[g], kvs + koff[g]);
                }
                #pragma unroll
                for (int g = 0; g < 4; ++g) {
                    mma_bf16(s[2 * g],     qh[kk], kb[g][0], kb[g][1]);
                    mma_bf16(s[2 * g + 1], qh[kk], kb[g][2], kb[g][3]);
                }
                #pragma unroll
                for (int g = 0; g < 4; ++g) {
                    mma_bf16(s[2 * g],     ql[kk], kb[g][0], kb[g][1]);
                    mma_bf16(s[2 * g + 1], ql[kk], kb[g][2], kb[g][3]);
                }
                #pragma unroll
                for (int g = 0; g < 4; ++g)
                    ldsm_x4(kb[g], kvs + 8192 + koff[g]);
                #pragma unroll
                for (int g = 0; g < 4; ++g) {
                    mma_bf16(s[2 * g],     qh[kk], kb[g][0], kb[g][1]);
                    mma_bf16(s[2 * g + 1], qh[kk], kb[g][2], kb[g][3]);
                }
            }

            const bool diag = (k0 + 63 > q0 + wid * 16);
            #pragma unroll
            for (int j = 0; j < 8; ++j) {
                #pragma unroll
                for (int r2 = 0; r2 < 2; ++r2) {
                    int qrow = q0 + wid * 16 + g8 + 8 * r2;
                    #pragma unroll
                    for (int e = 0; e < 2; ++e) {
                        float v = s[j][2 * r2 + e] * 0.125f;
                        if (diag && (k0 + j * 8 + t2 + e > qrow)) v = -1e30f;
                        s[j][2 * r2 + e] = v;
                    }
                }
            }

            #pragma unroll
            for (int r2 = 0; r2 < 2; ++r2) {
                float mx = -INFINITY;
                #pragma unroll
                for (int j = 0; j < 8; ++j)
                    mx = fmaxf(mx, fmaxf(s[j][2 * r2], s[j][2 * r2 + 1]));
                mx = fmaxf(mx, __shfl_xor_sync(0xffffffffu, mx, 1));
                mx = fmaxf(mx, __shfl_xor_sync(0xffffffffu, mx, 2));
                float mnew = fmaxf(mrow[r2], mx);
                float alpha = fast_exp2((mrow[r2] - mnew) * LOG2E);
                mrow[r2] = mnew;
                float ls = 0.0f;
                #pragma unroll
                for (int j = 0; j < 8; ++j) {
                    float p0 = fast_exp2((s[j][2 * r2] - mnew) * LOG2E);
                    float p1 = fast_exp2((s[j][2 * r2 + 1] - mnew) * LOG2E);
                    s[j][2 * r2] = p0;
                    s[j][2 * r2 + 1] = p1;
                    ls += p0 + p1;
                }
                ls += __shfl_xor_sync(0xffffffffu, ls, 1);
                ls += __shfl_xor_sync(0xffffffffu, ls, 2);
                lrow[r2] = lrow[r2] * alpha + ls;
                #pragma unroll
                for (int j = 0; j < 8; ++j) {
                    o[j][2 * r2] *= alpha;
                    o[j][2 * r2 + 1] *= alpha;
                }
            }

            // O += P@V : per kk, pass-ordered (distance 8)
            #pragma unroll
            for (int kk = 0; kk < 4; ++kk) {
                uint32_t ph[4], pl[4];
                split2(s[2 * kk][0],     s[2 * kk][1],     ph[0], pl[0]);
                split2(s[2 * kk][2],     s[2 * kk][3],     ph[1], pl[1]);
                split2(s[2 * kk + 1][0], s[2 * kk + 1][1], ph[2], pl[2]);
                split2(s[2 * kk + 1][2], s[2 * kk + 1][3], ph[3], pl[3]);
                int vrow = kk * 16 + (lid & 7) + ((lid >> 3) & 1) * 8;
                uint32_t vb[4][4];
                uint32_t voff[4];
                #pragma unroll
                for (int j2 = 0; j2 < 4; ++j2) {
                    voff[j2] = (uint32_t)(vrow * 128 + j2 * 32 + ((lid >> 4) & 1) * 16)
                               ^ ((uint32_t)(vrow & 7) << 4);
                    ldsm_x4_t(vb[j2], kvs + 16384 + voff[j2]);
                }
                #pragma unroll
                for (int j2 = 0; j2 < 4; ++j2) {
                    mma_bf16(o[2 * j2],     ph, vb[j2][0], vb[j2][1]);
                    mma_bf16(o[2 * j2 + 1], ph, vb[j2][2], vb[j2][3]);
                }
                #pragma unroll
                for (int j2 = 0; j2 < 4; ++j2) {
                    mma_bf16(o[2 * j2],     pl, vb[j2][0], vb[j2][1]);
                    mma_bf16(o[2 * j2 + 1], pl, vb[j2][2], vb[j2][3]);
                }
                #pragma unroll
                for (int j2 = 0; j2 < 4; ++j2)
                    ldsm_x4_t(vb[j2], kvs + 24576 + voff[j2]);
                #pragma unroll
                for (int j2 = 0; j2 < 4; ++j2) {
                    mma_bf16(o[2 * j2],     ph, vb[j2][0], vb[j2][1]);
                    mma_bf16(o[2 * j2 + 1], ph, vb[j2][2], vb[j2][3]);
                }
            }
        }
    }

    float inv0 = 1.0f / lrow[0], inv1 = 1.0f / lrow[1];
    size_t row0 = (size_t)(b * S_LEN + q0 + wid * 16 + g8);
    #pragma unroll
    for (int j = 0; j < 8; ++j) {
        int c = h * HDIM + j * 8 + t2;
        uint32_t hi0, lo0, hi1, lo1;
        split2(o[j][0] * inv0, o[j][1] * inv0, hi0, lo0);
        split2(o[j][2] * inv1, o[j][3] * inv1, hi1, lo1);
        *reinterpret_cast<uint32_t*>(&ctxhi[row0 * DM + c]) = hi0;
        *reinterpret_cast<uint32_t*>(&ctxlo[row0 * DM + c]) = lo0;
        *reinterpret_cast<uint32_t*>(&ctxhi[(row0 + 8) * DM + c]) = hi1;
        *reinterpret_cast<uint32_t*>(&ctxlo[(row0 + 8) * DM + c]) = lo1;
    }
}

// ---------------------------------------------------------------------------
extern "C" void kernel_launch(void* const* d_in, const int* in_sizes, int n_in,
                              void* d_out, int out_size)
{
    const float* x    = (const float*)d_in[0];
    const float* Wqkv = (const float*)d_in[1];
    const float* bqkv = (const float*)d_in[2];
    const float* Wout = (const float*)d_in[3];
    const float* bout = (const float*)d_in[4];
    float* out = (float*)d_out;

    __nv_bfloat16 *qkvhi, *qkvlo, *xhi, *xlo, *ctxhi, *ctxlo;
    __nv_bfloat16 *wqhi, *wqlo, *wohi, *wolo;
    cudaGetSymbolAddress((void**)&qkvhi, g_qkvhi);
    cudaGetSymbolAddress((void**)&qkvlo, g_qkvlo);
    cudaGetSymbolAddress((void**)&xhi, g_xhi);
    cudaGetSymbolAddress((void**)&xlo, g_xlo);
    cudaGetSymbolAddress((void**)&ctxhi, g_ctxhi);
    cudaGetSymbolAddress((void**)&ctxlo, g_ctxlo);
    cudaGetSymbolAddress((void**)&wqhi, g_wqkvThi);
    cudaGetSymbolAddress((void**)&wqlo, g_wqkvTlo);
    cudaGetSymbolAddress((void**)&wohi, g_woutThi);
    cudaGetSymbolAddress((void**)&wolo, g_woutTlo);

    cudaFuncSetAttribute(gemm_mma<0>, cudaFuncAttributeMaxDynamicSharedMemorySize, GEMM_SMEM);
    cudaFuncSetAttribute(gemm_mma<1>, cudaFuncAttributeMaxDynamicSharedMemorySize, GEMM_SMEM);
    cudaFuncSetAttribute(flash_tc, cudaFuncAttributeMaxDynamicSharedMemorySize, FLASH_SMEM_TC);

    int nx4 = MROWS * DM / 4;
    split_f32<<<(nx4 + 255) / 256, 256>>>(x, xhi, xlo, nx4);
    splitT_f32<<<dim3(3 * DM / 32, DM / 32), 256>>>(Wqkv, wqhi, wqlo, DM, 3 * DM);
    splitT_f32<<<dim3(DM / 32, DM / 32), 256>>>(Wout, wohi, wolo, DM, DM);

    gemm_mma<1><<<dim3(3 * DM / 128, MROWS / 128), 256, GEMM_SMEM>>>(
        xhi, xlo, wqhi, wqlo, bqkv, nullptr, qkvhi, qkvlo, MROWS, 3 * DM, DM);

    flash_tc<<<dim3(BATCH * NHEADS, S_LEN / 128), 256, FLASH_SMEM_TC>>>(
        qkvhi, qkvlo, ctxhi, ctxlo);

    gemm_mma<0><<<dim3(DM / 128, MROWS / 128), 256, GEMM_SMEM>>>(
        ctxhi, ctxlo, wohi, wolo, bout, out, nullptr, nullptr, MROWS, DM, DM);
}

// round 9
// speedup vs baseline: 4.5557x; 1.3452x over previous
#include <cuda_runtime.h>
#include <cuda_fp16.h>
#include <cstdint>
#include <math.h>

#define S_LEN   2048
#define DM      1024
#define NHEADS  16
#define HDIM    64
#define BATCH   2
#define MROWS   (BATCH * S_LEN)   // 4096

// ---------------------------------------------------------------------------
// Scratch (device globals; no runtime allocation allowed)
// ---------------------------------------------------------------------------
__device__ __align__(256) __half g_qkvhi[MROWS * 3 * DM];
__device__ __align__(256) __half g_qkvlo[MROWS * 3 * DM];   // only Q cols used
__device__ __align__(256) __half g_xhi[MROWS * DM];
__device__ __align__(256) __half g_xlo[MROWS * DM];
__device__ __align__(256) __half g_ctxhi[MROWS * DM];
__device__ __align__(256) __half g_ctxlo[MROWS * DM];
__device__ __align__(256) __half g_wqkvTh[3 * DM * DM];     // Wqkv^T [3072,1024] fp16
__device__ __align__(256) __half g_woutTh[DM * DM];         // Wout^T fp16

// ---------------------------------------------------------------------------
// Helpers
// ---------------------------------------------------------------------------
__device__ __forceinline__ uint32_t smem_to_u32(const void* p) {
    uint32_t a;
    asm("{ .reg .u64 t; cvta.to.shared.u64 t, %1; cvt.u32.u64 %0, t; }" : "=r"(a) : "l"(p));
    return a;
}
#define SMEM_SWIZZLE_128B(off) ((off) ^ (((off) >> 3) & 0x70))
#define SMEM_SWIZZLE_64B(off)  ((off) ^ (((off) >> 3) & 0x30))

__device__ __forceinline__ void cp16(uint32_t dst, const void* src) {
    asm volatile("cp.async.cg.shared.global [%0], [%1], 16;" :: "r"(dst), "l"(src));
}
#define CP_COMMIT()    asm volatile("cp.async.commit_group;" ::: "memory")
#define CP_WAIT(n)     asm volatile("cp.async.wait_group %0;" :: "n"(n) : "memory")

__device__ __forceinline__ void ldsm_x4(uint32_t (&r)[4], uint32_t addr) {
    asm volatile("ldmatrix.sync.aligned.m8n8.x4.shared.b16 {%0,%1,%2,%3}, [%4];"
        : "=r"(r[0]), "=r"(r[1]), "=r"(r[2]), "=r"(r[3]) : "r"(addr));
}
__device__ __forceinline__ void ldsm_x4_t(uint32_t (&r)[4], uint32_t addr) {
    asm volatile("ldmatrix.sync.aligned.m8n8.x4.trans.shared.b16 {%0,%1,%2,%3}, [%4];"
        : "=r"(r[0]), "=r"(r[1]), "=r"(r[2]), "=r"(r[3]) : "r"(addr));
}
__device__ __forceinline__ void mma_f16(float (&c)[4], const uint32_t (&a)[4],
                                        uint32_t b0, uint32_t b1) {
    asm volatile("mma.sync.aligned.m16n8k16.row.col.f32.f16.f16.f32 "
        "{%0,%1,%2,%3}, {%4,%5,%6,%7}, {%8,%9}, {%0,%1,%2,%3};"
        : "+f"(c[0]), "+f"(c[1]), "+f"(c[2]), "+f"(c[3])
        : "r"(a[0]), "r"(a[1]), "r"(a[2]), "r"(a[3]), "r"(b0), "r"(b1));
}
__device__ __forceinline__ float fast_exp2(float x) {
    float y;
    asm("ex2.approx.ftz.f32 %0, %1;" : "=f"(y) : "f"(x));
    return y;
}
// split two f32 into packed fp16x2 hi and lo (lo = residual)
__device__ __forceinline__ void split2h(float v0, float v1, uint32_t& hi, uint32_t& lo) {
    __half h0 = __float2half(v0), h1 = __float2half(v1);
    __half l0 = __float2half(v0 - __half2float(h0));
    __half l1 = __float2half(v1 - __half2float(h1));
    __half2 hp = __halves2half2(h0, h1);
    __half2 lp = __halves2half2(l0, l1);
    hi = *reinterpret_cast<uint32_t*>(&hp);
    lo = *reinterpret_cast<uint32_t*>(&lp);
}

// ---------------------------------------------------------------------------
// Split kernels
// ---------------------------------------------------------------------------
__global__ __launch_bounds__(256) void split_f32(
    const float* __restrict__ src, __half* __restrict__ hi,
    __half* __restrict__ lo, int n4)
{
    int i = blockIdx.x * 256 + threadIdx.x;
    if (i >= n4) return;
    float4 v = reinterpret_cast<const float4*>(src)[i];
    __half h[4], l[4];
    float vv[4] = {v.x, v.y, v.z, v.w};
    #pragma unroll
    for (int j = 0; j < 4; j++) {
        h[j] = __float2half(vv[j]);
        l[j] = __float2half(vv[j] - __half2float(h[j]));
    }
    reinterpret_cast<uint2*>(hi)[i] = *reinterpret_cast<uint2*>(h);
    reinterpret_cast<uint2*>(lo)[i] = *reinterpret_cast<uint2*>(l);
}

// Transpose + fp16 round (hi only): W[K,N] f32 -> WT[N,K] fp16
__global__ __launch_bounds__(256) void roundT_f32(
    const float* __restrict__ W, __half* __restrict__ hT, int K, int N)
{
    __shared__ float t[32][33];
    const int kb = blockIdx.y * 32, nb = blockIdx.x * 32;
    const int tx = threadIdx.x & 31, ty0 = threadIdx.x >> 5;
    #pragma unroll
    for (int r = ty0; r < 32; r += 8)
        t[r][tx] = W[(size_t)(kb + r) * N + nb + tx];
    __syncthreads();
    #pragma unroll
    for (int r = ty0; r < 32; r += 8)
        hT[(size_t)(nb + r) * K + kb + tx] = __float2half(t[tx][r]);
}

// ---------------------------------------------------------------------------
// mma.sync fp16 2-pass GEMM + bias:  C = (Ah+Al) @ Bh^T + bias
// CTA 128x128, BK=32 stages x2 (3 tiles/stage), 8 warps of 64x32.
// MODE 0: f32 C.  MODE 1: split fp16 (Chi always; Clo only for cols < DM).
// ---------------------------------------------------------------------------
#define GS_TILE   8192
#define GS_STAGE  (3 * GS_TILE)              // 24576
#define GEMM_SMEM (2 * GS_STAGE)             // 49152

template<int MODE>
__global__ __launch_bounds__(256, 2) void gemm_mma(
    const __half* __restrict__ Ahi, const __half* __restrict__ Alo,
    const __half* __restrict__ Bh,
    const float* __restrict__ bias, float* __restrict__ C,
    __half* __restrict__ Chi, __half* __restrict__ Clo,
    int M, int N, int K)
{
    extern __shared__ char smem[];
    const uint32_t sb = smem_to_u32(smem);
    const int tid = threadIdx.x;
    const int wid = tid >> 5, lid = tid & 31;
    const int wm = wid & 1;
    const int wn = wid >> 1;
    const int m0 = blockIdx.y * 128, n0 = blockIdx.x * 128;

    float acc[4][4][4];
    #pragma unroll
    for (int i = 0; i < 4; i++)
        #pragma unroll
        for (int j = 0; j < 4; j++)
            #pragma unroll
            for (int r = 0; r < 4; r++) acc[i][j][r] = 0.0f;

    const int a_row  = (lid & 7) + ((lid >> 3) & 1) * 8;
    const int a_koff = (lid >> 4) << 3;
    const int b_row  = ((lid >> 4) << 3) + (lid & 7);
    const int b_koff = ((lid >> 3) & 1) << 3;

    const int nStages = K >> 5;

    auto load_stage = [&](int buf, int k0) {
        uint32_t sbase = sb + buf * GS_STAGE;
        #pragma unroll
        for (int t = 0; t < 3; ++t) {
            const __half* src = (t == 0) ? Ahi : (t == 1) ? Alo : Bh;
            const int r0 = (t < 2) ? m0 : n0;
            #pragma unroll
            for (int p = 0; p < 2; ++p) {
                int idx = tid + p * 256;
                int r = idx >> 2;
                int c = (idx & 3) << 3;
                uint32_t off = (uint32_t)(r * 64 + c * 2);
                cp16(sbase + t * GS_TILE + SMEM_SWIZZLE_64B(off),
                     src + (size_t)(r0 + r) * K + k0 + c);
            }
        }
    };

    load_stage(0, 0);
    CP_COMMIT();

    for (int it = 0; it < nStages; ++it) {
        CP_WAIT(0);
        __syncthreads();
        if (it + 1 < nStages) {
            load_stage((it + 1) & 1, (it + 1) << 5);
            CP_COMMIT();
        }

        const uint32_t stage = sb + (it & 1) * GS_STAGE;
        #pragma unroll
        for (int ks = 0; ks < 2; ++ks) {
            const int kk = ks << 4;
            uint32_t ah[4][4], al[4][4], bb[2][4];
            #pragma unroll
            for (int mi = 0; mi < 4; ++mi) {
                int rg = wm * 64 + mi * 16 + a_row;
                uint32_t off = (uint32_t)(rg * 64 + (kk + a_koff) * 2);
                off = SMEM_SWIZZLE_64B(off);
                ldsm_x4(ah[mi], stage + off);
                ldsm_x4(al[mi], stage + GS_TILE + off);
            }
            #pragma unroll
            for (int g = 0; g < 2; ++g) {
                int rg = wn * 32 + g * 16 + b_row;
                uint32_t off = (uint32_t)(rg * 64 + (kk + b_koff) * 2);
                ldsm_x4(bb[g], stage + 2 * GS_TILE + SMEM_SWIZZLE_64B(off));
            }
            // pass 1: ah @ bh  (each acc written once per pass; distance 16)
            #pragma unroll
            for (int mi = 0; mi < 4; ++mi)
                #pragma unroll
                for (int g = 0; g < 2; ++g) {
                    mma_f16(acc[mi][2 * g],     ah[mi], bb[g][0], bb[g][1]);
                    mma_f16(acc[mi][2 * g + 1], ah[mi], bb[g][2], bb[g][3]);
                }
            // pass 2: al @ bh
            #pragma unroll
            for (int mi = 0; mi < 4; ++mi)
                #pragma unroll
                for (int g = 0; g < 2; ++g) {
                    mma_f16(acc[mi][2 * g],     al[mi], bb[g][0], bb[g][1]);
                    mma_f16(acc[mi][2 * g + 1], al[mi], bb[g][2], bb[g][3]);
                }
        }
    }

    const int cg = lid >> 2, ct = lid & 3;
    const bool write_lo = (MODE == 1) && (n0 < DM);   // only Q cols need lo
    #pragma unroll
    for (int mi = 0; mi < 4; ++mi) {
        #pragma unroll
        for (int ni = 0; ni < 4; ++ni) {
            int row = m0 + wm * 64 + mi * 16 + cg;
            int col = n0 + wn * 32 + ni * 8 + 2 * ct;
            float2 bv = *reinterpret_cast<const float2*>(&bias[col]);
            float v00 = acc[mi][ni][0] + bv.x, v01 = acc[mi][ni][1] + bv.y;
            float v10 = acc[mi][ni][2] + bv.x, v11 = acc[mi][ni][3] + bv.y;
            if (MODE == 0) {
                float2 o0 = {v00, v01}, o1 = {v10, v11};
                *reinterpret_cast<float2*>(&C[(size_t)row * N + col]) = o0;
                *reinterpret_cast<float2*>(&C[(size_t)(row + 8) * N + col]) = o1;
            } else {
                uint32_t h, l;
                split2h(v00, v01, h, l);
                *reinterpret_cast<uint32_t*>(&Chi[(size_t)row * N + col]) = h;
                if (write_lo)
                    *reinterpret_cast<uint32_t*>(&Clo[(size_t)row * N + col]) = l;
                split2h(v10, v11, h, l);
                *reinterpret_cast<uint32_t*>(&Chi[(size_t)(row + 8) * N + col]) = h;
                if (write_lo)
                    *reinterpret_cast<uint32_t*>(&Clo[(size_t)(row + 8) * N + col]) = l;
            }
        }
    }
}

// ---------------------------------------------------------------------------
// Tensor-core flash attention (fp16 2-pass). Q/P carry the split; K,V rounded.
// Block: (q-tile 128, b*h). 8 warps of 16 q-rows. cp.async 2-stage KV.
// ---------------------------------------------------------------------------
#define FTS_QHI   0
#define FTS_QLO   16384
#define FKV_BASE  32768
#define FKV_STAGE 16384      // Kh 8K + Vh 8K
#define FLASH_SMEM_TC (FKV_BASE + 2 * FKV_STAGE)   // 65536

__global__ __launch_bounds__(256, 2) void flash_tc(
    const __half* __restrict__ qkvhi, const __half* __restrict__ qkvlo,
    __half* __restrict__ ctxhi, __half* __restrict__ ctxlo)
{
    extern __shared__ char smem[];
    const uint32_t sb = smem_to_u32(smem);
    const int tid = threadIdx.x;
    const int wid = tid >> 5, lid = tid & 31;
    const int bh = blockIdx.x;
    const int qt = (gridDim.y - 1) - blockIdx.y;    // heavy tiles first
    const int b = bh >> 4, h = bh & 15;
    const int q0 = qt * 128;
    const float LOG2E = 1.4426950408889634f;

    auto load_kv = [&](int buf, int k0) {
        uint32_t sbase = sb + FKV_BASE + buf * FKV_STAGE;
        #pragma unroll
        for (int t = 0; t < 2; ++t) {              // 0: Kh, 1: Vh
            const int coloff = (t == 0) ? DM : 2 * DM;
            #pragma unroll
            for (int p = 0; p < 2; ++p) {
                int idx = tid + p * 256;
                int r = idx >> 3;
                int c = (idx & 7) << 3;
                uint32_t off = (uint32_t)(r * 128 + c * 2);
                cp16(sbase + t * 8192 + SMEM_SWIZZLE_128B(off),
                     qkvhi + (size_t)(b * S_LEN + k0 + r) * (3 * DM) + coloff + h * HDIM + c);
            }
        }
    };

    // Q hi/lo into smem, swizzled
    #pragma unroll
    for (int t = 0; t < 2; ++t) {
        const __half* src = t ? qkvlo : qkvhi;
        char* base = smem + (t ? FTS_QLO : FTS_QHI);
        #pragma unroll
        for (int p = 0; p < 4; ++p) {
            int idx = tid + p * 256;
            int r = idx >> 3;
            int c = (idx & 7) << 3;
            uint4 v = *reinterpret_cast<const uint4*>(
                src + (size_t)(b * S_LEN + q0 + r) * (3 * DM) + h * HDIM + c);
            uint32_t off = (uint32_t)(r * 128 + c * 2);
            *reinterpret_cast<uint4*>(base + SMEM_SWIZZLE_128B(off)) = v;
        }
    }
    load_kv(0, 0);
    CP_COMMIT();
    __syncthreads();

    const int a_row  = (lid & 7) + ((lid >> 3) & 1) * 8;
    const int a_koff = (lid >> 4) << 3;
    const int b_row  = ((lid >> 4) << 3) + (lid & 7);
    const int b_koff = ((lid >> 3) & 1) << 3;
    uint32_t qh[4][4], ql[4][4];
    #pragma unroll
    for (int kk = 0; kk < 4; ++kk) {
        int rg = wid * 16 + a_row;
        uint32_t sw = (uint32_t)(rg * 128 + (kk * 16 + a_koff) * 2)
                      ^ ((uint32_t)(rg & 7) << 4);
        ldsm_x4(qh[kk], sb + FTS_QHI + sw);
        ldsm_x4(ql[kk], sb + FTS_QLO + sw);
    }

    float o[8][4];
    #pragma unroll
    for (int j = 0; j < 8; ++j)
        #pragma unroll
        for (int r = 0; r < 4; ++r) o[j][r] = 0.0f;
    float mrow[2] = {-INFINITY, -INFINITY};
    float lrow[2] = {0.0f, 0.0f};

    const int g8 = lid >> 2, t2 = (lid & 3) * 2;
    const int nkt = 2 * qt + 2;

    for (int kt = 0; kt < nkt; ++kt) {
        const int k0 = kt * 64;
        CP_WAIT(0);
        __syncthreads();
        if (kt + 1 < nkt) {
            load_kv((kt + 1) & 1, (kt + 1) * 64);
            CP_COMMIT();
        }

        const uint32_t kvs = sb + FKV_BASE + (kt & 1) * FKV_STAGE;

        if (q0 + wid * 16 + 15 >= k0) {
            float s[8][4];
            #pragma unroll
            for (int j = 0; j < 8; ++j)
                #pragma unroll
                for (int r = 0; r < 4; ++r) s[j][r] = 0.0f;

            // S = (Qh+Ql) @ Kh^T : 2 passes per kk
            #pragma unroll
            for (int kk = 0; kk < 4; ++kk) {
                uint32_t kb[4][4];
                #pragma unroll
                for (int g = 0; g < 4; ++g) {
                    int rg = g * 16 + b_row;
                    uint32_t sw = (uint32_t)(rg * 128 + (kk * 16 + b_koff) * 2)
                                  ^ ((uint32_t)(rg & 7) << 4);
                    ldsm_x4(kb[g], kvs + sw);
                }
                #pragma unroll
                for (int g = 0; g < 4; ++g) {
                    mma_f16(s[2 * g],     qh[kk], kb[g][0], kb[g][1]);
                    mma_f16(s[2 * g + 1], qh[kk], kb[g][2], kb[g][3]);
                }
                #pragma unroll
                for (int g = 0; g < 4; ++g) {
                    mma_f16(s[2 * g],     ql[kk], kb[g][0], kb[g][1]);
                    mma_f16(s[2 * g + 1], ql[kk], kb[g][2], kb[g][3]);
                }
            }

            const bool diag = (k0 + 63 > q0 + wid * 16);
            #pragma unroll
            for (int j = 0; j < 8; ++j) {
                #pragma unroll
                for (int r2 = 0; r2 < 2; ++r2) {
                    int qrow = q0 + wid * 16 + g8 + 8 * r2;
                    #pragma unroll
                    for (int e = 0; e < 2; ++e) {
                        float v = s[j][2 * r2 + e] * 0.125f;
                        if (diag && (k0 + j * 8 + t2 + e > qrow)) v = -1e30f;
                        s[j][2 * r2 + e] = v;
                    }
                }
            }

            #pragma unroll
            for (int r2 = 0; r2 < 2; ++r2) {
                float mx = -INFINITY;
                #pragma unroll
                for (int j = 0; j < 8; ++j)
                    mx = fmaxf(mx, fmaxf(s[j][2 * r2], s[j][2 * r2 + 1]));
                mx = fmaxf(mx, __shfl_xor_sync(0xffffffffu, mx, 1));
                mx = fmaxf(mx, __shfl_xor_sync(0xffffffffu, mx, 2));
                float mnew = fmaxf(mrow[r2], mx);
                float alpha = fast_exp2((mrow[r2] - mnew) * LOG2E);
                mrow[r2] = mnew;
                float ls = 0.0f;
                #pragma unroll
                for (int j = 0; j < 8; ++j) {
                    float p0 = fast_exp2((s[j][2 * r2] - mnew) * LOG2E);
                    float p1 = fast_exp2((s[j][2 * r2 + 1] - mnew) * LOG2E);
                    s[j][2 * r2] = p0;
                    s[j][2 * r2 + 1] = p1;
                    ls += p0 + p1;
                }
                ls += __shfl_xor_sync(0xffffffffu, ls, 1);
                ls += __shfl_xor_sync(0xffffffffu, ls, 2);
                lrow[r2] = lrow[r2] * alpha + ls;
                #pragma unroll
                for (int j = 0; j < 8; ++j) {
                    o[j][2 * r2] *= alpha;
                    o[j][2 * r2 + 1] *= alpha;
                }
            }

            // O += (Ph+Pl) @ Vh : 2 passes per kk
            #pragma unroll
            for (int kk = 0; kk < 4; ++kk) {
                uint32_t ph[4], pl[4];
                split2h(s[2 * kk][0],     s[2 * kk][1],     ph[0], pl[0]);
                split2h(s[2 * kk][2],     s[2 * kk][3],     ph[1], pl[1]);
                split2h(s[2 * kk + 1][0], s[2 * kk + 1][1], ph[2], pl[2]);
                split2h(s[2 * kk + 1][2], s[2 * kk + 1][3], ph[3], pl[3]);
                int vrow = kk * 16 + (lid & 7) + ((lid >> 3) & 1) * 8;
                uint32_t vb[4][4];
                #pragma unroll
                for (int j2 = 0; j2 < 4; ++j2) {
                    uint32_t sw = (uint32_t)(vrow * 128 + j2 * 32 + ((lid >> 4) & 1) * 16)
                                  ^ ((uint32_t)(vrow & 7) << 4);
                    ldsm_x4_t(vb[j2], kvs + 8192 + sw);
                }
                #pragma unroll
                for (int j2 = 0; j2 < 4; ++j2) {
                    mma_f16(o[2 * j2],     ph, vb[j2][0], vb[j2][1]);
                    mma_f16(o[2 * j2 + 1], ph, vb[j2][2], vb[j2][3]);
                }
                #pragma unroll
                for (int j2 = 0; j2 < 4; ++j2) {
                    mma_f16(o[2 * j2],     pl, vb[j2][0], vb[j2][1]);
                    mma_f16(o[2 * j2 + 1], pl, vb[j2][2], vb[j2][3]);
                }
            }
        }
    }

    float inv0 = 1.0f / lrow[0], inv1 = 1.0f / lrow[1];
    size_t row0 = (size_t)(b * S_LEN + q0 + wid * 16 + g8);
    #pragma unroll
    for (int j = 0; j < 8; ++j) {
        int c = h * HDIM + j * 8 + t2;
        uint32_t hi0, lo0, hi1, lo1;
        split2h(o[j][0] * inv0, o[j][1] * inv0, hi0, lo0);
        split2h(o[j][2] * inv1, o[j][3] * inv1, hi1, lo1);
        *reinterpret_cast<uint32_t*>(&ctxhi[row0 * DM + c]) = hi0;
        *reinterpret_cast<uint32_t*>(&ctxlo[row0 * DM + c]) = lo0;
        *reinterpret_cast<uint32_t*>(&ctxhi[(row0 + 8) * DM + c]) = hi1;
        *reinterpret_cast<uint32_t*>(&ctxlo[(row0 + 8) * DM + c]) = lo1;
    }
}

// ---------------------------------------------------------------------------
extern "C" void kernel_launch(void* const* d_in, const int* in_sizes, int n_in,
                              void* d_out, int out_size)
{
    const float* x    = (const float*)d_in[0];
    const float* Wqkv = (const float*)d_in[1];
    const float* bqkv = (const float*)d_in[2];
    const float* Wout = (const float*)d_in[3];
    const float* bout = (const float*)d_in[4];
    float* out = (float*)d_out;

    __half *qkvhi, *qkvlo, *xhi, *xlo, *ctxhi, *ctxlo, *wqh, *woh;
    cudaGetSymbolAddress((void**)&qkvhi, g_qkvhi);
    cudaGetSymbolAddress((void**)&qkvlo, g_qkvlo);
    cudaGetSymbolAddress((void**)&xhi, g_xhi);
    cudaGetSymbolAddress((void**)&xlo, g_xlo);
    cudaGetSymbolAddress((void**)&ctxhi, g_ctxhi);
    cudaGetSymbolAddress((void**)&ctxlo, g_ctxlo);
    cudaGetSymbolAddress((void**)&wqh, g_wqkvTh);
    cudaGetSymbolAddress((void**)&woh, g_woutTh);

    cudaFuncSetAttribute(gemm_mma<0>, cudaFuncAttributeMaxDynamicSharedMemorySize, GEMM_SMEM);
    cudaFuncSetAttribute(gemm_mma<1>, cudaFuncAttributeMaxDynamicSharedMemorySize, GEMM_SMEM);
    cudaFuncSetAttribute(flash_tc, cudaFuncAttributeMaxDynamicSharedMemorySize, FLASH_SMEM_TC);

    int nx4 = MROWS * DM / 4;
    split_f32<<<(nx4 + 255) / 256, 256>>>(x, xhi, xlo, nx4);
    roundT_f32<<<dim3(3 * DM / 32, DM / 32), 256>>>(Wqkv, wqh, DM, 3 * DM);
    roundT_f32<<<dim3(DM / 32, DM / 32), 256>>>(Wout, woh, DM, DM);

    // 1) QKV projection -> split fp16 qkv (lo only for Q columns)
    gemm_mma<1><<<dim3(3 * DM / 128, MROWS / 128), 256, GEMM_SMEM>>>(
        xhi, xlo, wqh, bqkv, nullptr, qkvhi, qkvlo, MROWS, 3 * DM, DM);

    // 2) Causal flash attention -> split fp16 ctx
    flash_tc<<<dim3(BATCH * NHEADS, S_LEN / 128), 256, FLASH_SMEM_TC>>>(
        qkvhi, qkvlo, ctxhi, ctxlo);

    // 3) Output projection -> f32 out
    gemm_mma<0><<<dim3(DM / 128, MROWS / 128), 256, GEMM_SMEM>>>(
        ctxhi, ctxlo, woh, bout, out, nullptr, nullptr, MROWS, DM, DM);
}

// round 11
// speedup vs baseline: 6.3433x; 1.3924x over previous
#include <cuda_runtime.h>
#include <cuda_fp16.h>
#include <cstdint>
#include <math.h>

#define S_LEN   2048
#define DM      1024
#define NHEADS  16
#define HDIM    64
#define BATCH   2
#define MROWS   (BATCH * S_LEN)   // 4096

// ---------------------------------------------------------------------------
// Scratch (device globals; no runtime allocation allowed)
// ---------------------------------------------------------------------------
__device__ __align__(256) __half g_qkvhi[MROWS * 3 * DM];
__device__ __align__(256) __half g_qkvlo[MROWS * 3 * DM];   // only Q cols used
__device__ __align__(256) __half g_xhi[MROWS * DM];
__device__ __align__(256) __half g_xlo[MROWS * DM];
__device__ __align__(256) __half g_ctxhi[MROWS * DM];
__device__ __align__(256) __half g_wqkvTh[3 * DM * DM];     // Wqkv^T [3072,1024] fp16
__device__ __align__(256) __half g_woutTh[DM * DM];         // Wout^T fp16

// ---------------------------------------------------------------------------
// Helpers
// ---------------------------------------------------------------------------
__device__ __forceinline__ uint32_t smem_to_u32(const void* p) {
    uint32_t a;
    asm("{ .reg .u64 t; cvta.to.shared.u64 t, %1; cvt.u32.u64 %0, t; }" : "=r"(a) : "l"(p));
    return a;
}
#define SMEM_SWIZZLE_128B(off) ((off) ^ (((off) >> 3) & 0x70))
#define SMEM_SWIZZLE_64B(off)  ((off) ^ (((off) >> 3) & 0x30))

__device__ __forceinline__ void cp16(uint32_t dst, const void* src) {
    asm volatile("cp.async.cg.shared.global [%0], [%1], 16;" :: "r"(dst), "l"(src));
}
#define CP_COMMIT()    asm volatile("cp.async.commit_group;" ::: "memory")
#define CP_WAIT(n)     asm volatile("cp.async.wait_group %0;" :: "n"(n) : "memory")

__device__ __forceinline__ void ldsm_x4(uint32_t (&r)[4], uint32_t addr) {
    asm volatile("ldmatrix.sync.aligned.m8n8.x4.shared.b16 {%0,%1,%2,%3}, [%4];"
        : "=r"(r[0]), "=r"(r[1]), "=r"(r[2]), "=r"(r[3]) : "r"(addr));
}
__device__ __forceinline__ void ldsm_x4_t(uint32_t (&r)[4], uint32_t addr) {
    asm volatile("ldmatrix.sync.aligned.m8n8.x4.trans.shared.b16 {%0,%1,%2,%3}, [%4];"
        : "=r"(r[0]), "=r"(r[1]), "=r"(r[2]), "=r"(r[3]) : "r"(addr));
}
__device__ __forceinline__ void mma_f16(float (&c)[4], const uint32_t (&a)[4],
                                        uint32_t b0, uint32_t b1) {
    asm volatile("mma.sync.aligned.m16n8k16.row.col.f32.f16.f16.f32 "
        "{%0,%1,%2,%3}, {%4,%5,%6,%7}, {%8,%9}, {%0,%1,%2,%3};"
        : "+f"(c[0]), "+f"(c[1]), "+f"(c[2]), "+f"(c[3])
        : "r"(a[0]), "r"(a[1]), "r"(a[2]), "r"(a[3]), "r"(b0), "r"(b1));
}
__device__ __forceinline__ float fast_exp2(float x) {
    float y;
    asm("ex2.approx.ftz.f32 %0, %1;" : "=f"(y) : "f"(x));
    return y;
}
__device__ __forceinline__ uint32_t pack_h2(float v0, float v1) {
    __half2 hp = __floats2half2_rn(v0, v1);
    return *reinterpret_cast<uint32_t*>(&hp);
}
__device__ __forceinline__ void split2h(float v0, float v1, uint32_t& hi, uint32_t& lo) {
    __half h0 = __float2half(v0), h1 = __float2half(v1);
    __half l0 = __float2half(v0 - __half2float(h0));
    __half l1 = __float2half(v1 - __half2float(h1));
    __half2 hp = __halves2half2(h0, h1);
    __half2 lp = __halves2half2(l0, l1);
    hi = *reinterpret_cast<uint32_t*>(&hp);
    lo = *reinterpret_cast<uint32_t*>(&lp);
}

// ---------------------------------------------------------------------------
// Split kernels
// ---------------------------------------------------------------------------
__global__ __launch_bounds__(256) void split_f32(
    const float* __restrict__ src, __half* __restrict__ hi,
    __half* __restrict__ lo, int n4)
{
    int i = blockIdx.x * 256 + threadIdx.x;
    if (i >= n4) return;
    float4 v = reinterpret_cast<const float4*>(src)[i];
    __half h[4], l[4];
    float vv[4] = {v.x, v.y, v.z, v.w};
    #pragma unroll
    for (int j = 0; j < 4; j++) {
        h[j] = __float2half(vv[j]);
        l[j] = __float2half(vv[j] - __half2float(h[j]));
    }
    reinterpret_cast<uint2*>(hi)[i] = *reinterpret_cast<uint2*>(h);
    reinterpret_cast<uint2*>(lo)[i] = *reinterpret_cast<uint2*>(l);
}

__global__ __launch_bounds__(256) void roundT_f32(
    const float* __restrict__ W, __half* __restrict__ hT, int K, int N)
{
    __shared__ float t[32][33];
    const int kb = blockIdx.y * 32, nb = blockIdx.x * 32;
    const int tx = threadIdx.x & 31, ty0 = threadIdx.x >> 5;
    #pragma unroll
    for (int r = ty0; r < 32; r += 8)
        t[r][tx] = W[(size_t)(kb + r) * N + nb + tx];
    __syncthreads();
    #pragma unroll
    for (int r = ty0; r < 32; r += 8)
        hT[(size_t)(nb + r) * K + kb + tx] = __float2half(t[tx][r]);
}

// ---------------------------------------------------------------------------
// mma.sync fp16 GEMM + bias.
// MODE 0 (out-proj): A single (Ahi only), 1 pass, f32 C.   stage = 2 tiles.
// MODE 1 (QKV):      A split; pass2 only for Q cols (n0<DM); fp16 Chi always,
//                    Clo for Q cols.                         stage = 3 tiles.
// CTA 128x128, BK=32, 2 stages, 8 warps of 64x32.
// ---------------------------------------------------------------------------
#define GS_TILE 8192

template<int MODE>
__global__ __launch_bounds__(256, 2) void gemm_mma(
    const __half* __restrict__ Ahi, const __half* __restrict__ Alo,
    const __half* __restrict__ Bh,
    const float* __restrict__ bias, float* __restrict__ C,
    __half* __restrict__ Chi, __half* __restrict__ Clo,
    int M, int N, int K)
{
    constexpr int NT = (MODE == 0) ? 2 : 3;          // tiles per stage
    constexpr int STAGE = NT * GS_TILE;
    const int BTILE = (NT - 1) * GS_TILE;            // B tile offset

    extern __shared__ char smem[];
    const uint32_t sb = smem_to_u32(smem);
    const int tid = threadIdx.x;
    const int wid = tid >> 5, lid = tid & 31;
    const int wm = wid & 1;
    const int wn = wid >> 1;
    const int m0 = blockIdx.y * 128, n0 = blockIdx.x * 128;
    const bool pass2 = (MODE == 1) && (n0 < DM);     // A-lo pass (Q cols only)

    float acc[4][4][4];
    #pragma unroll
    for (int i = 0; i < 4; i++)
        #pragma unroll
        for (int j = 0; j < 4; j++)
            #pragma unroll
            for (int r = 0; r < 4; r++) acc[i][j][r] = 0.0f;

    const int a_row  = (lid & 7) + ((lid >> 3) & 1) * 8;
    const int a_koff = (lid >> 4) << 3;
    const int b_row  = ((lid >> 4) << 3) + (lid & 7);
    const int b_koff = ((lid >> 3) & 1) << 3;

    const int nStages = K >> 5;

    auto load_stage = [&](int buf, int k0) {
        uint32_t sbase = sb + buf * STAGE;
        #pragma unroll
        for (int t = 0; t < NT; ++t) {
            if (NT == 3 && t == 1 && !pass2) continue;   // skip unused Alo
            const __half* src = (t == 0) ? Ahi : (t == NT - 1) ? Bh : Alo;
            const int r0 = (t == NT - 1) ? n0 : m0;
            #pragma unroll
            for (int p = 0; p < 2; ++p) {
                int idx = tid + p * 256;
                int r = idx >> 2;
                int c = (idx & 3) << 3;
                uint32_t off = (uint32_t)(r * 64 + c * 2);
                cp16(sbase + t * GS_TILE + SMEM_SWIZZLE_64B(off),
                     src + (size_t)(r0 + r) * K + k0 + c);
            }
        }
    };

    load_stage(0, 0);
    CP_COMMIT();

    for (int it = 0; it < nStages; ++it) {
        CP_WAIT(0);
        __syncthreads();
        if (it + 1 < nStages) {
            load_stage((it + 1) & 1, (it + 1) << 5);
            CP_COMMIT();
        }

        const uint32_t stage = sb + (it & 1) * STAGE;
        #pragma unroll
        for (int ks = 0; ks < 2; ++ks) {
            const int kk = ks << 4;
            uint32_t ah[4][4], bb[2][4];
            uint32_t aoff[4];
            #pragma unroll
            for (int mi = 0; mi < 4; ++mi) {
                int rg = wm * 64 + mi * 16 + a_row;
                aoff[mi] = SMEM_SWIZZLE_64B((uint32_t)(rg * 64 + (kk + a_koff) * 2));
                ldsm_x4(ah[mi], stage + aoff[mi]);
            }
            #pragma unroll
            for (int g = 0; g < 2; ++g) {
                int rg = wn * 32 + g * 16 + b_row;
                uint32_t off = (uint32_t)(rg * 64 + (kk + b_koff) * 2);
                ldsm_x4(bb[g], stage + BTILE + SMEM_SWIZZLE_64B(off));
            }
            // pass 1: ah @ bh
            #pragma unroll
            for (int mi = 0; mi < 4; ++mi)
                #pragma unroll
                for (int g = 0; g < 2; ++g) {
                    mma_f16(acc[mi][2 * g],     ah[mi], bb[g][0], bb[g][1]);
                    mma_f16(acc[mi][2 * g + 1], ah[mi], bb[g][2], bb[g][3]);
                }
            // pass 2 (Q cols only): al @ bh
            if (MODE == 1 && pass2) {
                uint32_t al[4][4];
                #pragma unroll
                for (int mi = 0; mi < 4; ++mi)
                    ldsm_x4(al[mi], stage + GS_TILE + aoff[mi]);
                #pragma unroll
                for (int mi = 0; mi < 4; ++mi)
                    #pragma unroll
                    for (int g = 0; g < 2; ++g) {
                        mma_f16(acc[mi][2 * g],     al[mi], bb[g][0], bb[g][1]);
                        mma_f16(acc[mi][2 * g + 1], al[mi], bb[g][2], bb[g][3]);
                    }
            }
        }
    }

    const int cg = lid >> 2, ct = lid & 3;
    #pragma unroll
    for (int mi = 0; mi < 4; ++mi) {
        #pragma unroll
        for (int ni = 0; ni < 4; ++ni) {
            int row = m0 + wm * 64 + mi * 16 + cg;
            int col = n0 + wn * 32 + ni * 8 + 2 * ct;
            float2 bv = *reinterpret_cast<const float2*>(&bias[col]);
            float v00 = acc[mi][ni][0] + bv.x, v01 = acc[mi][ni][1] + bv.y;
            float v10 = acc[mi][ni][2] + bv.x, v11 = acc[mi][ni][3] + bv.y;
            if (MODE == 0) {
                float2 o0 = {v00, v01}, o1 = {v10, v11};
                *reinterpret_cast<float2*>(&C[(size_t)row * N + col]) = o0;
                *reinterpret_cast<float2*>(&C[(size_t)(row + 8) * N + col]) = o1;
            } else {
                if (pass2) {          // Q cols: split store
                    uint32_t h, l;
                    split2h(v00, v01, h, l);
                    *reinterpret_cast<uint32_t*>(&Chi[(size_t)row * N + col]) = h;
                    *reinterpret_cast<uint32_t*>(&Clo[(size_t)row * N + col]) = l;
                    split2h(v10, v11, h, l);
                    *reinterpret_cast<uint32_t*>(&Chi[(size_t)(row + 8) * N + col]) = h;
                    *reinterpret_cast<uint32_t*>(&Clo[(size_t)(row + 8) * N + col]) = l;
                } else {              // K/V cols: hi only
                    *reinterpret_cast<uint32_t*>(&Chi[(size_t)row * N + col]) =
                        pack_h2(v00, v01);
                    *reinterpret_cast<uint32_t*>(&Chi[(size_t)(row + 8) * N + col]) =
                        pack_h2(v10, v11);
                }
            }
        }
    }
}

#define GEMM_SMEM_0 (2 * 2 * GS_TILE)   // 32768
#define GEMM_SMEM_1 (2 * 3 * GS_TILE)   // 49152

// ---------------------------------------------------------------------------
// Tensor-core flash attention (fp16). S: 2 passes (Q split). PV: 1 pass.
// Block: (q-tile 128, b*h). 8 warps of 16 q-rows. cp.async 2-stage KV.
// ctx written fp16 hi only.
// ---------------------------------------------------------------------------
#define FTS_QHI   0
#define FTS_QLO   16384
#define FKV_BASE  32768
#define FKV_STAGE 16384      // Kh 8K + Vh 8K
#define FLASH_SMEM_TC (FKV_BASE + 2 * FKV_STAGE)   // 65536

__global__ __launch_bounds__(256, 2) void flash_tc(
    const __half* __restrict__ qkvhi, const __half* __restrict__ qkvlo,
    __half* __restrict__ ctxhi)
{
    extern __shared__ char smem[];
    const uint32_t sb = smem_to_u32(smem);
    const int tid = threadIdx.x;
    const int wid = tid >> 5, lid = tid & 31;
    const int bh = blockIdx.x;
    const int qt = (gridDim.y - 1) - blockIdx.y;    // heavy tiles first
    const int b = bh >> 4, h = bh & 15;
    const int q0 = qt * 128;
    const float LOG2E = 1.4426950408889634f;

    auto load_kv = [&](int buf, int k0) {
        uint32_t sbase = sb + FKV_BASE + buf * FKV_STAGE;
        #pragma unroll
        for (int t = 0; t < 2; ++t) {              // 0: Kh, 1: Vh
            const int coloff = (t == 0) ? DM : 2 * DM;
            #pragma unroll
            for (int p = 0; p < 2; ++p) {
                int idx = tid + p * 256;
                int r = idx >> 3;
                int c = (idx & 7) << 3;
                uint32_t off = (uint32_t)(r * 128 + c * 2);
                cp16(sbase + t * 8192 + SMEM_SWIZZLE_128B(off),
                     qkvhi + (size_t)(b * S_LEN + k0 + r) * (3 * DM) + coloff + h * HDIM + c);
            }
        }
    };

    #pragma unroll
    for (int t = 0; t < 2; ++t) {
        const __half* src = t ? qkvlo : qkvhi;
        char* base = smem + (t ? FTS_QLO : FTS_QHI);
        #pragma unroll
        for (int p = 0; p < 4; ++p) {
            int idx = tid + p * 256;
            int r = idx >> 3;
            int c = (idx & 7) << 3;
            uint4 v = *reinterpret_cast<const uint4*>(
                src + (size_t)(b * S_LEN + q0 + r) * (3 * DM) + h * HDIM + c);
            uint32_t off = (uint32_t)(r * 128 + c * 2);
            *reinterpret_cast<uint4*>(base + SMEM_SWIZZLE_128B(off)) = v;
        }
    }
    load_kv(0, 0);
    CP_COMMIT();
    __syncthreads();

    const int a_row  = (lid & 7) + ((lid >> 3) & 1) * 8;
    const int a_koff = (lid >> 4) << 3;
    const int b_row  = ((lid >> 4) << 3) + (lid & 7);
    const int b_koff = ((lid >> 3) & 1) << 3;
    uint32_t qh[4][4], ql[4][4];
    #pragma unroll
    for (int kk = 0; kk < 4; ++kk) {
        int rg = wid * 16 + a_row;
        uint32_t sw = (uint32_t)(rg * 128 + (kk * 16 + a_koff) * 2)
                      ^ ((uint32_t)(rg & 7) << 4);
        ldsm_x4(qh[kk], sb + FTS_QHI + sw);
        ldsm_x4(ql[kk], sb + FTS_QLO + sw);
    }

    float o[8][4];
    #pragma unroll
    for (int j = 0; j < 8; ++j)
        #pragma unroll
        for (int r = 0; r < 4; ++r) o[j][r] = 0.0f;
    float mrow[2] = {-INFINITY, -INFINITY};
    float lrow[2] = {0.0f, 0.0f};

    const int g8 = lid >> 2, t2 = (lid & 3) * 2;
    const int nkt = 2 * qt + 2;

    for (int kt = 0; kt < nkt; ++kt) {
        const int k0 = kt * 64;
        CP_WAIT(0);
        __syncthreads();
        if (kt + 1 < nkt) {
            load_kv((kt + 1) & 1, (kt + 1) * 64);
            CP_COMMIT();
        }

        const uint32_t kvs = sb + FKV_BASE + (kt & 1) * FKV_STAGE;

        if (q0 + wid * 16 + 15 >= k0) {
            float s[8][4];
            #pragma unroll
            for (int j = 0; j < 8; ++j)
                #pragma unroll
                for (int r = 0; r < 4; ++r) s[j][r] = 0.0f;

            // S = (Qh+Ql) @ Kh^T
            #pragma unroll
            for (int kk = 0; kk < 4; ++kk) {
                uint32_t kb[4][4];
                #pragma unroll
                for (int g = 0; g < 4; ++g) {
                    int rg = g * 16 + b_row;
                    uint32_t sw = (uint32_t)(rg * 128 + (kk * 16 + b_koff) * 2)
                                  ^ ((uint32_t)(rg & 7) << 4);
                    ldsm_x4(kb[g], kvs + sw);
                }
                #pragma unroll
                for (int g = 0; g < 4; ++g) {
                    mma_f16(s[2 * g],     qh[kk], kb[g][0], kb[g][1]);
                    mma_f16(s[2 * g + 1], qh[kk], kb[g][2], kb[g][3]);
                }
                #pragma unroll
                for (int g = 0; g < 4; ++g) {
                    mma_f16(s[2 * g],     ql[kk], kb[g][0], kb[g][1]);
                    mma_f16(s[2 * g + 1], ql[kk], kb[g][2], kb[g][3]);
                }
            }

            const bool diag = (k0 + 63 > q0 + wid * 16);
            #pragma unroll
            for (int j = 0; j < 8; ++j) {
                #pragma unroll
                for (int r2 = 0; r2 < 2; ++r2) {
                    int qrow = q0 + wid * 16 + g8 + 8 * r2;
                    #pragma unroll
                    for (int e = 0; e < 2; ++e) {
                        float v = s[j][2 * r2 + e] * 0.125f;
                        if (diag && (k0 + j * 8 + t2 + e > qrow)) v = -1e30f;
                        s[j][2 * r2 + e] = v;
                    }
                }
            }

            #pragma unroll
            for (int r2 = 0; r2 < 2; ++r2) {
                float mx = -INFINITY;
                #pragma unroll
                for (int j = 0; j < 8; ++j)
                    mx = fmaxf(mx, fmaxf(s[j][2 * r2], s[j][2 * r2 + 1]));
                mx = fmaxf(mx, __shfl_xor_sync(0xffffffffu, mx, 1));
                mx = fmaxf(mx, __shfl_xor_sync(0xffffffffu, mx, 2));
                float mnew = fmaxf(mrow[r2], mx);
                float alpha = fast_exp2((mrow[r2] - mnew) * LOG2E);
                mrow[r2] = mnew;
                float ls = 0.0f;
                #pragma unroll
                for (int j = 0; j < 8; ++j) {
                    float p0 = fast_exp2((s[j][2 * r2] - mnew) * LOG2E);
                    float p1 = fast_exp2((s[j][2 * r2 + 1] - mnew) * LOG2E);
                    s[j][2 * r2] = p0;
                    s[j][2 * r2 + 1] = p1;
                    ls += p0 + p1;
                }
                ls += __shfl_xor_sync(0xffffffffu, ls, 1);
                ls += __shfl_xor_sync(0xffffffffu, ls, 2);
                lrow[r2] = lrow[r2] * alpha + ls;
                #pragma unroll
                for (int j = 0; j < 8; ++j) {
                    o[j][2 * r2] *= alpha;
                    o[j][2 * r2 + 1] *= alpha;
                }
            }

            // O += Ph @ Vh (single pass)
            #pragma unroll
            for (int kk = 0; kk < 4; ++kk) {
                uint32_t ph[4];
                ph[0] = pack_h2(s[2 * kk][0],     s[2 * kk][1]);
                ph[1] = pack_h2(s[2 * kk][2],     s[2 * kk][3]);
                ph[2] = pack_h2(s[2 * kk + 1][0], s[2 * kk + 1][1]);
                ph[3] = pack_h2(s[2 * kk + 1][2], s[2 * kk + 1][3]);
                int vrow = kk * 16 + (lid & 7) + ((lid >> 3) & 1) * 8;
                uint32_t vb[4][4];
                #pragma unroll
                for (int j2 = 0; j2 < 4; ++j2) {
                    uint32_t sw = (uint32_t)(vrow * 128 + j2 * 32 + ((lid >> 4) & 1) * 16)
                                  ^ ((uint32_t)(vrow & 7) << 4);
                    ldsm_x4_t(vb[j2], kvs + 8192 + sw);
                }
                #pragma unroll
                for (int j2 = 0; j2 < 4; ++j2) {
                    mma_f16(o[2 * j2],     ph, vb[j2][0], vb[j2][1]);
                    mma_f16(o[2 * j2 + 1], ph, vb[j2][2], vb[j2][3]);
                }
            }
        }
    }

    float inv0 = 1.0f / lrow[0], inv1 = 1.0f / lrow[1];
    size_t row0 = (size_t)(b * S_LEN + q0 + wid * 16 + g8);
    #pragma unroll
    for (int j = 0; j < 8; ++j) {
        int c = h * HDIM + j * 8 + t2;
        *reinterpret_cast<uint32_t*>(&ctxhi[row0 * DM + c]) =
            pack_h2(o[j][0] * inv0, o[j][1] * inv0);
        *reinterpret_cast<uint32_t*>(&ctxhi[(row0 + 8) * DM + c]) =
            pack_h2(o[j][2] * inv1, o[j][3] * inv1);
    }
}

// ---------------------------------------------------------------------------
extern "C" void kernel_launch(void* const* d_in, const int* in_sizes, int n_in,
                              void* d_out, int out_size)
{
    const float* x    = (const float*)d_in[0];
    const float* Wqkv = (const float*)d_in[1];
    const float* bqkv = (const float*)d_in[2];
    const float* Wout = (const float*)d_in[3];
    const float* bout = (const float*)d_in[4];
    float* out = (float*)d_out;

    __half *qkvhi, *qkvlo, *xhi, *xlo, *ctxhi, *wqh, *woh;
    cudaGetSymbolAddress((void**)&qkvhi, g_qkvhi);
    cudaGetSymbolAddress((void**)&qkvlo, g_qkvlo);
    cudaGetSymbolAddress((void**)&xhi, g_xhi);
    cudaGetSymbolAddress((void**)&xlo, g_xlo);
    cudaGetSymbolAddress((void**)&ctxhi, g_ctxhi);
    cudaGetSymbolAddress((void**)&wqh, g_wqkvTh);
    cudaGetSymbolAddress((void**)&woh, g_woutTh);

    cudaFuncSetAttribute(gemm_mma<0>, cudaFuncAttributeMaxDynamicSharedMemorySize, GEMM_SMEM_0);
    cudaFuncSetAttribute(gemm_mma<1>, cudaFuncAttributeMaxDynamicSharedMemorySize, GEMM_SMEM_1);
    cudaFuncSetAttribute(flash_tc, cudaFuncAttributeMaxDynamicSharedMemorySize, FLASH_SMEM_TC);

    int nx4 = MROWS * DM / 4;
    split_f32<<<(nx4 + 255) / 256, 256>>>(x, xhi, xlo, nx4);
    roundT_f32<<<dim3(3 * DM / 32, DM / 32), 256>>>(Wqkv, wqh, DM, 3 * DM);
    roundT_f32<<<dim3(DM / 32, DM / 32), 256>>>(Wout, woh, DM, DM);

    // 1) QKV projection: Q cols 2-pass + split store; K/V cols 1-pass hi store
    gemm_mma<1><<<dim3(3 * DM / 128, MROWS / 128), 256, GEMM_SMEM_1>>>(
        xhi, xlo, wqh, bqkv, nullptr, qkvhi, qkvlo, MROWS, 3 * DM, DM);

    // 2) Causal flash attention -> fp16 ctx (hi only)
    flash_tc<<<dim3(BATCH * NHEADS, S_LEN / 128), 256, FLASH_SMEM_TC>>>(
        qkvhi, qkvlo, ctxhi);

    // 3) Output projection (single-pass A) -> f32 out
    gemm_mma<0><<<dim3(DM / 128, MROWS / 128), 256, GEMM_SMEM_0>>>(
        ctxhi, nullptr, woh, bout, out, nullptr, nullptr, MROWS, DM, DM);
}

// round 12
// speedup vs baseline: 7.6553x; 1.2068x over previous
#include <cuda_runtime.h>
#include <cuda_fp16.h>
#include <cstdint>
#include <math.h>

#define S_LEN   2048
#define DM      1024
#define NHEADS  16
#define HDIM    64
#define BATCH   2
#define MROWS   (BATCH * S_LEN)   // 4096

// ---------------------------------------------------------------------------
// Scratch (device globals; no runtime allocation allowed)
// ---------------------------------------------------------------------------
__device__ __align__(256) __half g_qkvh[MROWS * 3 * DM];
__device__ __align__(256) __half g_xh[MROWS * DM];
__device__ __align__(256) __half g_ctxh[MROWS * DM];
__device__ __align__(256) __half g_wqkvTh[3 * DM * DM];     // Wqkv^T [3072,1024] fp16
__device__ __align__(256) __half g_woutTh[DM * DM];         // Wout^T fp16

// ---------------------------------------------------------------------------
// Helpers
// ---------------------------------------------------------------------------
__device__ __forceinline__ uint32_t smem_to_u32(const void* p) {
    uint32_t a;
    asm("{ .reg .u64 t; cvta.to.shared.u64 t, %1; cvt.u32.u64 %0, t; }" : "=r"(a) : "l"(p));
    return a;
}
#define SMEM_SWIZZLE_128B(off) ((off) ^ (((off) >> 3) & 0x70))
#define SMEM_SWIZZLE_64B(off)  ((off) ^ (((off) >> 3) & 0x30))

__device__ __forceinline__ void cp16(uint32_t dst, const void* src) {
    asm volatile("cp.async.cg.shared.global [%0], [%1], 16;" :: "r"(dst), "l"(src));
}
#define CP_COMMIT()    asm volatile("cp.async.commit_group;" ::: "memory")
#define CP_WAIT(n)     asm volatile("cp.async.wait_group %0;" :: "n"(n) : "memory")

__device__ __forceinline__ void ldsm_x4(uint32_t (&r)[4], uint32_t addr) {
    asm volatile("ldmatrix.sync.aligned.m8n8.x4.shared.b16 {%0,%1,%2,%3}, [%4];"
        : "=r"(r[0]), "=r"(r[1]), "=r"(r[2]), "=r"(r[3]) : "r"(addr));
}
__device__ __forceinline__ void ldsm_x4_t(uint32_t (&r)[4], uint32_t addr) {
    asm volatile("ldmatrix.sync.aligned.m8n8.x4.trans.shared.b16 {%0,%1,%2,%3}, [%4];"
        : "=r"(r[0]), "=r"(r[1]), "=r"(r[2]), "=r"(r[3]) : "r"(addr));
}
__device__ __forceinline__ void mma_f16(float (&c)[4], const uint32_t (&a)[4],
                                        uint32_t b0, uint32_t b1) {
    asm volatile("mma.sync.aligned.m16n8k16.row.col.f32.f16.f16.f32 "
        "{%0,%1,%2,%3}, {%4,%5,%6,%7}, {%8,%9}, {%0,%1,%2,%3};"
        : "+f"(c[0]), "+f"(c[1]), "+f"(c[2]), "+f"(c[3])
        : "r"(a[0]), "r"(a[1]), "r"(a[2]), "r"(a[3]), "r"(b0), "r"(b1));
}
__device__ __forceinline__ float fast_exp2(float x) {
    float y;
    asm("ex2.approx.ftz.f32 %0, %1;" : "=f"(y) : "f"(x));
    return y;
}
__device__ __forceinline__ uint32_t pack_h2(float v0, float v1) {
    __half2 hp = __floats2half2_rn(v0, v1);
    return *reinterpret_cast<uint32_t*>(&hp);
}

// ---------------------------------------------------------------------------
// Prologue kernels
// ---------------------------------------------------------------------------
__global__ __launch_bounds__(256) void round_f32(
    const float* __restrict__ src, __half* __restrict__ dst, int n4)
{
    int i = blockIdx.x * 256 + threadIdx.x;
    if (i >= n4) return;
    float4 v = reinterpret_cast<const float4*>(src)[i];
    uint2 o;
    o.x = pack_h2(v.x, v.y);
    o.y = pack_h2(v.z, v.w);
    reinterpret_cast<uint2*>(dst)[i] = o;
}

__global__ __launch_bounds__(256) void roundT_f32(
    const float* __restrict__ W, __half* __restrict__ hT, int K, int N)
{
    __shared__ float t[32][33];
    const int kb = blockIdx.y * 32, nb = blockIdx.x * 32;
    const int tx = threadIdx.x & 31, ty0 = threadIdx.x >> 5;
    #pragma unroll
    for (int r = ty0; r < 32; r += 8)
        t[r][tx] = W[(size_t)(kb + r) * N + nb + tx];
    __syncthreads();
    #pragma unroll
    for (int r = ty0; r < 32; r += 8)
        hT[(size_t)(nb + r) * K + kb + tx] = __float2half(t[tx][r]);
}

// ---------------------------------------------------------------------------
// mma.sync fp16 single-pass GEMM + bias:  C = Ah @ Bh^T + bias
// CTA 128x128, BK=32, 2 stages x (A 8K + B 8K), 8 warps of 64x32.
// MODE 0: f32 C.  MODE 1: fp16 Ch.
// ---------------------------------------------------------------------------
#define GS_TILE   8192
#define GS_STAGE  (2 * GS_TILE)              // 16384
#define GEMM_SMEM (2 * GS_STAGE)             // 32768

template<int MODE>
__global__ __launch_bounds__(256, 2) void gemm_mma(
    const __half* __restrict__ Ah, const __half* __restrict__ Bh,
    const float* __restrict__ bias, float* __restrict__ C,
    __half* __restrict__ Ch, int M, int N, int K)
{
    extern __shared__ char smem[];
    const uint32_t sb = smem_to_u32(smem);
    const int tid = threadIdx.x;
    const int wid = tid >> 5, lid = tid & 31;
    const int wm = wid & 1;
    const int wn = wid >> 1;
    const int m0 = blockIdx.y * 128, n0 = blockIdx.x * 128;

    float acc[4][4][4];
    #pragma unroll
    for (int i = 0; i < 4; i++)
        #pragma unroll
        for (int j = 0; j < 4; j++)
            #pragma unroll
            for (int r = 0; r < 4; r++) acc[i][j][r] = 0.0f;

    const int a_row  = (lid & 7) + ((lid >> 3) & 1) * 8;
    const int a_koff = (lid >> 4) << 3;
    const int b_row  = ((lid >> 4) << 3) + (lid & 7);
    const int b_koff = ((lid >> 3) & 1) << 3;

    const int nStages = K >> 5;

    auto load_stage = [&](int buf, int k0) {
        uint32_t sbase = sb + buf * GS_STAGE;
        #pragma unroll
        for (int t = 0; t < 2; ++t) {
            const __half* src = (t == 0) ? Ah : Bh;
            const int r0 = (t == 0) ? m0 : n0;
            #pragma unroll
            for (int p = 0; p < 2; ++p) {
                int idx = tid + p * 256;
                int r = idx >> 2;
                int c = (idx & 3) << 3;
                uint32_t off = (uint32_t)(r * 64 + c * 2);
                cp16(sbase + t * GS_TILE + SMEM_SWIZZLE_64B(off),
                     src + (size_t)(r0 + r) * K + k0 + c);
            }
        }
    };

    load_stage(0, 0);
    CP_COMMIT();

    for (int it = 0; it < nStages; ++it) {
        CP_WAIT(0);
        __syncthreads();
        if (it + 1 < nStages) {
            load_stage((it + 1) & 1, (it + 1) << 5);
            CP_COMMIT();
        }

        const uint32_t stage = sb + (it & 1) * GS_STAGE;
        #pragma unroll
        for (int ks = 0; ks < 2; ++ks) {
            const int kk = ks << 4;
            uint32_t ah[4][4], bb[2][4];
            #pragma unroll
            for (int mi = 0; mi < 4; ++mi) {
                int rg = wm * 64 + mi * 16 + a_row;
                uint32_t off = SMEM_SWIZZLE_64B((uint32_t)(rg * 64 + (kk + a_koff) * 2));
                ldsm_x4(ah[mi], stage + off);
            }
            #pragma unroll
            for (int g = 0; g < 2; ++g) {
                int rg = wn * 32 + g * 16 + b_row;
                uint32_t off = (uint32_t)(rg * 64 + (kk + b_koff) * 2);
                ldsm_x4(bb[g], stage + GS_TILE + SMEM_SWIZZLE_64B(off));
            }
            #pragma unroll
            for (int mi = 0; mi < 4; ++mi)
                #pragma unroll
                for (int g = 0; g < 2; ++g) {
                    mma_f16(acc[mi][2 * g],     ah[mi], bb[g][0], bb[g][1]);
                    mma_f16(acc[mi][2 * g + 1], ah[mi], bb[g][2], bb[g][3]);
                }
        }
    }

    const int cg = lid >> 2, ct = lid & 3;
    #pragma unroll
    for (int mi = 0; mi < 4; ++mi) {
        #pragma unroll
        for (int ni = 0; ni < 4; ++ni) {
            int row = m0 + wm * 64 + mi * 16 + cg;
            int col = n0 + wn * 32 + ni * 8 + 2 * ct;
            float2 bv = *reinterpret_cast<const float2*>(&bias[col]);
            float v00 = acc[mi][ni][0] + bv.x, v01 = acc[mi][ni][1] + bv.y;
            float v10 = acc[mi][ni][2] + bv.x, v11 = acc[mi][ni][3] + bv.y;
            if (MODE == 0) {
                float2 o0 = {v00, v01}, o1 = {v10, v11};
                *reinterpret_cast<float2*>(&C[(size_t)row * N + col]) = o0;
                *reinterpret_cast<float2*>(&C[(size_t)(row + 8) * N + col]) = o1;
            } else {
                *reinterpret_cast<uint32_t*>(&Ch[(size_t)row * N + col]) =
                    pack_h2(v00, v01);
                *reinterpret_cast<uint32_t*>(&Ch[(size_t)(row + 8) * N + col]) =
                    pack_h2(v10, v11);
            }
        }
    }
}

// ---------------------------------------------------------------------------
// Tensor-core flash attention (fp16, single-pass S and PV).
// Block: (q-tile 128, b*h). 8 warps of 16 q-rows. cp.async 2-stage KV.
// ---------------------------------------------------------------------------
#define FTS_Q     0
#define FKV_BASE  16384
#define FKV_STAGE 16384      // Kh 8K + Vh 8K
#define FLASH_SMEM_TC (FKV_BASE + 2 * FKV_STAGE)   // 49152

__global__ __launch_bounds__(256, 2) void flash_tc(
    const __half* __restrict__ qkvh, __half* __restrict__ ctxh)
{
    extern __shared__ char smem[];
    const uint32_t sb = smem_to_u32(smem);
    const int tid = threadIdx.x;
    const int wid = tid >> 5, lid = tid & 31;
    const int bh = blockIdx.x;
    const int qt = (gridDim.y - 1) - blockIdx.y;    // heavy tiles first
    const int b = bh >> 4, h = bh & 15;
    const int q0 = qt * 128;
    const float LOG2E = 1.4426950408889634f;

    auto load_kv = [&](int buf, int k0) {
        uint32_t sbase = sb + FKV_BASE + buf * FKV_STAGE;
        #pragma unroll
        for (int t = 0; t < 2; ++t) {              // 0: Kh, 1: Vh
            const int coloff = (t == 0) ? DM : 2 * DM;
            #pragma unroll
            for (int p = 0; p < 2; ++p) {
                int idx = tid + p * 256;
                int r = idx >> 3;
                int c = (idx & 7) << 3;
                uint32_t off = (uint32_t)(r * 128 + c * 2);
                cp16(sbase + t * 8192 + SMEM_SWIZZLE_128B(off),
                     qkvh + (size_t)(b * S_LEN + k0 + r) * (3 * DM) + coloff + h * HDIM + c);
            }
        }
    };

    // Q tile into smem, swizzled
    #pragma unroll
    for (int p = 0; p < 4; ++p) {
        int idx = tid + p * 256;
        int r = idx >> 3;
        int c = (idx & 7) << 3;
        uint4 v = *reinterpret_cast<const uint4*>(
            qkvh + (size_t)(b * S_LEN + q0 + r) * (3 * DM) + h * HDIM + c);
        uint32_t off = (uint32_t)(r * 128 + c * 2);
        *reinterpret_cast<uint4*>(smem + FTS_Q + SMEM_SWIZZLE_128B(off)) = v;
    }
    load_kv(0, 0);
    CP_COMMIT();
    __syncthreads();

    const int a_row  = (lid & 7) + ((lid >> 3) & 1) * 8;
    const int a_koff = (lid >> 4) << 3;
    const int b_row  = ((lid >> 4) << 3) + (lid & 7);
    const int b_koff = ((lid >> 3) & 1) << 3;
    uint32_t qh[4][4];
    #pragma unroll
    for (int kk = 0; kk < 4; ++kk) {
        int rg = wid * 16 + a_row;
        uint32_t sw = (uint32_t)(rg * 128 + (kk * 16 + a_koff) * 2)
                      ^ ((uint32_t)(rg & 7) << 4);
        ldsm_x4(qh[kk], sb + FTS_Q + sw);
    }

    float o[8][4];
    #pragma unroll
    for (int j = 0; j < 8; ++j)
        #pragma unroll
        for (int r = 0; r < 4; ++r) o[j][r] = 0.0f;
    float mrow[2] = {-INFINITY, -INFINITY};
    float lrow[2] = {0.0f, 0.0f};

    const int g8 = lid >> 2, t2 = (lid & 3) * 2;
    const int nkt = 2 * qt + 2;

    for (int kt = 0; kt < nkt; ++kt) {
        const int k0 = kt * 64;
        CP_WAIT(0);
        __syncthreads();
        if (kt + 1 < nkt) {
            load_kv((kt + 1) & 1, (kt + 1) * 64);
            CP_COMMIT();
        }

        const uint32_t kvs = sb + FKV_BASE + (kt & 1) * FKV_STAGE;

        if (q0 + wid * 16 + 15 >= k0) {
            float s[8][4];
            #pragma unroll
            for (int j = 0; j < 8; ++j)
                #pragma unroll
                for (int r = 0; r < 4; ++r) s[j][r] = 0.0f;

            // S = Qh @ Kh^T (single pass)
            #pragma unroll
            for (int kk = 0; kk < 4; ++kk) {
                uint32_t kb[4][4];
                #pragma unroll
                for (int g = 0; g < 4; ++g) {
                    int rg = g * 16 + b_row;
                    uint32_t sw = (uint32_t)(rg * 128 + (kk * 16 + b_koff) * 2)
                                  ^ ((uint32_t)(rg & 7) << 4);
                    ldsm_x4(kb[g], kvs + sw);
                }
                #pragma unroll
                for (int g = 0; g < 4; ++g) {
                    mma_f16(s[2 * g],     qh[kk], kb[g][0], kb[g][1]);
                    mma_f16(s[2 * g + 1], qh[kk], kb[g][2], kb[g][3]);
                }
            }

            const bool diag = (k0 + 63 > q0 + wid * 16);
            #pragma unroll
            for (int j = 0; j < 8; ++j) {
                #pragma unroll
                for (int r2 = 0; r2 < 2; ++r2) {
                    int qrow = q0 + wid * 16 + g8 + 8 * r2;
                    #pragma unroll
                    for (int e = 0; e < 2; ++e) {
                        float v = s[j][2 * r2 + e] * 0.125f;
                        if (diag && (k0 + j * 8 + t2 + e > qrow)) v = -1e30f;
                        s[j][2 * r2 + e] = v;
                    }
                }
            }

            #pragma unroll
            for (int r2 = 0; r2 < 2; ++r2) {
                float mx = -INFINITY;
                #pragma unroll
                for (int j = 0; j < 8; ++j)
                    mx = fmaxf(mx, fmaxf(s[j][2 * r2], s[j][2 * r2 + 1]));
                mx = fmaxf(mx, __shfl_xor_sync(0xffffffffu, mx, 1));
                mx = fmaxf(mx, __shfl_xor_sync(0xffffffffu, mx, 2));
                float mnew = fmaxf(mrow[r2], mx);
                float alpha = fast_exp2((mrow[r2] - mnew) * LOG2E);
                mrow[r2] = mnew;
                float ls = 0.0f;
                #pragma unroll
                for (int j = 0; j < 8; ++j) {
                    float p0 = fast_exp2((s[j][2 * r2] - mnew) * LOG2E);
                    float p1 = fast_exp2((s[j][2 * r2 + 1] - mnew) * LOG2E);
                    s[j][2 * r2] = p0;
                    s[j][2 * r2 + 1] = p1;
                    ls += p0 + p1;
                }
                ls += __shfl_xor_sync(0xffffffffu, ls, 1);
                ls += __shfl_xor_sync(0xffffffffu, ls, 2);
                lrow[r2] = lrow[r2] * alpha + ls;
                #pragma unroll
                for (int j = 0; j < 8; ++j) {
                    o[j][2 * r2] *= alpha;
                    o[j][2 * r2 + 1] *= alpha;
                }
            }

            // O += Ph @ Vh (single pass)
            #pragma unroll
            for (int kk = 0; kk < 4; ++kk) {
                uint32_t ph[4];
                ph[0] = pack_h2(s[2 * kk][0],     s[2 * kk][1]);
                ph[1] = pack_h2(s[2 * kk][2],     s[2 * kk][3]);
                ph[2] = pack_h2(s[2 * kk + 1][0], s[2 * kk + 1][1]);
                ph[3] = pack_h2(s[2 * kk + 1][2], s[2 * kk + 1][3]);
                int vrow = kk * 16 + (lid & 7) + ((lid >> 3) & 1) * 8;
                uint32_t vb[4][4];
                #pragma unroll
                for (int j2 = 0; j2 < 4; ++j2) {
                    uint32_t sw = (uint32_t)(vrow * 128 + j2 * 32 + ((lid >> 4) & 1) * 16)
                                  ^ ((uint32_t)(vrow & 7) << 4);
                    ldsm_x4_t(vb[j2], kvs + 8192 + sw);
                }
                #pragma unroll
                for (int j2 = 0; j2 < 4; ++j2) {
                    mma_f16(o[2 * j2],     ph, vb[j2][0], vb[j2][1]);
                    mma_f16(o[2 * j2 + 1], ph, vb[j2][2], vb[j2][3]);
                }
            }
        }
    }

    float inv0 = 1.0f / lrow[0], inv1 = 1.0f / lrow[1];
    size_t row0 = (size_t)(b * S_LEN + q0 + wid * 16 + g8);
    #pragma unroll
    for (int j = 0; j < 8; ++j) {
        int c = h * HDIM + j * 8 + t2;
        *reinterpret_cast<uint32_t*>(&ctxh[row0 * DM + c]) =
            pack_h2(o[j][0] * inv0, o[j][1] * inv0);
        *reinterpret_cast<uint32_t*>(&ctxh[(row0 + 8) * DM + c]) =
            pack_h2(o[j][2] * inv1, o[j][3] * inv1);
    }
}

// ---------------------------------------------------------------------------
extern "C" void kernel_launch(void* const* d_in, const int* in_sizes, int n_in,
                              void* d_out, int out_size)
{
    const float* x    = (const float*)d_in[0];
    const float* Wqkv = (const float*)d_in[1];
    const float* bqkv = (const float*)d_in[2];
    const float* Wout = (const float*)d_in[3];
    const float* bout = (const float*)d_in[4];
    float* out = (float*)d_out;

    __half *qkvh, *xh, *ctxh, *wqh, *woh;
    cudaGetSymbolAddress((void**)&qkvh, g_qkvh);
    cudaGetSymbolAddress((void**)&xh, g_xh);
    cudaGetSymbolAddress((void**)&ctxh, g_ctxh);
    cudaGetSymbolAddress((void**)&wqh, g_wqkvTh);
    cudaGetSymbolAddress((void**)&woh, g_woutTh);

    cudaFuncSetAttribute(gemm_mma<0>, cudaFuncAttributeMaxDynamicSharedMemorySize, GEMM_SMEM);
    cudaFuncSetAttribute(gemm_mma<1>, cudaFuncAttributeMaxDynamicSharedMemorySize, GEMM_SMEM);
    cudaFuncSetAttribute(flash_tc, cudaFuncAttributeMaxDynamicSharedMemorySize, FLASH_SMEM_TC);

    int nx4 = MROWS * DM / 4;
    round_f32<<<(nx4 + 255) / 256, 256>>>(x, xh, nx4);
    roundT_f32<<<dim3(3 * DM / 32, DM / 32), 256>>>(Wqkv, wqh, DM, 3 * DM);
    roundT_f32<<<dim3(DM / 32, DM / 32), 256>>>(Wout, woh, DM, DM);

    // 1) QKV projection (single pass) -> fp16 qkv
    gemm_mma<1><<<dim3(3 * DM / 128, MROWS / 128), 256, GEMM_SMEM>>>(
        xh, wqh, bqkv, nullptr, qkvh, MROWS, 3 * DM, DM);

    // 2) Causal flash attention -> fp16 ctx
    flash_tc<<<dim3(BATCH * NHEADS, S_LEN / 128), 256, FLASH_SMEM_TC>>>(qkvh, ctxh);

    // 3) Output projection (single pass) -> f32 out
    gemm_mma<0><<<dim3(DM / 128, MROWS / 128), 256, GEMM_SMEM>>>(
        ctxh, woh, bout, out, nullptr, MROWS, DM, DM);
}